// round 1
// baseline (speedup 1.0000x reference)
#include <cuda_runtime.h>
#include <math.h>

#define L 4096
#define DI 192
#define NS 16

// ---------------- device scratch (static, no allocations) ----------------
__device__ float g_xg_pre[DI*L];
__device__ float g_z[DI*L];
__device__ float g_xg_f[DI*L];
__device__ float g_xg_t[DI*L];
__device__ float g_cmean[DI];
__device__ float g_BC[4*L*32];       // [k][s][0..15 B, 16..31 C]
__device__ float g_dt[4*DI*L];       // softplus(dt) per (k,d,s)
__device__ float g_du[4*DI*L];       // dt*u
__device__ float g_y4[4*DI*L];       // scan outputs, pixel-indexed
__device__ float g_xcdbl[2*38*DI];
__device__ float g_gate[DI];

__device__ __forceinline__ float softplusf_(float x){
    return (x > 20.f) ? x : log1pf(__expf(x));
}

// ---------------- K1: 1x1 in-proj (96 -> 384), split into xg_pre / silu(z) ----
__global__ void __launch_bounds__(128) k_inproj(const float* __restrict__ x,
                                                const float* __restrict__ W,
                                                const float* __restrict__ b) {
    __shared__ float ws[8*96];
    int ob = blockIdx.y * 8;
    for (int i = threadIdx.x; i < 8*96; i += 128) ws[i] = W[ob*96 + i];
    __syncthreads();
    int p = blockIdx.x * 128 + threadIdx.x;
    float acc[8];
    #pragma unroll
    for (int j = 0; j < 8; j++) acc[j] = 0.f;
    for (int c = 0; c < 96; c++) {
        float xv = x[c*L + p];
        #pragma unroll
        for (int j = 0; j < 8; j++) acc[j] = fmaf(ws[j*96 + c], xv, acc[j]);
    }
    #pragma unroll
    for (int j = 0; j < 8; j++) {
        int o = ob + j;
        float v = acc[j] + b[o];
        if (o < DI) {
            g_xg_pre[o*L + p] = v;
        } else {
            g_z[(o-DI)*L + p] = v / (1.f + __expf(-v));   // silu
        }
    }
}

// ---------------- K2: depthwise 3x3 + bias + silu, write f-order and t-order ----
__global__ void __launch_bounds__(1024) k_dwconv(const float* __restrict__ w,
                                                 const float* __restrict__ b) {
    __shared__ float t[32][33];
    int d = blockIdx.z;
    int tx = threadIdx.x, ty = threadIdx.y;
    int h = blockIdx.y*32 + ty;
    int wq = blockIdx.x*32 + tx;
    const float* src = g_xg_pre + d*L;
    float wk[9];
    #pragma unroll
    for (int i = 0; i < 9; i++) wk[i] = w[d*9 + i];
    float acc = b[d];
    #pragma unroll
    for (int kh = 0; kh < 3; kh++) {
        int hh = h + kh - 1;
        #pragma unroll
        for (int kw = 0; kw < 3; kw++) {
            int ww = wq + kw - 1;
            if (hh >= 0 && hh < 64 && ww >= 0 && ww < 64)
                acc = fmaf(wk[kh*3+kw], src[hh*64 + ww], acc);
        }
    }
    float v = acc / (1.f + __expf(-acc));   // silu
    g_xg_f[d*L + h*64 + wq] = v;
    t[ty][tx] = v;
    __syncthreads();
    float v2 = t[tx][ty];   // pixel (h = by*32+tx, w = bx*32+ty)
    g_xg_t[d*L + (blockIdx.x*32 + ty)*64 + blockIdx.y*32 + tx] = v2;
}

// ---------------- K2b: channel means of xg (post-silu) ----------------
__global__ void __launch_bounds__(256) k_cmean() {
    __shared__ float red[256];
    int d = blockIdx.x, tid = threadIdx.x;
    float s = 0.f;
    for (int i = tid; i < L; i += 256) s += g_xg_f[d*L + i];
    red[tid] = s; __syncthreads();
    for (int o = 128; o > 0; o >>= 1) {
        if (tid < o) red[tid] += red[tid + o];
        __syncthreads();
    }
    if (tid == 0) g_cmean[d] = red[0] * (1.f / L);
}

// ---------------- K3: x-proj (192->38) + dt-proj + softplus + dt*u ----------------
__global__ void __launch_bounds__(256) k_proj(const float* __restrict__ xpw,
                                              const float* __restrict__ dtw,
                                              const float* __restrict__ dtb) {
    __shared__ float xv[DI*32];       // [d][si]
    __shared__ float xd6[2*6*32];
    int tid = threadIdx.x;
    int s0 = blockIdx.x * 32;
    int oid = blockIdx.y;             // 0: f-order {k0,k2}; 1: t-order {k1,k3}
    const float* uptr = oid ? g_xg_t : g_xg_f;
    for (int idx = tid; idx < DI*32; idx += 256) {
        int d = idx >> 5, si = idx & 31;
        xv[idx] = uptr[d*L + s0 + si];
    }
    __syncthreads();
    for (int idx = tid; idx < 76*32; idx += 256) {
        int r = idx >> 5, si = idx & 31;
        int kk = (r < 38) ? 0 : 1;
        int c  = (r < 38) ? r : r - 38;
        int k  = oid + kk*2;
        float acc = 0.f;
        const float4* w4 = reinterpret_cast<const float4*>(xpw + (k*38 + c)*DI);
        #pragma unroll 4
        for (int d4 = 0; d4 < 48; d4++) {
            float4 wv = __ldg(w4 + d4);
            int d = d4*4;
            acc = fmaf(wv.x, xv[d*32+si],
                  fmaf(wv.y, xv[(d+1)*32+si],
                  fmaf(wv.z, xv[(d+2)*32+si],
                  fmaf(wv.w, xv[(d+3)*32+si], acc))));
        }
        if (c < 6)       xd6[(kk*6 + c)*32 + si] = acc;
        else if (c < 22) g_BC[(k*L + s0 + si)*32 + (c - 6)] = acc;
        else             g_BC[(k*L + s0 + si)*32 + 16 + (c - 22)] = acc;
    }
    __syncthreads();
    for (int idx = tid; idx < 2*DI*32; idx += 256) {
        int kk = idx / (DI*32);
        int rem = idx % (DI*32);
        int d = rem >> 5, si = rem & 31;
        int k = oid + kk*2;
        float acc = dtb[k*DI + d];
        #pragma unroll
        for (int r = 0; r < 6; r++)
            acc = fmaf(dtw[(k*DI + d)*6 + r], xd6[(kk*6 + r)*32 + si], acc);
        float dt = softplusf_(acc);
        float u = xv[d*32 + si];
        int gi = (k*DI + d)*L + s0 + si;
        g_dt[gi] = dt;
        g_du[gi] = dt * u;
    }
}

// ---------------- K4: the main selective scan (2 sequences per warp) ----------------
__global__ void __launch_bounds__(32) k_scan(const float* __restrict__ A_logs,
                                             const float* __restrict__ Ds) {
    int bid = blockIdx.x;
    int k = bid / 96;
    int pair = bid % 96;
    int lane = threadIdx.x;
    int n = lane & 15, half = lane >> 4;
    int d = pair*2 + half;
    int row = k*DI + d;
    float An = -__expf(A_logs[row*NS + n]);
    float Dd = Ds[row];
    const float* pdt = g_dt + row*L;
    const float* pdu = g_du + row*L;
    const float* pu  = ((k & 1) ? g_xg_t : g_xg_f) + d*L;
    const float* pBC = g_BC + k*L*32;
    float* pout = g_y4 + row*L;
    bool fwd  = (k < 2);
    bool tord = (k & 1);
    float h = 0.f;
    #pragma unroll 4
    for (int i = 0; i < L; i++) {
        int s = fwd ? i : (L - 1 - i);
        float dt = __ldg(pdt + s);
        float du = __ldg(pdu + s);
        float uu = __ldg(pu + s);
        float bn = __ldg(pBC + s*32 + n);
        float cn = __ldg(pBC + s*32 + 16 + n);
        float e = __expf(dt * An);
        h = fmaf(e, h, du * bn);
        float acc = h * cn;
        acc += __shfl_xor_sync(0xffffffffu, acc, 8);
        acc += __shfl_xor_sync(0xffffffffu, acc, 4);
        acc += __shfl_xor_sync(0xffffffffu, acc, 2);
        acc += __shfl_xor_sync(0xffffffffu, acc, 1);
        if (n == 0) {
            int p = tord ? (((s & 63) << 6) | (s >> 6)) : s;
            pout[p] = fmaf(uu, Dd, acc);
        }
    }
}

// ---------------- K5: channel-branch (tiny), single block ----------------
__global__ void __launch_bounds__(128) k_chan(
    const float* __restrict__ cin_w, const float* __restrict__ cin_b,
    const float* __restrict__ xcw,   const float* __restrict__ dtcw,
    const float* __restrict__ dtcb,  const float* __restrict__ Ac_logs,
    const float* __restrict__ Dsc,   const float* __restrict__ cout_w,
    const float* __restrict__ cout_b,const float* __restrict__ cnw,
    const float* __restrict__ cnb) {
    __shared__ float sxc[4*DI];
    __shared__ float sdt[2*4*DI];
    __shared__ float sdu[2*4*DI];
    __shared__ float su [2*4*DI];
    __shared__ float syc[2*4*DI];
    __shared__ float sg[DI];
    __shared__ float red[128];
    __shared__ float sstat[2];
    int tid = threadIdx.x;
    for (int idx = tid; idx < 4*DI; idx += 128) {
        int ci = idx / DI, l = idx % DI;
        sxc[idx] = g_cmean[l]*cin_w[ci] + cin_b[ci];
    }
    __syncthreads();
    for (int idx = tid; idx < 2*38*DI; idx += 128) {
        int k = idx / (38*DI);
        int r = (idx / DI) % 38;
        int l = idx % DI;
        int ls = k ? (DI-1-l) : l;
        float acc = 0.f;
        #pragma unroll
        for (int ci = 0; ci < 4; ci++)
            acc = fmaf(xcw[(k*38 + r)*4 + ci], sxc[ci*DI + ls], acc);
        g_xcdbl[idx] = acc;
    }
    __syncthreads();
    for (int idx = tid; idx < 2*4*DI; idx += 128) {
        int k = idx / (4*DI);
        int ci = (idx / DI) & 3;
        int l = idx % DI;
        float acc = dtcb[k*4 + ci];
        #pragma unroll
        for (int r = 0; r < 6; r++)
            acc = fmaf(dtcw[(k*4 + ci)*6 + r], g_xcdbl[(k*38 + r)*DI + l], acc);
        float dt = softplusf_(acc);
        int ls = k ? (DI-1-l) : l;
        float u = sxc[ci*DI + ls];
        sdt[idx] = dt; sdu[idx] = dt*u; su[idx] = u;
    }
    __syncthreads();
    {
        int w = tid >> 5, lane = tid & 31;
        int n = lane & 15, half = lane >> 4;
        int seq = w*2 + half;        // 0..7
        int k = seq >> 2, ci = seq & 3;
        float An = -__expf(Ac_logs[(k*4 + ci)*16 + n]);
        float Dc = Dsc[k*4 + ci];
        int base = seq * DI;
        float h = 0.f;
        for (int l = 0; l < DI; l++) {
            float dt = sdt[base + l];
            float du = sdu[base + l];
            float bn = g_xcdbl[(k*38 + 6 + n)*DI + l];
            float cn = g_xcdbl[(k*38 + 22 + n)*DI + l];
            float e = __expf(dt * An);
            h = fmaf(e, h, du * bn);
            float acc = h * cn;
            acc += __shfl_xor_sync(0xffffffffu, acc, 8);
            acc += __shfl_xor_sync(0xffffffffu, acc, 4);
            acc += __shfl_xor_sync(0xffffffffu, acc, 2);
            acc += __shfl_xor_sync(0xffffffffu, acc, 1);
            if (n == 0) syc[base + l] = fmaf(su[base + l], Dc, acc);
        }
    }
    __syncthreads();
    for (int l = tid; l < DI; l += 128) {
        float g = cout_b[0];
        #pragma unroll
        for (int ci = 0; ci < 4; ci++)
            g = fmaf(syc[ci*DI + l] + syc[(4 + ci)*DI + (DI-1-l)], cout_w[ci], g);
        sg[l] = g;
    }
    __syncthreads();
    float p1 = 0.f, p2 = 0.f;
    for (int l = tid; l < DI; l += 128) { float v = sg[l]; p1 += v; p2 += v*v; }
    red[tid] = p1; __syncthreads();
    for (int o = 64; o > 0; o >>= 1) { if (tid < o) red[tid] += red[tid+o]; __syncthreads(); }
    if (tid == 0) sstat[0] = red[0] * (1.f/DI);
    __syncthreads();
    red[tid] = p2; __syncthreads();
    for (int o = 64; o > 0; o >>= 1) { if (tid < o) red[tid] += red[tid+o]; __syncthreads(); }
    if (tid == 0) {
        float mu = sstat[0];
        sstat[1] = rsqrtf(red[0]*(1.f/DI) - mu*mu + 1e-5f);
    }
    __syncthreads();
    float mu = sstat[0], rs = sstat[1];
    for (int l = tid; l < DI; l += 128)
        g_gate[l] = (sg[l] - mu)*rs*cnw[l] + cnb[l];
}

// ---------------- K6: combine + LN + gate*z + out-proj (192 -> 96) ----------------
__global__ void __launch_bounds__(256) k_final(const float* __restrict__ onw,
                                               const float* __restrict__ onb,
                                               const float* __restrict__ ow,
                                               const float* __restrict__ ob,
                                               float* __restrict__ out) {
    __shared__ float sv[DI*33];       // [d][si] with pad-33 pitch
    __shared__ float smu[32], srs[32];
    int tid = threadIdx.x;
    int p0 = blockIdx.x * 32;
    for (int idx = tid; idx < DI*32; idx += 256) {
        int d = idx >> 5, si = idx & 31;
        int p = p0 + si;
        float s = g_y4[(0*DI + d)*L + p] + g_y4[(1*DI + d)*L + p]
                + g_y4[(2*DI + d)*L + p] + g_y4[(3*DI + d)*L + p];
        sv[d*33 + si] = s;
    }
    __syncthreads();
    {
        int w = tid >> 5, lane = tid & 31;
        for (int q = 0; q < 4; q++) {
            int si = w*4 + q;
            float s1 = 0.f, s2 = 0.f;
            #pragma unroll
            for (int j = 0; j < 6; j++) {
                float v = sv[(lane + j*32)*33 + si];
                s1 += v; s2 += v*v;
            }
            #pragma unroll
            for (int o = 16; o > 0; o >>= 1) {
                s1 += __shfl_xor_sync(0xffffffffu, s1, o);
                s2 += __shfl_xor_sync(0xffffffffu, s2, o);
            }
            if (lane == 0) {
                float mu = s1 * (1.f/DI);
                smu[si] = mu;
                srs[si] = rsqrtf(s2*(1.f/DI) - mu*mu + 1e-5f);
            }
        }
    }
    __syncthreads();
    for (int idx = tid; idx < DI*32; idx += 256) {
        int d = idx >> 5, si = idx & 31;
        int p = p0 + si;
        float v = sv[d*33 + si];
        v = (v - smu[si]) * srs[si] * onw[d] + onb[d];
        v = v * g_gate[d] * g_z[d*L + p];
        sv[d*33 + si] = v;
    }
    __syncthreads();
    for (int idx = tid; idx < 96*32; idx += 256) {
        int o = idx >> 5, si = idx & 31;
        float acc = ob[o];
        const float4* w4 = reinterpret_cast<const float4*>(ow + o*DI);
        #pragma unroll 4
        for (int d4 = 0; d4 < 48; d4++) {
            float4 wv = __ldg(w4 + d4);
            int d = d4*4;
            acc = fmaf(wv.x, sv[d*33+si],
                  fmaf(wv.y, sv[(d+1)*33+si],
                  fmaf(wv.z, sv[(d+2)*33+si],
                  fmaf(wv.w, sv[(d+3)*33+si], acc))));
        }
        out[o*L + p0 + si] = acc;
    }
}

// ---------------- launch ----------------
extern "C" void kernel_launch(void* const* d_in, const int* in_sizes, int n_in,
                              void* d_out, int out_size) {
    const float* x      = (const float*)d_in[0];
    const float* in_w   = (const float*)d_in[1];
    const float* in_b   = (const float*)d_in[2];
    const float* c2w    = (const float*)d_in[3];
    const float* c2b    = (const float*)d_in[4];
    const float* xpw    = (const float*)d_in[5];
    const float* dtw    = (const float*)d_in[6];
    const float* dtb    = (const float*)d_in[7];
    const float* Alogs  = (const float*)d_in[8];
    const float* Ds     = (const float*)d_in[9];
    const float* onw    = (const float*)d_in[10];
    const float* onb    = (const float*)d_in[11];
    const float* cinw   = (const float*)d_in[12];
    const float* cinb   = (const float*)d_in[13];
    const float* coutw  = (const float*)d_in[14];
    const float* coutb  = (const float*)d_in[15];
    const float* xcw    = (const float*)d_in[16];
    const float* dtcw   = (const float*)d_in[17];
    const float* dtcb   = (const float*)d_in[18];
    const float* Aclogs = (const float*)d_in[19];
    const float* Dsc    = (const float*)d_in[20];
    const float* cnw    = (const float*)d_in[21];
    const float* cnb    = (const float*)d_in[22];
    const float* ow     = (const float*)d_in[23];
    const float* obias  = (const float*)d_in[24];
    float* out = (float*)d_out;

    k_inproj<<<dim3(32, 48), 128>>>(x, in_w, in_b);
    k_dwconv<<<dim3(2, 2, 192), dim3(32, 32)>>>(c2w, c2b);
    k_cmean<<<192, 256>>>();
    k_proj<<<dim3(128, 2), 256>>>(xpw, dtw, dtb);
    k_chan<<<1, 128>>>(cinw, cinb, xcw, dtcw, dtcb, Aclogs, Dsc, coutw, coutb, cnw, cnb);
    k_scan<<<384, 32>>>(Alogs, Ds);
    k_final<<<128, 256>>>(onw, onb, ow, obias, out);
}

// round 2
// speedup vs baseline: 1.9690x; 1.9690x over previous
#include <cuda_runtime.h>
#include <math.h>

#define L 4096
#define DI 192
#define NS 16
#define NCHUNK 64
#define CLEN 64

// ---------------- device scratch (static, no allocations) ----------------
__device__ float g_xg_pre[DI*L];
__device__ float g_z[DI*L];
__device__ float g_xg_f[DI*L];
__device__ float g_xg_t[DI*L];
__device__ float g_cmean[DI];
__device__ float g_BC[4*L*32];       // [k][s][0..15 B, 16..31 C]
__device__ float g_dt[4*DI*L];       // softplus(dt) per (k,d,s)
__device__ float g_du[4*DI*L];       // dt*u
__device__ float g_y4[4*DI*L];       // scan outputs, pixel-indexed
__device__ float g_xcdbl[2*38*DI];
__device__ float g_gate[DI];
// chunked-scan carries: [seq(768)][chunk(64)][n(16)]
__device__ float g_ch[768*NCHUNK*16];
__device__ float g_cp[768*NCHUNK*16];
__device__ float g_h0[768*NCHUNK*16];

__device__ __forceinline__ float softplusf_(float x){
    return (x > 20.f) ? x : log1pf(__expf(x));
}
__device__ __forceinline__ float ex2_(float x){
    float r;
    asm("ex2.approx.ftz.f32 %0, %1;" : "=f"(r) : "f"(x));
    return r;
}

// ---------------- K1: 1x1 in-proj (96 -> 384), split into xg_pre / silu(z) ----
__global__ void __launch_bounds__(128) k_inproj(const float* __restrict__ x,
                                                const float* __restrict__ W,
                                                const float* __restrict__ b) {
    __shared__ float ws[96*8];   // transposed: [c][j]
    int ob = blockIdx.y * 8;
    for (int i = threadIdx.x; i < 96*8; i += 128) {
        int c = i >> 3, j = i & 7;
        ws[i] = W[(ob + j)*96 + c];
    }
    __syncthreads();
    int p = blockIdx.x * 128 + threadIdx.x;
    if (blockIdx.y == 0 && p < DI) g_cmean[p] = 0.f;  // unused slot kept warm
    float acc[8];
    #pragma unroll
    for (int j = 0; j < 8; j++) acc[j] = 0.f;
    #pragma unroll 4
    for (int c = 0; c < 96; c++) {
        float xv = __ldg(x + c*L + p);
        float4 w0 = *reinterpret_cast<const float4*>(ws + c*8);
        float4 w1 = *reinterpret_cast<const float4*>(ws + c*8 + 4);
        acc[0] = fmaf(w0.x, xv, acc[0]);
        acc[1] = fmaf(w0.y, xv, acc[1]);
        acc[2] = fmaf(w0.z, xv, acc[2]);
        acc[3] = fmaf(w0.w, xv, acc[3]);
        acc[4] = fmaf(w1.x, xv, acc[4]);
        acc[5] = fmaf(w1.y, xv, acc[5]);
        acc[6] = fmaf(w1.z, xv, acc[6]);
        acc[7] = fmaf(w1.w, xv, acc[7]);
    }
    #pragma unroll
    for (int j = 0; j < 8; j++) {
        int o = ob + j;
        float v = acc[j] + b[o];
        if (o < DI) {
            g_xg_pre[o*L + p] = v;
        } else {
            g_z[(o-DI)*L + p] = v / (1.f + __expf(-v));   // silu
        }
    }
}

// ---------------- K2: depthwise 3x3 + bias + silu, write f-order and t-order ----
__global__ void __launch_bounds__(1024) k_dwconv(const float* __restrict__ w,
                                                 const float* __restrict__ b) {
    __shared__ float t[32][33];
    int d = blockIdx.z;
    int tx = threadIdx.x, ty = threadIdx.y;
    int h = blockIdx.y*32 + ty;
    int wq = blockIdx.x*32 + tx;
    const float* src = g_xg_pre + d*L;
    float wk[9];
    #pragma unroll
    for (int i = 0; i < 9; i++) wk[i] = w[d*9 + i];
    float acc = b[d];
    #pragma unroll
    for (int kh = 0; kh < 3; kh++) {
        int hh = h + kh - 1;
        #pragma unroll
        for (int kw = 0; kw < 3; kw++) {
            int ww = wq + kw - 1;
            if (hh >= 0 && hh < 64 && ww >= 0 && ww < 64)
                acc = fmaf(wk[kh*3+kw], src[hh*64 + ww], acc);
        }
    }
    float v = acc / (1.f + __expf(-acc));   // silu
    g_xg_f[d*L + h*64 + wq] = v;
    t[ty][tx] = v;
    __syncthreads();
    float v2 = t[tx][ty];
    g_xg_t[d*L + (blockIdx.x*32 + ty)*64 + blockIdx.y*32 + tx] = v2;
}

// ---------------- K2b: channel means of xg (post-silu) ----------------
__global__ void __launch_bounds__(256) k_cmean() {
    __shared__ float red[256];
    int d = blockIdx.x, tid = threadIdx.x;
    float s = 0.f;
    for (int i = tid; i < L; i += 256) s += g_xg_f[d*L + i];
    red[tid] = s; __syncthreads();
    for (int o = 128; o > 0; o >>= 1) {
        if (tid < o) red[tid] += red[tid + o];
        __syncthreads();
    }
    if (tid == 0) g_cmean[d] = red[0] * (1.f / L);
}

// ---------------- K3: x-proj (192->38) + dt-proj + softplus + dt*u ----------------
// grid (128, 4): y = oid + 2*kk ; each block handles one k, 32 pixels
__global__ void __launch_bounds__(256) k_proj(const float* __restrict__ xpw,
                                              const float* __restrict__ dtw,
                                              const float* __restrict__ dtb) {
    __shared__ float xv[DI*32];       // [d][si]
    __shared__ float xd6[6*32];
    __shared__ float sBC[32][33];     // [si][c] staging for coalesced BC write
    int tid = threadIdx.x;
    int s0 = blockIdx.x * 32;
    int oid = blockIdx.y & 1;
    int kk  = blockIdx.y >> 1;
    int k = oid + kk*2;
    const float* uptr = oid ? g_xg_t : g_xg_f;
    for (int i4 = tid; i4 < DI*8; i4 += 256) {     // 1536 float4s
        int d = i4 >> 3, j = i4 & 7;
        float4 v = *reinterpret_cast<const float4*>(uptr + d*L + s0 + j*4);
        reinterpret_cast<float4*>(xv)[i4] = v;     // xv[d*32 + 4j]
    }
    __syncthreads();
    for (int idx = tid; idx < 38*32; idx += 256) {
        int r = idx >> 5, si = idx & 31;
        const float4* w4 = reinterpret_cast<const float4*>(xpw + (k*38 + r)*DI);
        float a0 = 0.f, a1 = 0.f, a2 = 0.f, a3 = 0.f;
        #pragma unroll 12
        for (int d4 = 0; d4 < 48; d4++) {
            float4 wv = __ldg(w4 + d4);
            int d = d4*4;
            a0 = fmaf(wv.x, xv[d*32+si], a0);
            a1 = fmaf(wv.y, xv[(d+1)*32+si], a1);
            a2 = fmaf(wv.z, xv[(d+2)*32+si], a2);
            a3 = fmaf(wv.w, xv[(d+3)*32+si], a3);
        }
        float acc = (a0 + a1) + (a2 + a3);
        if (r < 6) xd6[r*32 + si] = acc;
        else       sBC[si][r - 6] = acc;          // slots 0..31 (B then C)
    }
    __syncthreads();
    // coalesced BC write: 32 px * 32 slots
    for (int idx = tid; idx < 32*32; idx += 256) {
        int si = idx >> 5, c = idx & 31;
        g_BC[(k*L + s0 + si)*32 + c] = sBC[si][c];
    }
    for (int idx = tid; idx < DI*32; idx += 256) {
        int d = idx >> 5, si = idx & 31;
        float acc = dtb[k*DI + d];
        #pragma unroll
        for (int r = 0; r < 6; r++)
            acc = fmaf(__ldg(dtw + (k*DI + d)*6 + r), xd6[r*32 + si], acc);
        float dt = softplusf_(acc);
        float u = xv[d*32 + si];
        int gi = (k*DI + d)*L + s0 + si;
        g_dt[gi] = dt;
        g_du[gi] = dt * u;
    }
}

// ---------------- K4a: chunked scan pass 1 — local state + decay product ----
// unit = seq*64 + chunk, 16 lanes per unit, 16 units per 256-thread block
__global__ void __launch_bounds__(256) k_scan1(const float* __restrict__ A_logs) {
    int unit = blockIdx.x*16 + (threadIdx.x >> 4);
    int n = threadIdx.x & 15;
    int seq = unit >> 6;
    int chunk = unit & 63;
    int k = seq / DI;
    bool fwd = (k < 2);
    const float* pdt = g_dt + seq*L;
    const float* pdu = g_du + seq*L;
    const float* pBC = g_BC + (k*L)*32;
    float An2 = -__expf(A_logs[seq*NS + n]) * 1.4426950408889634f;
    float h = 0.f, P = 1.f;
    int base = chunk * CLEN;
    #pragma unroll 4
    for (int i = 0; i < CLEN; i++) {
        int gi = base + i;
        int s = fwd ? gi : (L - 1 - gi);
        float dt = __ldg(pdt + s);
        float du = __ldg(pdu + s);
        float bn = __ldg(pBC + s*32 + n);
        float e = ex2_(dt * An2);
        h = fmaf(e, h, du * bn);
        P *= e;
    }
    g_ch[unit*16 + n] = h;
    g_cp[unit*16 + n] = P;
}

// ---------------- K4b: chunk-combine (serial over 64 chunks, tiny) ----------
__global__ void __launch_bounds__(256) k_scan2() {
    int seq = blockIdx.x*16 + (threadIdx.x >> 4);
    int n = threadIdx.x & 15;
    float H = 0.f;
    int base = seq * NCHUNK;
    for (int c = 0; c < NCHUNK; c++) {
        int idx = (base + c)*16 + n;
        float hh = g_ch[idx];
        float pp = g_cp[idx];
        g_h0[idx] = H;
        H = fmaf(pp, H, hh);
    }
}

// ---------------- K4c: chunked scan pass 3 — re-scan with correct h0, emit y --
__global__ void __launch_bounds__(256) k_scan3(const float* __restrict__ A_logs,
                                               const float* __restrict__ Ds) {
    int unit = blockIdx.x*16 + (threadIdx.x >> 4);
    int n = threadIdx.x & 15;
    int seq = unit >> 6;
    int chunk = unit & 63;
    int k = seq / DI;
    int d = seq - k*DI;
    bool fwd  = (k < 2);
    bool tord = (k & 1);
    const float* pdt = g_dt + seq*L;
    const float* pdu = g_du + seq*L;
    const float* pu  = (tord ? g_xg_t : g_xg_f) + d*L;
    const float* pBC = g_BC + (k*L)*32;
    float* pout = g_y4 + seq*L;
    float An2 = -__expf(A_logs[seq*NS + n]) * 1.4426950408889634f;
    float Dd = Ds[seq];
    float h = g_h0[unit*16 + n];
    int base = chunk * CLEN;
    #pragma unroll 2
    for (int i = 0; i < CLEN; i++) {
        int gi = base + i;
        int s = fwd ? gi : (L - 1 - gi);
        float dt = __ldg(pdt + s);
        float du = __ldg(pdu + s);
        float uu = __ldg(pu + s);
        float bn = __ldg(pBC + s*32 + n);
        float cn = __ldg(pBC + s*32 + 16 + n);
        float e = ex2_(dt * An2);
        h = fmaf(e, h, du * bn);
        float acc = h * cn;
        acc += __shfl_xor_sync(0xffffffffu, acc, 8);
        acc += __shfl_xor_sync(0xffffffffu, acc, 4);
        acc += __shfl_xor_sync(0xffffffffu, acc, 2);
        acc += __shfl_xor_sync(0xffffffffu, acc, 1);
        if (n == 0) {
            int p = tord ? (((s & 63) << 6) | (s >> 6)) : s;
            pout[p] = fmaf(uu, Dd, acc);
        }
    }
}

// ---------------- K5: channel-branch (tiny), single block ----------------
__global__ void __launch_bounds__(128) k_chan(
    const float* __restrict__ cin_w, const float* __restrict__ cin_b,
    const float* __restrict__ xcw,   const float* __restrict__ dtcw,
    const float* __restrict__ dtcb,  const float* __restrict__ Ac_logs,
    const float* __restrict__ Dsc,   const float* __restrict__ cout_w,
    const float* __restrict__ cout_b,const float* __restrict__ cnw,
    const float* __restrict__ cnb) {
    __shared__ float sxc[4*DI];
    __shared__ float sdt[2*4*DI];
    __shared__ float sdu[2*4*DI];
    __shared__ float su [2*4*DI];
    __shared__ float syc[2*4*DI];
    __shared__ float sg[DI];
    __shared__ float red[128];
    __shared__ float sstat[2];
    int tid = threadIdx.x;
    for (int idx = tid; idx < 4*DI; idx += 128) {
        int ci = idx / DI, l = idx % DI;
        sxc[idx] = g_cmean[l]*cin_w[ci] + cin_b[ci];
    }
    __syncthreads();
    for (int idx = tid; idx < 2*38*DI; idx += 128) {
        int k = idx / (38*DI);
        int r = (idx / DI) % 38;
        int l = idx % DI;
        int ls = k ? (DI-1-l) : l;
        float acc = 0.f;
        #pragma unroll
        for (int ci = 0; ci < 4; ci++)
            acc = fmaf(xcw[(k*38 + r)*4 + ci], sxc[ci*DI + ls], acc);
        g_xcdbl[idx] = acc;
    }
    __syncthreads();
    for (int idx = tid; idx < 2*4*DI; idx += 128) {
        int k = idx / (4*DI);
        int ci = (idx / DI) & 3;
        int l = idx % DI;
        float acc = dtcb[k*4 + ci];
        #pragma unroll
        for (int r = 0; r < 6; r++)
            acc = fmaf(dtcw[(k*4 + ci)*6 + r], g_xcdbl[(k*38 + r)*DI + l], acc);
        float dt = softplusf_(acc);
        int ls = k ? (DI-1-l) : l;
        float u = sxc[ci*DI + ls];
        sdt[idx] = dt; sdu[idx] = dt*u; su[idx] = u;
    }
    __syncthreads();
    {
        int w = tid >> 5, lane = tid & 31;
        int n = lane & 15, half = lane >> 4;
        int seq = w*2 + half;        // 0..7
        int k = seq >> 2, ci = seq & 3;
        float An = -__expf(Ac_logs[(k*4 + ci)*16 + n]);
        float Dc = Dsc[k*4 + ci];
        int base = seq * DI;
        float h = 0.f;
        for (int l = 0; l < DI; l++) {
            float dt = sdt[base + l];
            float du = sdu[base + l];
            float bn = g_xcdbl[(k*38 + 6 + n)*DI + l];
            float cn = g_xcdbl[(k*38 + 22 + n)*DI + l];
            float e = __expf(dt * An);
            h = fmaf(e, h, du * bn);
            float acc = h * cn;
            acc += __shfl_xor_sync(0xffffffffu, acc, 8);
            acc += __shfl_xor_sync(0xffffffffu, acc, 4);
            acc += __shfl_xor_sync(0xffffffffu, acc, 2);
            acc += __shfl_xor_sync(0xffffffffu, acc, 1);
            if (n == 0) syc[base + l] = fmaf(su[base + l], Dc, acc);
        }
    }
    __syncthreads();
    for (int l = tid; l < DI; l += 128) {
        float g = cout_b[0];
        #pragma unroll
        for (int ci = 0; ci < 4; ci++)
            g = fmaf(syc[ci*DI + l] + syc[(4 + ci)*DI + (DI-1-l)], cout_w[ci], g);
        sg[l] = g;
    }
    __syncthreads();
    float p1 = 0.f, p2 = 0.f;
    for (int l = tid; l < DI; l += 128) { float v = sg[l]; p1 += v; p2 += v*v; }
    red[tid] = p1; __syncthreads();
    for (int o = 64; o > 0; o >>= 1) { if (tid < o) red[tid] += red[tid+o]; __syncthreads(); }
    if (tid == 0) sstat[0] = red[0] * (1.f/DI);
    __syncthreads();
    red[tid] = p2; __syncthreads();
    for (int o = 64; o > 0; o >>= 1) { if (tid < o) red[tid] += red[tid+o]; __syncthreads(); }
    if (tid == 0) {
        float mu = sstat[0];
        sstat[1] = rsqrtf(red[0]*(1.f/DI) - mu*mu + 1e-5f);
    }
    __syncthreads();
    float mu = sstat[0], rs = sstat[1];
    for (int l = tid; l < DI; l += 128)
        g_gate[l] = (sg[l] - mu)*rs*cnw[l] + cnb[l];
}

// ---------------- K6: combine + LN + gate*z + out-proj (192 -> 96) ----------------
__global__ void __launch_bounds__(256) k_final(const float* __restrict__ onw,
                                               const float* __restrict__ onb,
                                               const float* __restrict__ ow,
                                               const float* __restrict__ ob,
                                               float* __restrict__ out) {
    __shared__ float sv[DI*33];       // [d][si] with pad-33 pitch
    __shared__ float smu[32], srs[32];
    int tid = threadIdx.x;
    int p0 = blockIdx.x * 32;
    for (int idx = tid; idx < DI*32; idx += 256) {
        int d = idx >> 5, si = idx & 31;
        int p = p0 + si;
        float s = g_y4[(0*DI + d)*L + p] + g_y4[(1*DI + d)*L + p]
                + g_y4[(2*DI + d)*L + p] + g_y4[(3*DI + d)*L + p];
        sv[d*33 + si] = s;
    }
    __syncthreads();
    {
        int w = tid >> 5, lane = tid & 31;
        for (int q = 0; q < 4; q++) {
            int si = w*4 + q;
            float s1 = 0.f, s2 = 0.f;
            #pragma unroll
            for (int j = 0; j < 6; j++) {
                float v = sv[(lane + j*32)*33 + si];
                s1 += v; s2 += v*v;
            }
            #pragma unroll
            for (int o = 16; o > 0; o >>= 1) {
                s1 += __shfl_xor_sync(0xffffffffu, s1, o);
                s2 += __shfl_xor_sync(0xffffffffu, s2, o);
            }
            if (lane == 0) {
                float mu = s1 * (1.f/DI);
                smu[si] = mu;
                srs[si] = rsqrtf(s2*(1.f/DI) - mu*mu + 1e-5f);
            }
        }
    }
    __syncthreads();
    for (int idx = tid; idx < DI*32; idx += 256) {
        int d = idx >> 5, si = idx & 31;
        int p = p0 + si;
        float v = sv[d*33 + si];
        v = (v - smu[si]) * srs[si] * onw[d] + onb[d];
        v = v * g_gate[d] * g_z[d*L + p];
        sv[d*33 + si] = v;
    }
    __syncthreads();
    for (int idx = tid; idx < 96*32; idx += 256) {
        int o = idx >> 5, si = idx & 31;
        const float4* w4 = reinterpret_cast<const float4*>(ow + o*DI);
        float a0 = 0.f, a1 = 0.f, a2 = 0.f, a3 = 0.f;
        #pragma unroll 12
        for (int d4 = 0; d4 < 48; d4++) {
            float4 wv = __ldg(w4 + d4);
            int d = d4*4;
            a0 = fmaf(wv.x, sv[d*33+si], a0);
            a1 = fmaf(wv.y, sv[(d+1)*33+si], a1);
            a2 = fmaf(wv.z, sv[(d+2)*33+si], a2);
            a3 = fmaf(wv.w, sv[(d+3)*33+si], a3);
        }
        out[o*L + p0 + si] = ob[o] + (a0 + a1) + (a2 + a3);
    }
}

// ---------------- launch ----------------
extern "C" void kernel_launch(void* const* d_in, const int* in_sizes, int n_in,
                              void* d_out, int out_size) {
    const float* x      = (const float*)d_in[0];
    const float* in_w   = (const float*)d_in[1];
    const float* in_b   = (const float*)d_in[2];
    const float* c2w    = (const float*)d_in[3];
    const float* c2b    = (const float*)d_in[4];
    const float* xpw    = (const float*)d_in[5];
    const float* dtw    = (const float*)d_in[6];
    const float* dtb    = (const float*)d_in[7];
    const float* Alogs  = (const float*)d_in[8];
    const float* Ds     = (const float*)d_in[9];
    const float* onw    = (const float*)d_in[10];
    const float* onb    = (const float*)d_in[11];
    const float* cinw   = (const float*)d_in[12];
    const float* cinb   = (const float*)d_in[13];
    const float* coutw  = (const float*)d_in[14];
    const float* coutb  = (const float*)d_in[15];
    const float* xcw    = (const float*)d_in[16];
    const float* dtcw   = (const float*)d_in[17];
    const float* dtcb   = (const float*)d_in[18];
    const float* Aclogs = (const float*)d_in[19];
    const float* Dsc    = (const float*)d_in[20];
    const float* cnw    = (const float*)d_in[21];
    const float* cnb    = (const float*)d_in[22];
    const float* ow     = (const float*)d_in[23];
    const float* obias  = (const float*)d_in[24];
    float* out = (float*)d_out;

    k_inproj<<<dim3(32, 48), 128>>>(x, in_w, in_b);
    k_dwconv<<<dim3(2, 2, 192), dim3(32, 32)>>>(c2w, c2b);
    k_cmean<<<192, 256>>>();
    k_proj<<<dim3(128, 4), 256>>>(xpw, dtw, dtb);
    k_scan1<<<3072, 256>>>(Alogs);
    k_scan2<<<48, 256>>>();
    k_scan3<<<3072, 256>>>(Alogs, Ds);
    k_chan<<<1, 128>>>(cinw, cinb, xcw, dtcw, dtcb, Aclogs, Dsc, coutw, coutb, cnw, cnb);
    k_final<<<128, 256>>>(onw, onb, ow, obias, out);
}

// round 4
// speedup vs baseline: 2.3071x; 1.1718x over previous
#include <cuda_runtime.h>
#include <math.h>

#define L 4096
#define DI 192
#define NS 16
#define NCHUNK 64
#define CLEN 64

// ---------------- device scratch (static, no allocations) ----------------
__device__ float g_xg_pre[DI*L];
__device__ float g_z[DI*L];
__device__ float g_xg_f[DI*L];
__device__ float g_xg_t[DI*L];
__device__ float g_cmean[DI];
__device__ float g_BC[4*L*32];        // [k][s][n][2] : slot 2n = B_n, 2n+1 = C_n
__device__ float2 g_dtu[768*L];       // (softplus dt, dt*u) per (seq, s)
__device__ float g_y4[4*DI*L];        // scan outputs, pixel-indexed
__device__ float g_xcdbl[2*38*DI];
__device__ float g_gate[DI];
// chunked-scan carries: [seq(768)][chunk(64)][n(16)]
__device__ float g_ch[768*NCHUNK*16];
__device__ float g_cp[768*NCHUNK*16];
__device__ float g_h0[768*NCHUNK*16];

__device__ __forceinline__ float softplusf_(float x){
    return (x > 20.f) ? x : log1pf(__expf(x));
}
__device__ __forceinline__ float ex2_(float x){
    float r;
    asm("ex2.approx.ftz.f32 %0, %1;" : "=f"(r) : "f"(x));
    return r;
}

// ---------------- K1: 1x1 in-proj (96 -> 384), 16 outputs per thread ----------
__global__ void __launch_bounds__(128) k_inproj(const float* __restrict__ x,
                                                const float* __restrict__ W,
                                                const float* __restrict__ b) {
    __shared__ float ws[96*16];   // transposed: [c][j]
    int ob = blockIdx.y * 16;
    for (int i = threadIdx.x; i < 96*16; i += 128) {
        int c = i >> 4, j = i & 15;
        ws[i] = W[(ob + j)*96 + c];
    }
    __syncthreads();
    int p = blockIdx.x * 128 + threadIdx.x;
    if (blockIdx.y == 0 && p < DI) g_cmean[p] = 0.f;   // zero for dwconv atomics
    float acc[16];
    #pragma unroll
    for (int j = 0; j < 16; j++) acc[j] = 0.f;
    #pragma unroll 2
    for (int c = 0; c < 96; c++) {
        float xv = __ldg(x + c*L + p);
        #pragma unroll
        for (int q = 0; q < 4; q++) {
            float4 w = *reinterpret_cast<const float4*>(ws + c*16 + q*4);
            acc[q*4+0] = fmaf(w.x, xv, acc[q*4+0]);
            acc[q*4+1] = fmaf(w.y, xv, acc[q*4+1]);
            acc[q*4+2] = fmaf(w.z, xv, acc[q*4+2]);
            acc[q*4+3] = fmaf(w.w, xv, acc[q*4+3]);
        }
    }
    #pragma unroll
    for (int j = 0; j < 16; j++) {
        int o = ob + j;
        float v = acc[j] + b[o];
        if (o < DI) {
            g_xg_pre[o*L + p] = v;
        } else {
            g_z[(o-DI)*L + p] = v / (1.f + __expf(-v));   // silu
        }
    }
}

// ------- K2: depthwise 3x3 + bias + silu + fused channel-mean (atomics) -------
__global__ void __launch_bounds__(1024) k_dwconv(const float* __restrict__ w,
                                                 const float* __restrict__ b) {
    __shared__ float t[32][33];
    __shared__ float wsum[32];
    int d = blockIdx.z;
    int tx = threadIdx.x, ty = threadIdx.y;
    int h = blockIdx.y*32 + ty;
    int wq = blockIdx.x*32 + tx;
    const float* src = g_xg_pre + d*L;
    float wk[9];
    #pragma unroll
    for (int i = 0; i < 9; i++) wk[i] = w[d*9 + i];
    float acc = b[d];
    #pragma unroll
    for (int kh = 0; kh < 3; kh++) {
        int hh = h + kh - 1;
        #pragma unroll
        for (int kw = 0; kw < 3; kw++) {
            int ww = wq + kw - 1;
            if (hh >= 0 && hh < 64 && ww >= 0 && ww < 64)
                acc = fmaf(wk[kh*3+kw], src[hh*64 + ww], acc);
        }
    }
    float v = acc / (1.f + __expf(-acc));   // silu
    g_xg_f[d*L + h*64 + wq] = v;
    t[ty][tx] = v;
    // block reduction for channel mean
    int tid = ty*32 + tx;
    int lane = tid & 31, wi = tid >> 5;
    float s = v;
    #pragma unroll
    for (int o = 16; o > 0; o >>= 1) s += __shfl_xor_sync(0xffffffffu, s, o);
    if (lane == 0) wsum[wi] = s;
    __syncthreads();
    float v2 = t[tx][ty];
    g_xg_t[d*L + (blockIdx.x*32 + ty)*64 + blockIdx.y*32 + tx] = v2;
    if (wi == 0) {
        float s2 = wsum[lane];
        #pragma unroll
        for (int o = 16; o > 0; o >>= 1) s2 += __shfl_xor_sync(0xffffffffu, s2, o);
        if (lane == 0) atomicAdd(&g_cmean[d], s2 * (1.f / L));
    }
}

// ---------------- K3: x-proj + dt-proj, register-tiled GEMM ----------------
// grid (128, 4): y = oid + 2*kk ; each block: one k, 32 pixels
// weights staged in half-K slabs (38 x 96) to stay under the 48KB smem limit
__global__ void __launch_bounds__(320) k_proj(const float* __restrict__ xpw,
                                              const float* __restrict__ dtw,
                                              const float* __restrict__ dtb) {
    __shared__ float xv[DI*32];       // [d][si]  (24 KB)
    __shared__ float wsm[38*97];      // half-K weight slab, padded (14.7 KB)
    __shared__ float xd6[6*32];
    __shared__ float sBC[32][33];     // [si][slot]
    int tid = threadIdx.x;
    int s0 = blockIdx.x * 32;
    int oid = blockIdx.y & 1;
    int kk  = blockIdx.y >> 1;
    int k = oid + kk*2;
    const float* uptr = oid ? g_xg_t : g_xg_f;
    for (int i4 = tid; i4 < DI*8; i4 += 320) {
        int d = i4 >> 3, j = i4 & 7;
        float4 v = *reinterpret_cast<const float4*>(uptr + d*L + s0 + j*4);
        *reinterpret_cast<float4*>(xv + d*32 + j*4) = v;
    }
    int r_ = tid >> 3, sq_ = tid & 7;
    float a0 = 0.f, a1 = 0.f, a2 = 0.f, a3 = 0.f;
    #pragma unroll
    for (int half = 0; half < 2; half++) {
        __syncthreads();           // xv ready (half 0) / prior reads done (half 1)
        for (int i = tid; i < 38*96; i += 320) {
            int r = i / 96, dd = i - r*96;
            wsm[r*97 + dd] = __ldg(xpw + (k*38 + r)*192 + half*96 + dd);
        }
        __syncthreads();
        if (tid < 304) {
            const float* wr = wsm + r_*97;
            const float* xb = xv + sq_*4 + half*96*32;
            #pragma unroll 4
            for (int dd = 0; dd < 96; dd++) {
                float w = wr[dd];
                float4 xq = *reinterpret_cast<const float4*>(xb + dd*32);
                a0 = fmaf(w, xq.x, a0);
                a1 = fmaf(w, xq.y, a1);
                a2 = fmaf(w, xq.z, a2);
                a3 = fmaf(w, xq.w, a3);
            }
        }
    }
    __syncthreads();
    if (tid < 304) {
        int sb = sq_*4;
        if (r_ < 6) {
            xd6[r_*32 + sb]     = a0;
            xd6[r_*32 + sb + 1] = a1;
            xd6[r_*32 + sb + 2] = a2;
            xd6[r_*32 + sb + 3] = a3;
        } else {
            int slot = (r_ < 22) ? 2*(r_ - 6) : 2*(r_ - 22) + 1;
            sBC[sb][slot]     = a0;
            sBC[sb + 1][slot] = a1;
            sBC[sb + 2][slot] = a2;
            sBC[sb + 3][slot] = a3;
        }
    }
    __syncthreads();
    for (int idx = tid; idx < 32*32; idx += 320) {
        int si = idx >> 5, c = idx & 31;
        g_BC[((size_t)k*L + s0 + si)*32 + c] = sBC[si][c];
    }
    for (int idx = tid; idx < DI*32; idx += 320) {
        int d = idx >> 5, si = idx & 31;
        int row = k*DI + d;
        float acc = __ldg(dtb + row);
        #pragma unroll
        for (int r = 0; r < 6; r++)
            acc = fmaf(__ldg(dtw + row*6 + r), xd6[r*32 + si], acc);
        float dt = softplusf_(acc);
        float u = xv[d*32 + si];
        g_dtu[(size_t)row*L + s0 + si] = make_float2(dt, dt*u);
    }
}

// -------- K4a: chunked scan pass 1 — 2 states/lane, 8 lanes per unit --------
__global__ void __launch_bounds__(256) k_scan1(const float* __restrict__ A_logs) {
    int unit = blockIdx.x*32 + (threadIdx.x >> 3);
    int ln = threadIdx.x & 7;
    int seq = unit >> 6;
    int chunk = unit & 63;
    int k = seq / DI;
    bool fwd = (k < 2);
    const float2* pdtu = g_dtu + (size_t)seq*L;
    const float4* pBC4 = reinterpret_cast<const float4*>(g_BC + (size_t)k*L*32);
    const float LOG2E = 1.4426950408889634f;
    float An0 = -__expf(A_logs[seq*NS + 2*ln])     * LOG2E;
    float An1 = -__expf(A_logs[seq*NS + 2*ln + 1]) * LOG2E;
    float h0 = 0.f, h1 = 0.f, P0 = 1.f, P1 = 1.f;
    int base = chunk * CLEN;
    #pragma unroll 4
    for (int i = 0; i < CLEN; i++) {
        int s = fwd ? (base + i) : (L - 1 - (base + i));
        float2 dtu = __ldg(pdtu + s);
        float4 bc = __ldg(pBC4 + s*8 + ln);
        float e0 = ex2_(dtu.x * An0);
        float e1 = ex2_(dtu.x * An1);
        h0 = fmaf(e0, h0, dtu.y * bc.x);
        h1 = fmaf(e1, h1, dtu.y * bc.z);
        P0 *= e0; P1 *= e1;
    }
    reinterpret_cast<float2*>(g_ch)[unit*8 + ln] = make_float2(h0, h1);
    reinterpret_cast<float2*>(g_cp)[unit*8 + ln] = make_float2(P0, P1);
}

// ---------------- K4b: chunk-combine (serial over 64 chunks, tiny) ----------
__global__ void __launch_bounds__(256) k_scan2() {
    int seq = blockIdx.x*16 + (threadIdx.x >> 4);
    int n = threadIdx.x & 15;
    float H = 0.f;
    int base = seq * NCHUNK;
    for (int c = 0; c < NCHUNK; c++) {
        int idx = (base + c)*16 + n;
        float hh = g_ch[idx];
        float pp = g_cp[idx];
        g_h0[idx] = H;
        H = fmaf(pp, H, hh);
    }
}

// -------- K4c: chunked scan pass 3 — re-scan with h0, emit y (2 states/lane) --
__global__ void __launch_bounds__(256) k_scan3(const float* __restrict__ A_logs,
                                               const float* __restrict__ Ds) {
    int unit = blockIdx.x*32 + (threadIdx.x >> 3);
    int ln = threadIdx.x & 7;
    int seq = unit >> 6;
    int chunk = unit & 63;
    int k = seq / DI;
    int d = seq - k*DI;
    bool fwd  = (k < 2);
    bool tord = (k & 1);
    const float2* pdtu = g_dtu + (size_t)seq*L;
    const float4* pBC4 = reinterpret_cast<const float4*>(g_BC + (size_t)k*L*32);
    const float* pu = (tord ? g_xg_t : g_xg_f) + d*L;
    float* pout = g_y4 + seq*L;
    const float LOG2E = 1.4426950408889634f;
    float An0 = -__expf(A_logs[seq*NS + 2*ln])     * LOG2E;
    float An1 = -__expf(A_logs[seq*NS + 2*ln + 1]) * LOG2E;
    float Dd = Ds[seq];
    float2 hh = reinterpret_cast<const float2*>(g_h0)[unit*8 + ln];
    float h0 = hh.x, h1 = hh.y;
    int base = chunk * CLEN;
    #pragma unroll 2
    for (int i = 0; i < CLEN; i++) {
        int s = fwd ? (base + i) : (L - 1 - (base + i));
        float2 dtu = __ldg(pdtu + s);
        float4 bc = __ldg(pBC4 + s*8 + ln);
        float uu = __ldg(pu + s);
        float e0 = ex2_(dtu.x * An0);
        float e1 = ex2_(dtu.x * An1);
        h0 = fmaf(e0, h0, dtu.y * bc.x);
        h1 = fmaf(e1, h1, dtu.y * bc.z);
        float acc = fmaf(h1, bc.w, h0 * bc.y);
        acc += __shfl_xor_sync(0xffffffffu, acc, 4);
        acc += __shfl_xor_sync(0xffffffffu, acc, 2);
        acc += __shfl_xor_sync(0xffffffffu, acc, 1);
        if (ln == 0) {
            int p = tord ? (((s & 63) << 6) | (s >> 6)) : s;
            pout[p] = fmaf(uu, Dd, acc);
        }
    }
}

// ---------------- K5: channel-branch (tiny), single block ----------------
__global__ void __launch_bounds__(128) k_chan(
    const float* __restrict__ cin_w, const float* __restrict__ cin_b,
    const float* __restrict__ xcw,   const float* __restrict__ dtcw,
    const float* __restrict__ dtcb,  const float* __restrict__ Ac_logs,
    const float* __restrict__ Dsc,   const float* __restrict__ cout_w,
    const float* __restrict__ cout_b,const float* __restrict__ cnw,
    const float* __restrict__ cnb) {
    __shared__ float sxc[4*DI];
    __shared__ float sdt[2*4*DI];
    __shared__ float sdu[2*4*DI];
    __shared__ float su [2*4*DI];
    __shared__ float syc[2*4*DI];
    __shared__ float sg[DI];
    __shared__ float red[128];
    __shared__ float sstat[2];
    int tid = threadIdx.x;
    for (int idx = tid; idx < 4*DI; idx += 128) {
        int ci = idx / DI, l = idx % DI;
        sxc[idx] = g_cmean[l]*cin_w[ci] + cin_b[ci];
    }
    __syncthreads();
    for (int idx = tid; idx < 2*38*DI; idx += 128) {
        int k = idx / (38*DI);
        int r = (idx / DI) % 38;
        int l = idx % DI;
        int ls = k ? (DI-1-l) : l;
        float acc = 0.f;
        #pragma unroll
        for (int ci = 0; ci < 4; ci++)
            acc = fmaf(xcw[(k*38 + r)*4 + ci], sxc[ci*DI + ls], acc);
        g_xcdbl[idx] = acc;
    }
    __syncthreads();
    for (int idx = tid; idx < 2*4*DI; idx += 128) {
        int k = idx / (4*DI);
        int ci = (idx / DI) & 3;
        int l = idx % DI;
        float acc = dtcb[k*4 + ci];
        #pragma unroll
        for (int r = 0; r < 6; r++)
            acc = fmaf(dtcw[(k*4 + ci)*6 + r], g_xcdbl[(k*38 + r)*DI + l], acc);
        float dt = softplusf_(acc);
        int ls = k ? (DI-1-l) : l;
        float u = sxc[ci*DI + ls];
        sdt[idx] = dt; sdu[idx] = dt*u; su[idx] = u;
    }
    __syncthreads();
    {
        int w = tid >> 5, lane = tid & 31;
        int n = lane & 15, half = lane >> 4;
        int seq = w*2 + half;        // 0..7
        int k = seq >> 2, ci = seq & 3;
        float An = -__expf(Ac_logs[(k*4 + ci)*16 + n]);
        float Dc = Dsc[k*4 + ci];
        int base = seq * DI;
        float h = 0.f;
        for (int l = 0; l < DI; l++) {
            float dt = sdt[base + l];
            float du = sdu[base + l];
            float bn = g_xcdbl[(k*38 + 6 + n)*DI + l];
            float cn = g_xcdbl[(k*38 + 22 + n)*DI + l];
            float e = __expf(dt * An);
            h = fmaf(e, h, du * bn);
            float acc = h * cn;
            acc += __shfl_xor_sync(0xffffffffu, acc, 8);
            acc += __shfl_xor_sync(0xffffffffu, acc, 4);
            acc += __shfl_xor_sync(0xffffffffu, acc, 2);
            acc += __shfl_xor_sync(0xffffffffu, acc, 1);
            if (n == 0) syc[base + l] = fmaf(su[base + l], Dc, acc);
        }
    }
    __syncthreads();
    for (int l = tid; l < DI; l += 128) {
        float g = cout_b[0];
        #pragma unroll
        for (int ci = 0; ci < 4; ci++)
            g = fmaf(syc[ci*DI + l] + syc[(4 + ci)*DI + (DI-1-l)], cout_w[ci], g);
        sg[l] = g;
    }
    __syncthreads();
    float p1 = 0.f, p2 = 0.f;
    for (int l = tid; l < DI; l += 128) { float v = sg[l]; p1 += v; p2 += v*v; }
    red[tid] = p1; __syncthreads();
    for (int o = 64; o > 0; o >>= 1) { if (tid < o) red[tid] += red[tid+o]; __syncthreads(); }
    if (tid == 0) sstat[0] = red[0] * (1.f/DI);
    __syncthreads();
    red[tid] = p2; __syncthreads();
    for (int o = 64; o > 0; o >>= 1) { if (tid < o) red[tid] += red[tid+o]; __syncthreads(); }
    if (tid == 0) {
        float mu = sstat[0];
        sstat[1] = rsqrtf(red[0]*(1.f/DI) - mu*mu + 1e-5f);
    }
    __syncthreads();
    float mu = sstat[0], rs = sstat[1];
    for (int l = tid; l < DI; l += 128)
        g_gate[l] = (sg[l] - mu)*rs*cnw[l] + cnb[l];
}

// ---------------- K6: combine + LN + gate*z + out-proj (192 -> 96) ----------------
__global__ void __launch_bounds__(256) k_final(const float* __restrict__ onw,
                                               const float* __restrict__ onb,
                                               const float* __restrict__ ow,
                                               const float* __restrict__ ob,
                                               float* __restrict__ out) {
    __shared__ float sv[DI*33];       // [d][si] with pad-33 pitch
    __shared__ float smu[32], srs[32];
    int tid = threadIdx.x;
    int p0 = blockIdx.x * 32;
    for (int idx = tid; idx < DI*32; idx += 256) {
        int d = idx >> 5, si = idx & 31;
        int p = p0 + si;
        float s = g_y4[(0*DI + d)*L + p] + g_y4[(1*DI + d)*L + p]
                + g_y4[(2*DI + d)*L + p] + g_y4[(3*DI + d)*L + p];
        sv[d*33 + si] = s;
    }
    __syncthreads();
    {
        int w = tid >> 5, lane = tid & 31;
        for (int q = 0; q < 4; q++) {
            int si = w*4 + q;
            float s1 = 0.f, s2 = 0.f;
            #pragma unroll
            for (int j = 0; j < 6; j++) {
                float v = sv[(lane + j*32)*33 + si];
                s1 += v; s2 += v*v;
            }
            #pragma unroll
            for (int o = 16; o > 0; o >>= 1) {
                s1 += __shfl_xor_sync(0xffffffffu, s1, o);
                s2 += __shfl_xor_sync(0xffffffffu, s2, o);
            }
            if (lane == 0) {
                float mu = s1 * (1.f/DI);
                smu[si] = mu;
                srs[si] = rsqrtf(s2*(1.f/DI) - mu*mu + 1e-5f);
            }
        }
    }
    __syncthreads();
    for (int idx = tid; idx < DI*32; idx += 256) {
        int d = idx >> 5, si = idx & 31;
        int p = p0 + si;
        float v = sv[d*33 + si];
        v = (v - smu[si]) * srs[si] * onw[d] + onb[d];
        v = v * g_gate[d] * g_z[d*L + p];
        sv[d*33 + si] = v;
    }
    __syncthreads();
    for (int idx = tid; idx < 96*32; idx += 256) {
        int o = idx >> 5, si = idx & 31;
        const float4* w4 = reinterpret_cast<const float4*>(ow + o*DI);
        float a0 = 0.f, a1 = 0.f, a2 = 0.f, a3 = 0.f;
        #pragma unroll 12
        for (int d4 = 0; d4 < 48; d4++) {
            float4 wv = __ldg(w4 + d4);
            int d = d4*4;
            a0 = fmaf(wv.x, sv[d*33+si], a0);
            a1 = fmaf(wv.y, sv[(d+1)*33+si], a1);
            a2 = fmaf(wv.z, sv[(d+2)*33+si], a2);
            a3 = fmaf(wv.w, sv[(d+3)*33+si], a3);
        }
        out[o*L + p0 + si] = ob[o] + (a0 + a1) + (a2 + a3);
    }
}

// ---------------- launch ----------------
extern "C" void kernel_launch(void* const* d_in, const int* in_sizes, int n_in,
                              void* d_out, int out_size) {
    const float* x      = (const float*)d_in[0];
    const float* in_w   = (const float*)d_in[1];
    const float* in_b   = (const float*)d_in[2];
    const float* c2w    = (const float*)d_in[3];
    const float* c2b    = (const float*)d_in[4];
    const float* xpw    = (const float*)d_in[5];
    const float* dtw    = (const float*)d_in[6];
    const float* dtb    = (const float*)d_in[7];
    const float* Alogs  = (const float*)d_in[8];
    const float* Ds     = (const float*)d_in[9];
    const float* onw    = (const float*)d_in[10];
    const float* onb    = (const float*)d_in[11];
    const float* cinw   = (const float*)d_in[12];
    const float* cinb   = (const float*)d_in[13];
    const float* coutw  = (const float*)d_in[14];
    const float* coutb  = (const float*)d_in[15];
    const float* xcw    = (const float*)d_in[16];
    const float* dtcw   = (const float*)d_in[17];
    const float* dtcb   = (const float*)d_in[18];
    const float* Aclogs = (const float*)d_in[19];
    const float* Dsc    = (const float*)d_in[20];
    const float* cnw    = (const float*)d_in[21];
    const float* cnb    = (const float*)d_in[22];
    const float* ow     = (const float*)d_in[23];
    const float* obias  = (const float*)d_in[24];
    float* out = (float*)d_out;

    k_inproj<<<dim3(32, 24), 128>>>(x, in_w, in_b);
    k_dwconv<<<dim3(2, 2, 192), dim3(32, 32)>>>(c2w, c2b);
    k_proj<<<dim3(128, 4), 320>>>(xpw, dtw, dtb);
    k_scan1<<<1536, 256>>>(Alogs);
    k_scan2<<<48, 256>>>();
    k_scan3<<<1536, 256>>>(Alogs, Ds);
    k_chan<<<1, 128>>>(cinw, cinb, xcw, dtcw, dtcb, Aclogs, Dsc, coutw, coutb, cnw, cnb);
    k_final<<<128, 256>>>(onw, onb, ow, obias, out);
}

// round 5
// speedup vs baseline: 2.4891x; 1.0789x over previous
#include <cuda_runtime.h>
#include <math.h>

#define L 4096
#define DI 192
#define NS 16
#define NCHUNK 64
#define CLEN 64

// ---------------- device scratch (static, no allocations) ----------------
__device__ float g_xg_pre[DI*L];
__device__ float g_z[DI*L];
__device__ float g_xg_f[DI*L];
__device__ float g_xg_t[DI*L];
__device__ float g_cmean[DI];
__device__ float g_BC[4*L*32];        // [k][s][n][2] : slot 2n = B_n, 2n+1 = C_n
__device__ float2 g_dtu[768*L];       // (softplus dt, dt*u) per (seq, s)
__device__ float g_y4[4*DI*L];        // scan outputs, pixel-indexed
__device__ float g_xcdbl[2*38*DI];
__device__ float g_gate[DI];

__device__ __forceinline__ float softplusf_(float x){
    return (x > 20.f) ? x : log1pf(__expf(x));
}
__device__ __forceinline__ float ex2_(float x){
    float r;
    asm("ex2.approx.ftz.f32 %0, %1;" : "=f"(r) : "f"(x));
    return r;
}

// ---------------- K1: 1x1 in-proj (96 -> 384), 16 outputs per thread ----------
__global__ void __launch_bounds__(128) k_inproj(const float* __restrict__ x,
                                                const float* __restrict__ W,
                                                const float* __restrict__ b) {
    __shared__ float ws[96*16];   // transposed: [c][j]
    int ob = blockIdx.y * 16;
    for (int i = threadIdx.x; i < 96*16; i += 128) {
        int c = i >> 4, j = i & 15;
        ws[i] = W[(ob + j)*96 + c];
    }
    __syncthreads();
    int p = blockIdx.x * 128 + threadIdx.x;
    if (blockIdx.y == 0 && p < DI) g_cmean[p] = 0.f;   // zero for dwconv atomics
    float acc[16];
    #pragma unroll
    for (int j = 0; j < 16; j++) acc[j] = 0.f;
    #pragma unroll 2
    for (int c = 0; c < 96; c++) {
        float xv = __ldg(x + c*L + p);
        #pragma unroll
        for (int q = 0; q < 4; q++) {
            float4 w = *reinterpret_cast<const float4*>(ws + c*16 + q*4);
            acc[q*4+0] = fmaf(w.x, xv, acc[q*4+0]);
            acc[q*4+1] = fmaf(w.y, xv, acc[q*4+1]);
            acc[q*4+2] = fmaf(w.z, xv, acc[q*4+2]);
            acc[q*4+3] = fmaf(w.w, xv, acc[q*4+3]);
        }
    }
    #pragma unroll
    for (int j = 0; j < 16; j++) {
        int o = ob + j;
        float v = acc[j] + b[o];
        if (o < DI) {
            g_xg_pre[o*L + p] = v;
        } else {
            g_z[(o-DI)*L + p] = v / (1.f + __expf(-v));   // silu
        }
    }
}

// ------- K2: depthwise 3x3 + bias + silu + fused channel-mean (atomics) -------
__global__ void __launch_bounds__(1024) k_dwconv(const float* __restrict__ w,
                                                 const float* __restrict__ b) {
    __shared__ float t[32][33];
    __shared__ float wsum[32];
    int d = blockIdx.z;
    int tx = threadIdx.x, ty = threadIdx.y;
    int h = blockIdx.y*32 + ty;
    int wq = blockIdx.x*32 + tx;
    const float* src = g_xg_pre + d*L;
    float wk[9];
    #pragma unroll
    for (int i = 0; i < 9; i++) wk[i] = w[d*9 + i];
    float acc = b[d];
    #pragma unroll
    for (int kh = 0; kh < 3; kh++) {
        int hh = h + kh - 1;
        #pragma unroll
        for (int kw = 0; kw < 3; kw++) {
            int ww = wq + kw - 1;
            if (hh >= 0 && hh < 64 && ww >= 0 && ww < 64)
                acc = fmaf(wk[kh*3+kw], src[hh*64 + ww], acc);
        }
    }
    float v = acc / (1.f + __expf(-acc));   // silu
    g_xg_f[d*L + h*64 + wq] = v;
    t[ty][tx] = v;
    // block reduction for channel mean
    int tid = ty*32 + tx;
    int lane = tid & 31, wi = tid >> 5;
    float s = v;
    #pragma unroll
    for (int o = 16; o > 0; o >>= 1) s += __shfl_xor_sync(0xffffffffu, s, o);
    if (lane == 0) wsum[wi] = s;
    __syncthreads();
    float v2 = t[tx][ty];
    g_xg_t[d*L + (blockIdx.x*32 + ty)*64 + blockIdx.y*32 + tx] = v2;
    if (wi == 0) {
        float s2 = wsum[lane];
        #pragma unroll
        for (int o = 16; o > 0; o >>= 1) s2 += __shfl_xor_sync(0xffffffffu, s2, o);
        if (lane == 0) atomicAdd(&g_cmean[d], s2 * (1.f / L));
    }
}

// ---------------- K3: x-proj + dt-proj, register-tiled GEMM ----------------
// grid (128, 4): y = oid + 2*kk ; each block: one k, 32 pixels
// weights staged in half-K slabs (38 x 96) to stay under the 48KB smem limit
__global__ void __launch_bounds__(320) k_proj(const float* __restrict__ xpw,
                                              const float* __restrict__ dtw,
                                              const float* __restrict__ dtb) {
    __shared__ float xv[DI*32];       // [d][si]  (24 KB)
    __shared__ float wsm[38*97];      // half-K weight slab, padded (14.7 KB)
    __shared__ float xd6[6*32];
    __shared__ float sBC[32][33];     // [si][slot]
    int tid = threadIdx.x;
    int s0 = blockIdx.x * 32;
    int oid = blockIdx.y & 1;
    int kk  = blockIdx.y >> 1;
    int k = oid + kk*2;
    const float* uptr = oid ? g_xg_t : g_xg_f;
    for (int i4 = tid; i4 < DI*8; i4 += 320) {
        int d = i4 >> 3, j = i4 & 7;
        float4 v = *reinterpret_cast<const float4*>(uptr + d*L + s0 + j*4);
        *reinterpret_cast<float4*>(xv + d*32 + j*4) = v;
    }
    int r_ = tid >> 3, sq_ = tid & 7;
    float a0 = 0.f, a1 = 0.f, a2 = 0.f, a3 = 0.f;
    #pragma unroll
    for (int half = 0; half < 2; half++) {
        __syncthreads();           // xv ready (half 0) / prior reads done (half 1)
        for (int i = tid; i < 38*96; i += 320) {
            int r = i / 96, dd = i - r*96;
            wsm[r*97 + dd] = __ldg(xpw + (k*38 + r)*192 + half*96 + dd);
        }
        __syncthreads();
        if (tid < 304) {
            const float* wr = wsm + r_*97;
            const float* xb = xv + sq_*4 + half*96*32;
            #pragma unroll 4
            for (int dd = 0; dd < 96; dd++) {
                float w = wr[dd];
                float4 xq = *reinterpret_cast<const float4*>(xb + dd*32);
                a0 = fmaf(w, xq.x, a0);
                a1 = fmaf(w, xq.y, a1);
                a2 = fmaf(w, xq.z, a2);
                a3 = fmaf(w, xq.w, a3);
            }
        }
    }
    __syncthreads();
    if (tid < 304) {
        int sb = sq_*4;
        if (r_ < 6) {
            xd6[r_*32 + sb]     = a0;
            xd6[r_*32 + sb + 1] = a1;
            xd6[r_*32 + sb + 2] = a2;
            xd6[r_*32 + sb + 3] = a3;
        } else {
            int slot = (r_ < 22) ? 2*(r_ - 6) : 2*(r_ - 22) + 1;
            sBC[sb][slot]     = a0;
            sBC[sb + 1][slot] = a1;
            sBC[sb + 2][slot] = a2;
            sBC[sb + 3][slot] = a3;
        }
    }
    __syncthreads();
    for (int idx = tid; idx < 32*32; idx += 320) {
        int si = idx >> 5, c = idx & 31;
        g_BC[((size_t)k*L + s0 + si)*32 + c] = sBC[si][c];
    }
    for (int idx = tid; idx < DI*32; idx += 320) {
        int d = idx >> 5, si = idx & 31;
        int row = k*DI + d;
        float acc = __ldg(dtb + row);
        #pragma unroll
        for (int r = 0; r < 6; r++)
            acc = fmaf(__ldg(dtw + row*6 + r), xd6[r*32 + si], acc);
        float dt = softplusf_(acc);
        float u = xv[d*32 + si];
        g_dtu[(size_t)row*L + s0 + si] = make_float2(dt, dt*u);
    }
}

// -------- K4: FUSED chunked scan — one block per sequence ----------------
// 512 threads = 64 chunk-units x 8 lanes (2 states per lane).
// Phase 1: local chunk scan (h, decay product via ex2(An*sum_dt)).
// Phase 2: in-smem serial chunk combine (8 threads), in-place h -> h0.
// Phase 3: re-scan with correct h0 (dtu L1-hot), emit y.
__global__ void __launch_bounds__(512) k_scan(const float* __restrict__ A_logs,
                                              const float* __restrict__ Ds) {
    __shared__ float2 s_h[NCHUNK][8];   // {h0,h1} per (chunk, lane)
    __shared__ float2 s_p[NCHUNK][8];   // {P0,P1}
    int tid = threadIdx.x;
    int unit = tid >> 3;                // chunk index 0..63
    int ln = tid & 7;
    int seq = blockIdx.x;
    int k = seq / DI;
    int d = seq - k*DI;
    bool fwd  = (k < 2);
    bool tord = (k & 1);
    const float2* pdtu = g_dtu + (size_t)seq*L;
    const float4* pBC4 = reinterpret_cast<const float4*>(g_BC + (size_t)k*L*32);
    const float LOG2E = 1.4426950408889634f;
    float An0 = -__expf(__ldg(A_logs + seq*NS + 2*ln))     * LOG2E;
    float An1 = -__expf(__ldg(A_logs + seq*NS + 2*ln + 1)) * LOG2E;
    int base = unit * CLEN;

    // ---- phase 1 ----
    {
        float h0 = 0.f, h1 = 0.f, sdt = 0.f;
        #pragma unroll 4
        for (int i = 0; i < CLEN; i++) {
            int s = fwd ? (base + i) : (L - 1 - (base + i));
            float2 dtu = __ldg(pdtu + s);
            float4 bc = __ldg(pBC4 + s*8 + ln);
            float e0 = ex2_(dtu.x * An0);
            float e1 = ex2_(dtu.x * An1);
            h0 = fmaf(e0, h0, dtu.y * bc.x);
            h1 = fmaf(e1, h1, dtu.y * bc.z);
            sdt += dtu.x;
        }
        s_h[unit][ln] = make_float2(h0, h1);
        s_p[unit][ln] = make_float2(ex2_(An0 * sdt), ex2_(An1 * sdt));
    }
    __syncthreads();

    // ---- phase 2: serial combine across chunks, in-place h -> h0 ----
    if (tid < 8) {
        float H0 = 0.f, H1 = 0.f;
        #pragma unroll 4
        for (int c = 0; c < NCHUNK; c++) {
            float2 hh = s_h[c][tid];
            float2 pp = s_p[c][tid];
            s_h[c][tid] = make_float2(H0, H1);
            H0 = fmaf(pp.x, H0, hh.x);
            H1 = fmaf(pp.y, H1, hh.y);
        }
    }
    __syncthreads();

    // ---- phase 3: re-scan with correct initial state, emit y ----
    {
        float2 hh = s_h[unit][ln];
        float h0 = hh.x, h1 = hh.y;
        float Dd = __ldg(Ds + seq);
        const float* pu = (tord ? g_xg_t : g_xg_f) + d*L;
        float* pout = g_y4 + (size_t)seq*L;
        #pragma unroll 2
        for (int i = 0; i < CLEN; i++) {
            int s = fwd ? (base + i) : (L - 1 - (base + i));
            float2 dtu = __ldg(pdtu + s);
            float4 bc = __ldg(pBC4 + s*8 + ln);
            float uu = __ldg(pu + s);
            float e0 = ex2_(dtu.x * An0);
            float e1 = ex2_(dtu.x * An1);
            h0 = fmaf(e0, h0, dtu.y * bc.x);
            h1 = fmaf(e1, h1, dtu.y * bc.z);
            float acc = fmaf(h1, bc.w, h0 * bc.y);
            acc += __shfl_xor_sync(0xffffffffu, acc, 4);
            acc += __shfl_xor_sync(0xffffffffu, acc, 2);
            acc += __shfl_xor_sync(0xffffffffu, acc, 1);
            if (ln == 0) {
                int p = tord ? (((s & 63) << 6) | (s >> 6)) : s;
                pout[p] = fmaf(uu, Dd, acc);
            }
        }
    }
}

// ---------------- K5: channel-branch (tiny), single block ----------------
__global__ void __launch_bounds__(128) k_chan(
    const float* __restrict__ cin_w, const float* __restrict__ cin_b,
    const float* __restrict__ xcw,   const float* __restrict__ dtcw,
    const float* __restrict__ dtcb,  const float* __restrict__ Ac_logs,
    const float* __restrict__ Dsc,   const float* __restrict__ cout_w,
    const float* __restrict__ cout_b,const float* __restrict__ cnw,
    const float* __restrict__ cnb) {
    __shared__ float sxc[4*DI];
    __shared__ float sdt[2*4*DI];
    __shared__ float sdu[2*4*DI];
    __shared__ float su [2*4*DI];
    __shared__ float syc[2*4*DI];
    __shared__ float sg[DI];
    __shared__ float red[128];
    __shared__ float sstat[2];
    int tid = threadIdx.x;
    for (int idx = tid; idx < 4*DI; idx += 128) {
        int ci = idx / DI, l = idx % DI;
        sxc[idx] = g_cmean[l]*cin_w[ci] + cin_b[ci];
    }
    __syncthreads();
    for (int idx = tid; idx < 2*38*DI; idx += 128) {
        int k = idx / (38*DI);
        int r = (idx / DI) % 38;
        int l = idx % DI;
        int ls = k ? (DI-1-l) : l;
        float acc = 0.f;
        #pragma unroll
        for (int ci = 0; ci < 4; ci++)
            acc = fmaf(xcw[(k*38 + r)*4 + ci], sxc[ci*DI + ls], acc);
        g_xcdbl[idx] = acc;
    }
    __syncthreads();
    for (int idx = tid; idx < 2*4*DI; idx += 128) {
        int k = idx / (4*DI);
        int ci = (idx / DI) & 3;
        int l = idx % DI;
        float acc = dtcb[k*4 + ci];
        #pragma unroll
        for (int r = 0; r < 6; r++)
            acc = fmaf(dtcw[(k*4 + ci)*6 + r], g_xcdbl[(k*38 + r)*DI + l], acc);
        float dt = softplusf_(acc);
        int ls = k ? (DI-1-l) : l;
        float u = sxc[ci*DI + ls];
        sdt[idx] = dt; sdu[idx] = dt*u; su[idx] = u;
    }
    __syncthreads();
    {
        int w = tid >> 5, lane = tid & 31;
        int n = lane & 15, half = lane >> 4;
        int seq = w*2 + half;        // 0..7
        int k = seq >> 2, ci = seq & 3;
        float An = -__expf(Ac_logs[(k*4 + ci)*16 + n]);
        float Dc = Dsc[k*4 + ci];
        int base = seq * DI;
        float h = 0.f;
        for (int l = 0; l < DI; l++) {
            float dt = sdt[base + l];
            float du = sdu[base + l];
            float bn = g_xcdbl[(k*38 + 6 + n)*DI + l];
            float cn = g_xcdbl[(k*38 + 22 + n)*DI + l];
            float e = __expf(dt * An);
            h = fmaf(e, h, du * bn);
            float acc = h * cn;
            acc += __shfl_xor_sync(0xffffffffu, acc, 8);
            acc += __shfl_xor_sync(0xffffffffu, acc, 4);
            acc += __shfl_xor_sync(0xffffffffu, acc, 2);
            acc += __shfl_xor_sync(0xffffffffu, acc, 1);
            if (n == 0) syc[base + l] = fmaf(su[base + l], Dc, acc);
        }
    }
    __syncthreads();
    for (int l = tid; l < DI; l += 128) {
        float g = cout_b[0];
        #pragma unroll
        for (int ci = 0; ci < 4; ci++)
            g = fmaf(syc[ci*DI + l] + syc[(4 + ci)*DI + (DI-1-l)], cout_w[ci], g);
        sg[l] = g;
    }
    __syncthreads();
    float p1 = 0.f, p2 = 0.f;
    for (int l = tid; l < DI; l += 128) { float v = sg[l]; p1 += v; p2 += v*v; }
    red[tid] = p1; __syncthreads();
    for (int o = 64; o > 0; o >>= 1) { if (tid < o) red[tid] += red[tid+o]; __syncthreads(); }
    if (tid == 0) sstat[0] = red[0] * (1.f/DI);
    __syncthreads();
    red[tid] = p2; __syncthreads();
    for (int o = 64; o > 0; o >>= 1) { if (tid < o) red[tid] += red[tid+o]; __syncthreads(); }
    if (tid == 0) {
        float mu = sstat[0];
        sstat[1] = rsqrtf(red[0]*(1.f/DI) - mu*mu + 1e-5f);
    }
    __syncthreads();
    float mu = sstat[0], rs = sstat[1];
    for (int l = tid; l < DI; l += 128)
        g_gate[l] = (sg[l] - mu)*rs*cnw[l] + cnb[l];
}

// ---------------- K6: combine + LN + gate*z + out-proj (192 -> 96) ----------------
__global__ void __launch_bounds__(256) k_final(const float* __restrict__ onw,
                                               const float* __restrict__ onb,
                                               const float* __restrict__ ow,
                                               const float* __restrict__ ob,
                                               float* __restrict__ out) {
    __shared__ float sv[DI*33];       // [d][si] with pad-33 pitch
    __shared__ float smu[32], srs[32];
    int tid = threadIdx.x;
    int p0 = blockIdx.x * 32;
    for (int idx = tid; idx < DI*32; idx += 256) {
        int d = idx >> 5, si = idx & 31;
        int p = p0 + si;
        float s = g_y4[(0*DI + d)*L + p] + g_y4[(1*DI + d)*L + p]
                + g_y4[(2*DI + d)*L + p] + g_y4[(3*DI + d)*L + p];
        sv[d*33 + si] = s;
    }
    __syncthreads();
    {
        int w = tid >> 5, lane = tid & 31;
        for (int q = 0; q < 4; q++) {
            int si = w*4 + q;
            float s1 = 0.f, s2 = 0.f;
            #pragma unroll
            for (int j = 0; j < 6; j++) {
                float v = sv[(lane + j*32)*33 + si];
                s1 += v; s2 += v*v;
            }
            #pragma unroll
            for (int o = 16; o > 0; o >>= 1) {
                s1 += __shfl_xor_sync(0xffffffffu, s1, o);
                s2 += __shfl_xor_sync(0xffffffffu, s2, o);
            }
            if (lane == 0) {
                float mu = s1 * (1.f/DI);
                smu[si] = mu;
                srs[si] = rsqrtf(s2*(1.f/DI) - mu*mu + 1e-5f);
            }
        }
    }
    __syncthreads();
    for (int idx = tid; idx < DI*32; idx += 256) {
        int d = idx >> 5, si = idx & 31;
        int p = p0 + si;
        float v = sv[d*33 + si];
        v = (v - smu[si]) * srs[si] * onw[d] + onb[d];
        v = v * g_gate[d] * g_z[d*L + p];
        sv[d*33 + si] = v;
    }
    __syncthreads();
    for (int idx = tid; idx < 96*32; idx += 256) {
        int o = idx >> 5, si = idx & 31;
        const float4* w4 = reinterpret_cast<const float4*>(ow + o*DI);
        float a0 = 0.f, a1 = 0.f, a2 = 0.f, a3 = 0.f;
        #pragma unroll 12
        for (int d4 = 0; d4 < 48; d4++) {
            float4 wv = __ldg(w4 + d4);
            int d = d4*4;
            a0 = fmaf(wv.x, sv[d*33+si], a0);
            a1 = fmaf(wv.y, sv[(d+1)*33+si], a1);
            a2 = fmaf(wv.z, sv[(d+2)*33+si], a2);
            a3 = fmaf(wv.w, sv[(d+3)*33+si], a3);
        }
        out[o*L + p0 + si] = ob[o] + (a0 + a1) + (a2 + a3);
    }
}

// ---------------- launch ----------------
extern "C" void kernel_launch(void* const* d_in, const int* in_sizes, int n_in,
                              void* d_out, int out_size) {
    const float* x      = (const float*)d_in[0];
    const float* in_w   = (const float*)d_in[1];
    const float* in_b   = (const float*)d_in[2];
    const float* c2w    = (const float*)d_in[3];
    const float* c2b    = (const float*)d_in[4];
    const float* xpw    = (const float*)d_in[5];
    const float* dtw    = (const float*)d_in[6];
    const float* dtb    = (const float*)d_in[7];
    const float* Alogs  = (const float*)d_in[8];
    const float* Ds     = (const float*)d_in[9];
    const float* onw    = (const float*)d_in[10];
    const float* onb    = (const float*)d_in[11];
    const float* cinw   = (const float*)d_in[12];
    const float* cinb   = (const float*)d_in[13];
    const float* coutw  = (const float*)d_in[14];
    const float* coutb  = (const float*)d_in[15];
    const float* xcw    = (const float*)d_in[16];
    const float* dtcw   = (const float*)d_in[17];
    const float* dtcb   = (const float*)d_in[18];
    const float* Aclogs = (const float*)d_in[19];
    const float* Dsc    = (const float*)d_in[20];
    const float* cnw    = (const float*)d_in[21];
    const float* cnb    = (const float*)d_in[22];
    const float* ow     = (const float*)d_in[23];
    const float* obias  = (const float*)d_in[24];
    float* out = (float*)d_out;

    k_inproj<<<dim3(32, 24), 128>>>(x, in_w, in_b);
    k_dwconv<<<dim3(2, 2, 192), dim3(32, 32)>>>(c2w, c2b);
    k_proj<<<dim3(128, 4), 320>>>(xpw, dtw, dtb);
    k_scan<<<768, 512>>>(Alogs, Ds);
    k_chan<<<1, 128>>>(cinw, cinb, xcw, dtcw, dtcb, Aclogs, Dsc, coutw, coutb, cnw, cnb);
    k_final<<<128, 256>>>(onw, onb, ow, obias, out);
}

// round 6
// speedup vs baseline: 2.6651x; 1.0707x over previous
#include <cuda_runtime.h>
#include <math.h>

#define L 4096
#define DI 192
#define NS 16
#define NCHUNK 64
#define CLEN 64

// ---------------- device scratch (static, no allocations) ----------------
__device__ float g_xg_pre[DI*L];
__device__ float g_z[DI*L];
__device__ float g_xg_f[DI*L];
__device__ float g_xg_t[DI*L];
__device__ float g_cmean[DI];
__device__ float g_BC[4*L*32];        // [k][s][n][2] : slot 2n = B_n, 2n+1 = C_n
__device__ float2 g_dtu[768*L];       // (softplus dt, u) per (seq, s)
__device__ float g_y4[4*DI*L];        // scan outputs, pixel-indexed
__device__ float g_xcdbl[2*38*DI];
__device__ float g_gate[DI];

__device__ __forceinline__ float softplusf_(float x){
    return (x > 20.f) ? x : log1pf(__expf(x));
}
__device__ __forceinline__ float ex2_(float x){
    float r;
    asm("ex2.approx.ftz.f32 %0, %1;" : "=f"(r) : "f"(x));
    return r;
}

// ---------------- K1: 1x1 in-proj (96 -> 384), 16 outputs per thread ----------
__global__ void __launch_bounds__(128) k_inproj(const float* __restrict__ x,
                                                const float* __restrict__ W,
                                                const float* __restrict__ b) {
    __shared__ float ws[96*16];   // transposed: [c][j]
    int ob = blockIdx.y * 16;
    for (int i = threadIdx.x; i < 96*16; i += 128) {
        int c = i >> 4, j = i & 15;
        ws[i] = W[(ob + j)*96 + c];
    }
    __syncthreads();
    int p = blockIdx.x * 128 + threadIdx.x;
    if (blockIdx.y == 0 && p < DI) g_cmean[p] = 0.f;   // zero for dwconv atomics
    float acc[16];
    #pragma unroll
    for (int j = 0; j < 16; j++) acc[j] = 0.f;
    #pragma unroll 2
    for (int c = 0; c < 96; c++) {
        float xv = __ldg(x + c*L + p);
        #pragma unroll
        for (int q = 0; q < 4; q++) {
            float4 w = *reinterpret_cast<const float4*>(ws + c*16 + q*4);
            acc[q*4+0] = fmaf(w.x, xv, acc[q*4+0]);
            acc[q*4+1] = fmaf(w.y, xv, acc[q*4+1]);
            acc[q*4+2] = fmaf(w.z, xv, acc[q*4+2]);
            acc[q*4+3] = fmaf(w.w, xv, acc[q*4+3]);
        }
    }
    #pragma unroll
    for (int j = 0; j < 16; j++) {
        int o = ob + j;
        float v = acc[j] + b[o];
        if (o < DI) {
            g_xg_pre[o*L + p] = v;
        } else {
            g_z[(o-DI)*L + p] = v / (1.f + __expf(-v));   // silu
        }
    }
}

// ------- K2: depthwise 3x3 + bias + silu + fused channel-mean (atomics) -------
__global__ void __launch_bounds__(1024) k_dwconv(const float* __restrict__ w,
                                                 const float* __restrict__ b) {
    __shared__ float t[32][33];
    __shared__ float wsum[32];
    int d = blockIdx.z;
    int tx = threadIdx.x, ty = threadIdx.y;
    int h = blockIdx.y*32 + ty;
    int wq = blockIdx.x*32 + tx;
    const float* src = g_xg_pre + d*L;
    float wk[9];
    #pragma unroll
    for (int i = 0; i < 9; i++) wk[i] = w[d*9 + i];
    float acc = b[d];
    #pragma unroll
    for (int kh = 0; kh < 3; kh++) {
        int hh = h + kh - 1;
        #pragma unroll
        for (int kw = 0; kw < 3; kw++) {
            int ww = wq + kw - 1;
            if (hh >= 0 && hh < 64 && ww >= 0 && ww < 64)
                acc = fmaf(wk[kh*3+kw], src[hh*64 + ww], acc);
        }
    }
    float v = acc / (1.f + __expf(-acc));   // silu
    g_xg_f[d*L + h*64 + wq] = v;
    t[ty][tx] = v;
    // block reduction for channel mean
    int tid = ty*32 + tx;
    int lane = tid & 31, wi = tid >> 5;
    float s = v;
    #pragma unroll
    for (int o = 16; o > 0; o >>= 1) s += __shfl_xor_sync(0xffffffffu, s, o);
    if (lane == 0) wsum[wi] = s;
    __syncthreads();
    float v2 = t[tx][ty];
    g_xg_t[d*L + (blockIdx.x*32 + ty)*64 + blockIdx.y*32 + tx] = v2;
    if (wi == 0) {
        float s2 = wsum[lane];
        #pragma unroll
        for (int o = 16; o > 0; o >>= 1) s2 += __shfl_xor_sync(0xffffffffu, s2, o);
        if (lane == 0) atomicAdd(&g_cmean[d], s2 * (1.f / L));
    }
}

// ---------------- K3: x-proj + dt-proj, register-tiled GEMM ----------------
__global__ void __launch_bounds__(320) k_proj(const float* __restrict__ xpw,
                                              const float* __restrict__ dtw,
                                              const float* __restrict__ dtb) {
    __shared__ float xv[DI*32];       // [d][si]  (24 KB)
    __shared__ float wsm[38*97];      // half-K weight slab, padded (14.7 KB)
    __shared__ float xd6[6*32];
    __shared__ float sBC[32][33];     // [si][slot]
    int tid = threadIdx.x;
    int s0 = blockIdx.x * 32;
    int oid = blockIdx.y & 1;
    int kk  = blockIdx.y >> 1;
    int k = oid + kk*2;
    const float* uptr = oid ? g_xg_t : g_xg_f;
    for (int i4 = tid; i4 < DI*8; i4 += 320) {
        int d = i4 >> 3, j = i4 & 7;
        float4 v = *reinterpret_cast<const float4*>(uptr + d*L + s0 + j*4);
        *reinterpret_cast<float4*>(xv + d*32 + j*4) = v;
    }
    int r_ = tid >> 3, sq_ = tid & 7;
    float a0 = 0.f, a1 = 0.f, a2 = 0.f, a3 = 0.f;
    #pragma unroll
    for (int half = 0; half < 2; half++) {
        __syncthreads();
        for (int i = tid; i < 38*96; i += 320) {
            int r = i / 96, dd = i - r*96;
            wsm[r*97 + dd] = __ldg(xpw + (k*38 + r)*192 + half*96 + dd);
        }
        __syncthreads();
        if (tid < 304) {
            const float* wr = wsm + r_*97;
            const float* xb = xv + sq_*4 + half*96*32;
            #pragma unroll 4
            for (int dd = 0; dd < 96; dd++) {
                float w = wr[dd];
                float4 xq = *reinterpret_cast<const float4*>(xb + dd*32);
                a0 = fmaf(w, xq.x, a0);
                a1 = fmaf(w, xq.y, a1);
                a2 = fmaf(w, xq.z, a2);
                a3 = fmaf(w, xq.w, a3);
            }
        }
    }
    __syncthreads();
    if (tid < 304) {
        int sb = sq_*4;
        if (r_ < 6) {
            xd6[r_*32 + sb]     = a0;
            xd6[r_*32 + sb + 1] = a1;
            xd6[r_*32 + sb + 2] = a2;
            xd6[r_*32 + sb + 3] = a3;
        } else {
            int slot = (r_ < 22) ? 2*(r_ - 6) : 2*(r_ - 22) + 1;
            sBC[sb][slot]     = a0;
            sBC[sb + 1][slot] = a1;
            sBC[sb + 2][slot] = a2;
            sBC[sb + 3][slot] = a3;
        }
    }
    __syncthreads();
    for (int idx = tid; idx < 32*32; idx += 320) {
        int si = idx >> 5, c = idx & 31;
        g_BC[((size_t)k*L + s0 + si)*32 + c] = sBC[si][c];
    }
    for (int idx = tid; idx < DI*32; idx += 320) {
        int d = idx >> 5, si = idx & 31;
        int row = k*DI + d;
        float acc = __ldg(dtb + row);
        #pragma unroll
        for (int r = 0; r < 6; r++)
            acc = fmaf(__ldg(dtw + row*6 + r), xd6[r*32 + si], acc);
        float dt = softplusf_(acc);
        float u = xv[d*32 + si];
        g_dtu[(size_t)row*L + s0 + si] = make_float2(dt, u);   // (dt, u)
    }
}

// -------- K4: FUSED chunked scan, wavefront-economical ----------------
// 512 threads = 64 chunk-units x 8 lanes (2 states per lane).
// 2 steps per iteration: float4 dtu load (1 wf / 2 steps), u carried (no uu load),
// joint 4-shfl reduction for 2 outputs, coalesced 8-wide stores for f-order.
template<bool FWD, bool TORD>
__device__ __forceinline__ void scan_body(
    const float4* __restrict__ pdtu4, const float4* __restrict__ pBC4,
    float* __restrict__ pout, float An0, float An1, float Dd,
    int base, int ln, int unit, int tid,
    float2 (*s_h)[8], float2 (*s_p)[8])
{
    // ---- phase 1: local chunk scan ----
    float h0 = 0.f, h1 = 0.f, sdt = 0.f;
    #pragma unroll 4
    for (int j = 0; j < 32; j++) {
        int sA = FWD ? (base + 2*j) : (L - 1 - base - 2*j);
        int sB = FWD ? (sA + 1) : (sA - 1);
        float4 q = __ldg(pdtu4 + ((FWD ? sA : sB) >> 1));
        float dtA = FWD ? q.x : q.z, uA = FWD ? q.y : q.w;
        float dtB = FWD ? q.z : q.x, uB = FWD ? q.w : q.y;
        float4 bcA = __ldg(pBC4 + sA*8 + ln);
        float4 bcB = __ldg(pBC4 + sB*8 + ln);
        float duA = dtA*uA, duB = dtB*uB;
        h0 = fmaf(ex2_(dtA*An0), h0, duA*bcA.x);
        h1 = fmaf(ex2_(dtA*An1), h1, duA*bcA.z);
        h0 = fmaf(ex2_(dtB*An0), h0, duB*bcB.x);
        h1 = fmaf(ex2_(dtB*An1), h1, duB*bcB.z);
        sdt += dtA + dtB;
    }
    s_h[unit][ln] = make_float2(h0, h1);
    s_p[unit][ln] = make_float2(ex2_(An0*sdt), ex2_(An1*sdt));
    __syncthreads();

    // ---- phase 2: serial combine across chunks, in-place h -> h0 ----
    if (tid < 8) {
        float H0 = 0.f, H1 = 0.f;
        #pragma unroll 4
        for (int c = 0; c < NCHUNK; c++) {
            float2 hh = s_h[c][tid];
            float2 pp = s_p[c][tid];
            s_h[c][tid] = make_float2(H0, H1);
            H0 = fmaf(pp.x, H0, hh.x);
            H1 = fmaf(pp.y, H1, hh.y);
        }
    }
    __syncthreads();

    // ---- phase 3: re-scan with correct initial state, emit y ----
    float2 hh = s_h[unit][ln];
    h0 = hh.x; h1 = hh.y;
    float ybuf = 0.f;
    #pragma unroll 2
    for (int j = 0; j < 32; j++) {
        int sA = FWD ? (base + 2*j) : (L - 1 - base - 2*j);
        int sB = FWD ? (sA + 1) : (sA - 1);
        float4 q = __ldg(pdtu4 + ((FWD ? sA : sB) >> 1));
        float dtA = FWD ? q.x : q.z, uA = FWD ? q.y : q.w;
        float dtB = FWD ? q.z : q.x, uB = FWD ? q.w : q.y;
        float4 bcA = __ldg(pBC4 + sA*8 + ln);
        float4 bcB = __ldg(pBC4 + sB*8 + ln);
        float duA = dtA*uA, duB = dtB*uB;
        h0 = fmaf(ex2_(dtA*An0), h0, duA*bcA.x);
        h1 = fmaf(ex2_(dtA*An1), h1, duA*bcA.z);
        float accA = fmaf(h1, bcA.w, h0*bcA.y);
        h0 = fmaf(ex2_(dtB*An0), h0, duB*bcB.x);
        h1 = fmaf(ex2_(dtB*An1), h1, duB*bcB.z);
        float accB = fmaf(h1, bcB.w, h0*bcB.y);
        // joint reduce: 4 shfls for 2 outputs.
        // After this, even lanes hold full accA sum, odd lanes full accB sum.
        accA += __shfl_xor_sync(0xffffffffu, accA, 1);
        accB += __shfl_xor_sync(0xffffffffu, accB, 1);
        float u2 = (ln & 1) ? accB : accA;
        u2 += __shfl_xor_sync(0xffffffffu, u2, 2);
        u2 += __shfl_xor_sync(0xffffffffu, u2, 4);
        float yA = fmaf(uA, Dd, u2);   // valid on even lanes
        float yB = fmaf(uB, Dd, u2);   // valid on odd lanes
        if (TORD) {
            if (ln == 0)      pout[((sA & 63) << 6) | (sA >> 6)] = yA;
            else if (ln == 1) pout[((sB & 63) << 6) | (sB >> 6)] = yB;
        } else {
            int tgt = (2*j) & 7;
            if (ln == tgt)          ybuf = yA;
            else if (ln == tgt + 1) ybuf = yB;
            if ((j & 3) == 3) {
                int il = base + 8*(j >> 2) + ln;       // scan-order index
                pout[FWD ? il : (L - 1 - il)] = ybuf;  // coalesced 8-wide
            }
        }
    }
}

__global__ void __launch_bounds__(512) k_scan(const float* __restrict__ A_logs,
                                              const float* __restrict__ Ds) {
    __shared__ float2 s_h[NCHUNK][8];
    __shared__ float2 s_p[NCHUNK][8];
    int tid = threadIdx.x;
    int unit = tid >> 3;
    int ln = tid & 7;
    int seq = blockIdx.x;
    int k = seq / DI;
    const float4* pdtu4 = reinterpret_cast<const float4*>(g_dtu + (size_t)seq*L);
    const float4* pBC4 = reinterpret_cast<const float4*>(g_BC + (size_t)k*L*32);
    float* pout = g_y4 + (size_t)seq*L;
    const float LOG2E = 1.4426950408889634f;
    float An0 = -__expf(__ldg(A_logs + seq*NS + 2*ln))     * LOG2E;
    float An1 = -__expf(__ldg(A_logs + seq*NS + 2*ln + 1)) * LOG2E;
    float Dd = __ldg(Ds + seq);
    int base = unit * CLEN;
    if (k == 0)      scan_body<true,  false>(pdtu4, pBC4, pout, An0, An1, Dd, base, ln, unit, tid, s_h, s_p);
    else if (k == 1) scan_body<true,  true >(pdtu4, pBC4, pout, An0, An1, Dd, base, ln, unit, tid, s_h, s_p);
    else if (k == 2) scan_body<false, false>(pdtu4, pBC4, pout, An0, An1, Dd, base, ln, unit, tid, s_h, s_p);
    else             scan_body<false, true >(pdtu4, pBC4, pout, An0, An1, Dd, base, ln, unit, tid, s_h, s_p);
}

// ---------------- K5: channel-branch (tiny), single block ----------------
__global__ void __launch_bounds__(128) k_chan(
    const float* __restrict__ cin_w, const float* __restrict__ cin_b,
    const float* __restrict__ xcw,   const float* __restrict__ dtcw,
    const float* __restrict__ dtcb,  const float* __restrict__ Ac_logs,
    const float* __restrict__ Dsc,   const float* __restrict__ cout_w,
    const float* __restrict__ cout_b,const float* __restrict__ cnw,
    const float* __restrict__ cnb) {
    __shared__ float sxc[4*DI];
    __shared__ float sdt[2*4*DI];
    __shared__ float sdu[2*4*DI];
    __shared__ float su [2*4*DI];
    __shared__ float syc[2*4*DI];
    __shared__ float sg[DI];
    __shared__ float red[128];
    __shared__ float sstat[2];
    int tid = threadIdx.x;
    for (int idx = tid; idx < 4*DI; idx += 128) {
        int ci = idx / DI, l = idx % DI;
        sxc[idx] = g_cmean[l]*cin_w[ci] + cin_b[ci];
    }
    __syncthreads();
    for (int idx = tid; idx < 2*38*DI; idx += 128) {
        int k = idx / (38*DI);
        int r = (idx / DI) % 38;
        int l = idx % DI;
        int ls = k ? (DI-1-l) : l;
        float acc = 0.f;
        #pragma unroll
        for (int ci = 0; ci < 4; ci++)
            acc = fmaf(xcw[(k*38 + r)*4 + ci], sxc[ci*DI + ls], acc);
        g_xcdbl[idx] = acc;
    }
    __syncthreads();
    for (int idx = tid; idx < 2*4*DI; idx += 128) {
        int k = idx / (4*DI);
        int ci = (idx / DI) & 3;
        int l = idx % DI;
        float acc = dtcb[k*4 + ci];
        #pragma unroll
        for (int r = 0; r < 6; r++)
            acc = fmaf(dtcw[(k*4 + ci)*6 + r], g_xcdbl[(k*38 + r)*DI + l], acc);
        float dt = softplusf_(acc);
        int ls = k ? (DI-1-l) : l;
        float u = sxc[ci*DI + ls];
        sdt[idx] = dt; sdu[idx] = dt*u; su[idx] = u;
    }
    __syncthreads();
    {
        int w = tid >> 5, lane = tid & 31;
        int n = lane & 15, half = lane >> 4;
        int seq = w*2 + half;        // 0..7
        int k = seq >> 2, ci = seq & 3;
        float An = -__expf(Ac_logs[(k*4 + ci)*16 + n]);
        float Dc = Dsc[k*4 + ci];
        int base = seq * DI;
        float h = 0.f;
        for (int l = 0; l < DI; l++) {
            float dt = sdt[base + l];
            float du = sdu[base + l];
            float bn = g_xcdbl[(k*38 + 6 + n)*DI + l];
            float cn = g_xcdbl[(k*38 + 22 + n)*DI + l];
            float e = __expf(dt * An);
            h = fmaf(e, h, du * bn);
            float acc = h * cn;
            acc += __shfl_xor_sync(0xffffffffu, acc, 8);
            acc += __shfl_xor_sync(0xffffffffu, acc, 4);
            acc += __shfl_xor_sync(0xffffffffu, acc, 2);
            acc += __shfl_xor_sync(0xffffffffu, acc, 1);
            if (n == 0) syc[base + l] = fmaf(su[base + l], Dc, acc);
        }
    }
    __syncthreads();
    for (int l = tid; l < DI; l += 128) {
        float g = cout_b[0];
        #pragma unroll
        for (int ci = 0; ci < 4; ci++)
            g = fmaf(syc[ci*DI + l] + syc[(4 + ci)*DI + (DI-1-l)], cout_w[ci], g);
        sg[l] = g;
    }
    __syncthreads();
    float p1 = 0.f, p2 = 0.f;
    for (int l = tid; l < DI; l += 128) { float v = sg[l]; p1 += v; p2 += v*v; }
    red[tid] = p1; __syncthreads();
    for (int o = 64; o > 0; o >>= 1) { if (tid < o) red[tid] += red[tid+o]; __syncthreads(); }
    if (tid == 0) sstat[0] = red[0] * (1.f/DI);
    __syncthreads();
    red[tid] = p2; __syncthreads();
    for (int o = 64; o > 0; o >>= 1) { if (tid < o) red[tid] += red[tid+o]; __syncthreads(); }
    if (tid == 0) {
        float mu = sstat[0];
        sstat[1] = rsqrtf(red[0]*(1.f/DI) - mu*mu + 1e-5f);
    }
    __syncthreads();
    float mu = sstat[0], rs = sstat[1];
    for (int l = tid; l < DI; l += 128)
        g_gate[l] = (sg[l] - mu)*rs*cnw[l] + cnb[l];
}

// ---------------- K6: combine + LN + gate*z + out-proj (192 -> 96) ----------------
__global__ void __launch_bounds__(256) k_final(const float* __restrict__ onw,
                                               const float* __restrict__ onb,
                                               const float* __restrict__ ow,
                                               const float* __restrict__ ob,
                                               float* __restrict__ out) {
    __shared__ float sv[DI*33];       // [d][si] with pad-33 pitch
    __shared__ float smu[32], srs[32];
    int tid = threadIdx.x;
    int p0 = blockIdx.x * 32;
    for (int idx = tid; idx < DI*32; idx += 256) {
        int d = idx >> 5, si = idx & 31;
        int p = p0 + si;
        float s = g_y4[(0*DI + d)*L + p] + g_y4[(1*DI + d)*L + p]
                + g_y4[(2*DI + d)*L + p] + g_y4[(3*DI + d)*L + p];
        sv[d*33 + si] = s;
    }
    __syncthreads();
    {
        int w = tid >> 5, lane = tid & 31;
        for (int q = 0; q < 4; q++) {
            int si = w*4 + q;
            float s1 = 0.f, s2 = 0.f;
            #pragma unroll
            for (int j = 0; j < 6; j++) {
                float v = sv[(lane + j*32)*33 + si];
                s1 += v; s2 += v*v;
            }
            #pragma unroll
            for (int o = 16; o > 0; o >>= 1) {
                s1 += __shfl_xor_sync(0xffffffffu, s1, o);
                s2 += __shfl_xor_sync(0xffffffffu, s2, o);
            }
            if (lane == 0) {
                float mu = s1 * (1.f/DI);
                smu[si] = mu;
                srs[si] = rsqrtf(s2*(1.f/DI) - mu*mu + 1e-5f);
            }
        }
    }
    __syncthreads();
    for (int idx = tid; idx < DI*32; idx += 256) {
        int d = idx >> 5, si = idx & 31;
        int p = p0 + si;
        float v = sv[d*33 + si];
        v = (v - smu[si]) * srs[si] * onw[d] + onb[d];
        v = v * g_gate[d] * g_z[d*L + p];
        sv[d*33 + si] = v;
    }
    __syncthreads();
    for (int idx = tid; idx < 96*32; idx += 256) {
        int o = idx >> 5, si = idx & 31;
        const float4* w4 = reinterpret_cast<const float4*>(ow + o*DI);
        float a0 = 0.f, a1 = 0.f, a2 = 0.f, a3 = 0.f;
        #pragma unroll 12
        for (int d4 = 0; d4 < 48; d4++) {
            float4 wv = __ldg(w4 + d4);
            int d = d4*4;
            a0 = fmaf(wv.x, sv[d*33+si], a0);
            a1 = fmaf(wv.y, sv[(d+1)*33+si], a1);
            a2 = fmaf(wv.z, sv[(d+2)*33+si], a2);
            a3 = fmaf(wv.w, sv[(d+3)*33+si], a3);
        }
        out[o*L + p0 + si] = ob[o] + (a0 + a1) + (a2 + a3);
    }
}

// ---------------- launch ----------------
extern "C" void kernel_launch(void* const* d_in, const int* in_sizes, int n_in,
                              void* d_out, int out_size) {
    const float* x      = (const float*)d_in[0];
    const float* in_w   = (const float*)d_in[1];
    const float* in_b   = (const float*)d_in[2];
    const float* c2w    = (const float*)d_in[3];
    const float* c2b    = (const float*)d_in[4];
    const float* xpw    = (const float*)d_in[5];
    const float* dtw    = (const float*)d_in[6];
    const float* dtb    = (const float*)d_in[7];
    const float* Alogs  = (const float*)d_in[8];
    const float* Ds     = (const float*)d_in[9];
    const float* onw    = (const float*)d_in[10];
    const float* onb    = (const float*)d_in[11];
    const float* cinw   = (const float*)d_in[12];
    const float* cinb   = (const float*)d_in[13];
    const float* coutw  = (const float*)d_in[14];
    const float* coutb  = (const float*)d_in[15];
    const float* xcw    = (const float*)d_in[16];
    const float* dtcw   = (const float*)d_in[17];
    const float* dtcb   = (const float*)d_in[18];
    const float* Aclogs = (const float*)d_in[19];
    const float* Dsc    = (const float*)d_in[20];
    const float* cnw    = (const float*)d_in[21];
    const float* cnb    = (const float*)d_in[22];
    const float* ow     = (const float*)d_in[23];
    const float* obias  = (const float*)d_in[24];
    float* out = (float*)d_out;

    k_inproj<<<dim3(32, 24), 128>>>(x, in_w, in_b);
    k_dwconv<<<dim3(2, 2, 192), dim3(32, 32)>>>(c2w, c2b);
    k_proj<<<dim3(128, 4), 320>>>(xpw, dtw, dtb);
    k_scan<<<768, 512>>>(Alogs, Ds);
    k_chan<<<1, 128>>>(cinw, cinb, xcw, dtcw, dtcb, Aclogs, Dsc, coutw, coutb, cnw, cnb);
    k_final<<<128, 256>>>(onw, onb, ow, obias, out);
}

// round 7
// speedup vs baseline: 2.7056x; 1.0152x over previous
#include <cuda_runtime.h>
#include <math.h>

#define L 4096
#define DI 192
#define NS 16
#define NCHUNK 32
#define CLEN 128

// ---------------- device scratch (static, no allocations) ----------------
__device__ float g_xg_pre[DI*L];
__device__ float g_z[DI*L];
__device__ float g_xg_f[DI*L];
__device__ float g_xg_t[DI*L];
__device__ float g_cmean[DI];
// chunk-interleaved scan inputs:
//   g_B2[k][i(128)][c(32)][8 float2]  : B states for step s = c*128+i
//   g_C2 same for C
//   g_dtu4[seq][i2(64)][c(32)]        : (dtA,uA,dtB,uB) for steps 2*i2, 2*i2+1 of chunk c
__device__ float2 g_B2[4*4096*8];
__device__ float2 g_C2[4*4096*8];
__device__ float4 g_dtu4[768*2048];
__device__ float g_y4[4*DI*L];        // scan outputs, pixel-indexed
__device__ float g_xcdbl[2*38*DI];
__device__ float g_gate[DI];

__device__ __forceinline__ float softplusf_(float x){
    return (x > 20.f) ? x : log1pf(__expf(x));
}
__device__ __forceinline__ float ex2_(float x){
    float r;
    asm("ex2.approx.ftz.f32 %0, %1;" : "=f"(r) : "f"(x));
    return r;
}

// ---------------- K1: 1x1 in-proj (96 -> 384), 16 outputs per thread ----------
__global__ void __launch_bounds__(128) k_inproj(const float* __restrict__ x,
                                                const float* __restrict__ W,
                                                const float* __restrict__ b) {
    __shared__ float ws[96*16];   // transposed: [c][j]
    int ob = blockIdx.y * 16;
    for (int i = threadIdx.x; i < 96*16; i += 128) {
        int c = i >> 4, j = i & 15;
        ws[i] = W[(ob + j)*96 + c];
    }
    __syncthreads();
    int p = blockIdx.x * 128 + threadIdx.x;
    if (blockIdx.y == 0 && p < DI) g_cmean[p] = 0.f;   // zero for dwconv atomics
    float acc[16];
    #pragma unroll
    for (int j = 0; j < 16; j++) acc[j] = 0.f;
    #pragma unroll 2
    for (int c = 0; c < 96; c++) {
        float xv = __ldg(x + c*L + p);
        #pragma unroll
        for (int q = 0; q < 4; q++) {
            float4 w = *reinterpret_cast<const float4*>(ws + c*16 + q*4);
            acc[q*4+0] = fmaf(w.x, xv, acc[q*4+0]);
            acc[q*4+1] = fmaf(w.y, xv, acc[q*4+1]);
            acc[q*4+2] = fmaf(w.z, xv, acc[q*4+2]);
            acc[q*4+3] = fmaf(w.w, xv, acc[q*4+3]);
        }
    }
    #pragma unroll
    for (int j = 0; j < 16; j++) {
        int o = ob + j;
        float v = acc[j] + b[o];
        if (o < DI) {
            g_xg_pre[o*L + p] = v;
        } else {
            g_z[(o-DI)*L + p] = v / (1.f + __expf(-v));   // silu
        }
    }
}

// ------- K2: depthwise 3x3 + bias + silu + fused channel-mean (atomics) -------
__global__ void __launch_bounds__(1024) k_dwconv(const float* __restrict__ w,
                                                 const float* __restrict__ b) {
    __shared__ float t[32][33];
    __shared__ float wsum[32];
    int d = blockIdx.z;
    int tx = threadIdx.x, ty = threadIdx.y;
    int h = blockIdx.y*32 + ty;
    int wq = blockIdx.x*32 + tx;
    const float* src = g_xg_pre + d*L;
    float wk[9];
    #pragma unroll
    for (int i = 0; i < 9; i++) wk[i] = w[d*9 + i];
    float acc = b[d];
    #pragma unroll
    for (int kh = 0; kh < 3; kh++) {
        int hh = h + kh - 1;
        #pragma unroll
        for (int kw = 0; kw < 3; kw++) {
            int ww = wq + kw - 1;
            if (hh >= 0 && hh < 64 && ww >= 0 && ww < 64)
                acc = fmaf(wk[kh*3+kw], src[hh*64 + ww], acc);
        }
    }
    float v = acc / (1.f + __expf(-acc));   // silu
    g_xg_f[d*L + h*64 + wq] = v;
    t[ty][tx] = v;
    // block reduction for channel mean
    int tid = ty*32 + tx;
    int lane = tid & 31, wi = tid >> 5;
    float s = v;
    #pragma unroll
    for (int o = 16; o > 0; o >>= 1) s += __shfl_xor_sync(0xffffffffu, s, o);
    if (lane == 0) wsum[wi] = s;
    __syncthreads();
    float v2 = t[tx][ty];
    g_xg_t[d*L + (blockIdx.x*32 + ty)*64 + blockIdx.y*32 + tx] = v2;
    if (wi == 0) {
        float s2 = wsum[lane];
        #pragma unroll
        for (int o = 16; o > 0; o >>= 1) s2 += __shfl_xor_sync(0xffffffffu, s2, o);
        if (lane == 0) atomicAdd(&g_cmean[d], s2 * (1.f / L));
    }
}

// ---------------- K3: x-proj + dt-proj, register-tiled GEMM ----------------
// grid (128, 4): 32 pixels per block; writes chunk-interleaved B/C/dtu layouts.
__global__ void __launch_bounds__(320) k_proj(const float* __restrict__ xpw,
                                              const float* __restrict__ dtw,
                                              const float* __restrict__ dtb) {
    __shared__ float xv[DI*32];       // [d][si]  (24 KB)
    __shared__ float wsm[38*97];      // half-K weight slab, padded (14.7 KB)
    __shared__ float xd6[6*32];
    __shared__ float sBC[32][33];     // [si][slot]  even=B_n, odd=C_n
    int tid = threadIdx.x;
    int s0 = blockIdx.x * 32;
    int oid = blockIdx.y & 1;
    int kk  = blockIdx.y >> 1;
    int k = oid + kk*2;
    int c0 = s0 >> 7;                 // chunk (same for all 32 pixels)
    int i0 = s0 & 127;                // step-in-chunk base (multiple of 32)
    const float* uptr = oid ? g_xg_t : g_xg_f;
    for (int i4 = tid; i4 < DI*8; i4 += 320) {
        int d = i4 >> 3, j = i4 & 7;
        float4 v = *reinterpret_cast<const float4*>(uptr + d*L + s0 + j*4);
        *reinterpret_cast<float4*>(xv + d*32 + j*4) = v;
    }
    int r_ = tid >> 3, sq_ = tid & 7;
    float a0 = 0.f, a1 = 0.f, a2 = 0.f, a3 = 0.f;
    #pragma unroll
    for (int half = 0; half < 2; half++) {
        __syncthreads();
        for (int i = tid; i < 38*96; i += 320) {
            int r = i / 96, dd = i - r*96;
            wsm[r*97 + dd] = __ldg(xpw + (k*38 + r)*192 + half*96 + dd);
        }
        __syncthreads();
        if (tid < 304) {
            const float* wr = wsm + r_*97;
            const float* xb = xv + sq_*4 + half*96*32;
            #pragma unroll 4
            for (int dd = 0; dd < 96; dd++) {
                float w = wr[dd];
                float4 xq = *reinterpret_cast<const float4*>(xb + dd*32);
                a0 = fmaf(w, xq.x, a0);
                a1 = fmaf(w, xq.y, a1);
                a2 = fmaf(w, xq.z, a2);
                a3 = fmaf(w, xq.w, a3);
            }
        }
    }
    __syncthreads();
    if (tid < 304) {
        int sb = sq_*4;
        if (r_ < 6) {
            xd6[r_*32 + sb]     = a0;
            xd6[r_*32 + sb + 1] = a1;
            xd6[r_*32 + sb + 2] = a2;
            xd6[r_*32 + sb + 3] = a3;
        } else {
            int slot = (r_ < 22) ? 2*(r_ - 6) : 2*(r_ - 22) + 1;
            sBC[sb][slot]     = a0;
            sBC[sb + 1][slot] = a1;
            sBC[sb + 2][slot] = a2;
            sBC[sb + 3][slot] = a3;
        }
    }
    __syncthreads();
    // write B and C to chunk-interleaved layout
    float* gB = reinterpret_cast<float*>(g_B2);
    float* gC = reinterpret_cast<float*>(g_C2);
    for (int idx = tid; idx < 32*16; idx += 320) {
        int si = idx >> 4, n = idx & 15;
        int fo = (k*4096 + (i0 + si)*32 + c0)*16 + n;
        gB[fo] = sBC[si][2*n];
        gC[fo] = sBC[si][2*n + 1];
    }
    // dt-proj + write (dt, u) pairs to chunk-interleaved float4 layout
    float2* dtu2 = reinterpret_cast<float2*>(g_dtu4);
    for (int idx = tid; idx < DI*32; idx += 320) {
        int d = idx >> 5, si = idx & 31;
        int row = k*DI + d;
        float acc = __ldg(dtb + row);
        #pragma unroll
        for (int r = 0; r < 6; r++)
            acc = fmaf(__ldg(dtw + row*6 + r), xd6[r*32 + si], acc);
        float dt = softplusf_(acc);
        float u = xv[d*32 + si];
        int i = i0 + si;
        int idx2 = row*4096 + (i >> 1)*64 + c0*2 + (i & 1);
        dtu2[idx2] = make_float2(dt, u);
    }
}

// -------- K4: FUSED chunked scan, warp-dense loads, single wave ----------
// 256 threads = 32 chunks x 8 lanes (2 states/lane), CLEN=128.
// Warp's 4 units read the same step offset in 4 adjacent chunks -> dense lines.
template<bool FWD, bool TORD>
__device__ __forceinline__ void scan_body(
    const float4* __restrict__ pdtu4, const float2* __restrict__ pB2,
    const float2* __restrict__ pC2, float* __restrict__ pout,
    float An0, float An1, float Dd, int c, int ln, int tid,
    float2 (*s_h)[8], float2 (*s_p)[8])
{
    // ---- phase 1: local chunk scan (B only) ----
    float h0 = 0.f, h1 = 0.f, sdt = 0.f;
    #pragma unroll 4
    for (int j = 0; j < 64; j++) {
        int iA = FWD ? (2*j) : (127 - 2*j);
        int iB = FWD ? (iA + 1) : (iA - 1);
        float4 q = pdtu4[(FWD ? j : (63 - j))*32 + c];
        float dtA = FWD ? q.x : q.z, uA = FWD ? q.y : q.w;
        float dtB = FWD ? q.z : q.x, uB = FWD ? q.w : q.y;
        float2 bA = pB2[(iA*32 + c)*8 + ln];
        float2 bB = pB2[(iB*32 + c)*8 + ln];
        float duA = dtA*uA, duB = dtB*uB;
        h0 = fmaf(ex2_(dtA*An0), h0, duA*bA.x);
        h1 = fmaf(ex2_(dtA*An1), h1, duA*bA.y);
        h0 = fmaf(ex2_(dtB*An0), h0, duB*bB.x);
        h1 = fmaf(ex2_(dtB*An1), h1, duB*bB.y);
        sdt += dtA + dtB;
    }
    s_h[c][ln] = make_float2(h0, h1);
    s_p[c][ln] = make_float2(ex2_(An0*sdt), ex2_(An1*sdt));
    __syncthreads();

    // ---- phase 2: serial combine across chunks (scan order), in-place h -> h0 ----
    if (tid < 8) {
        float H0 = 0.f, H1 = 0.f;
        #pragma unroll 4
        for (int cc = 0; cc < NCHUNK; cc++) {
            int c2 = FWD ? cc : (NCHUNK - 1 - cc);
            float2 hh = s_h[c2][tid];
            float2 pp = s_p[c2][tid];
            s_h[c2][tid] = make_float2(H0, H1);
            H0 = fmaf(pp.x, H0, hh.x);
            H1 = fmaf(pp.y, H1, hh.y);
        }
    }
    __syncthreads();

    // ---- phase 3: re-scan with correct initial state, emit y ----
    float2 hh = s_h[c][ln];
    h0 = hh.x; h1 = hh.y;
    float ybuf = 0.f;
    const int pa = FWD ? 0 : 1;       // parity of sA
    #pragma unroll 4
    for (int j = 0; j < 64; j++) {
        int iA = FWD ? (2*j) : (127 - 2*j);
        int iB = FWD ? (iA + 1) : (iA - 1);
        int sA = c*CLEN + iA;
        int sB = c*CLEN + iB;
        float4 q = pdtu4[(FWD ? j : (63 - j))*32 + c];
        float dtA = FWD ? q.x : q.z, uA = FWD ? q.y : q.w;
        float dtB = FWD ? q.z : q.x, uB = FWD ? q.w : q.y;
        float2 bA = pB2[(iA*32 + c)*8 + ln];
        float2 bB = pB2[(iB*32 + c)*8 + ln];
        float2 cA = pC2[(iA*32 + c)*8 + ln];
        float2 cB = pC2[(iB*32 + c)*8 + ln];
        float duA = dtA*uA, duB = dtB*uB;
        h0 = fmaf(ex2_(dtA*An0), h0, duA*bA.x);
        h1 = fmaf(ex2_(dtA*An1), h1, duA*bA.y);
        float accA = fmaf(h1, cA.y, h0*cA.x);
        h0 = fmaf(ex2_(dtB*An0), h0, duB*bB.x);
        h1 = fmaf(ex2_(dtB*An1), h1, duB*bB.y);
        float accB = fmaf(h1, cB.y, h0*cB.x);
        // joint reduce: lanes with parity pa end with full accA, others accB
        accA += __shfl_xor_sync(0xffffffffu, accA, 1);
        accB += __shfl_xor_sync(0xffffffffu, accB, 1);
        float u2 = ((ln & 1) == pa) ? accA : accB;
        u2 += __shfl_xor_sync(0xffffffffu, u2, 2);
        u2 += __shfl_xor_sync(0xffffffffu, u2, 4);
        float yA = fmaf(uA, Dd, u2);   // valid on lanes with parity pa
        float yB = fmaf(uB, Dd, u2);   // valid on lanes with parity 1-pa
        if (TORD) {
            if (ln == pa)     pout[((sA & 63) << 6) | (sA >> 6)] = yA;
            if (ln == 1 - pa) pout[((sB & 63) << 6) | (sB >> 6)] = yB;
        } else {
            int tgtA = sA & 7, tgtB = sB & 7;
            if (ln == tgtA)      ybuf = yA;
            else if (ln == tgtB) ybuf = yB;
            if ((j & 3) == 3)
                pout[(sA & ~7) + ln] = ybuf;   // coalesced 8-wide
        }
    }
}

__global__ void __launch_bounds__(256) k_scan(const float* __restrict__ A_logs,
                                              const float* __restrict__ Ds) {
    __shared__ float2 s_h[NCHUNK][8];
    __shared__ float2 s_p[NCHUNK][8];
    int tid = threadIdx.x;
    int c = tid >> 3;
    int ln = tid & 7;
    int seq = blockIdx.x;
    int k = seq / DI;
    const float4* pdtu4 = g_dtu4 + (size_t)seq*2048;
    const float2* pB2 = g_B2 + (size_t)k*4096*8;
    const float2* pC2 = g_C2 + (size_t)k*4096*8;
    float* pout = g_y4 + (size_t)seq*L;
    const float LOG2E = 1.4426950408889634f;
    float An0 = -__expf(__ldg(A_logs + seq*NS + 2*ln))     * LOG2E;
    float An1 = -__expf(__ldg(A_logs + seq*NS + 2*ln + 1)) * LOG2E;
    float Dd = __ldg(Ds + seq);
    if (k == 0)      scan_body<true,  false>(pdtu4, pB2, pC2, pout, An0, An1, Dd, c, ln, tid, s_h, s_p);
    else if (k == 1) scan_body<true,  true >(pdtu4, pB2, pC2, pout, An0, An1, Dd, c, ln, tid, s_h, s_p);
    else if (k == 2) scan_body<false, false>(pdtu4, pB2, pC2, pout, An0, An1, Dd, c, ln, tid, s_h, s_p);
    else             scan_body<false, true >(pdtu4, pB2, pC2, pout, An0, An1, Dd, c, ln, tid, s_h, s_p);
}

// ---------------- K5: channel-branch (tiny), single block ----------------
__global__ void __launch_bounds__(128) k_chan(
    const float* __restrict__ cin_w, const float* __restrict__ cin_b,
    const float* __restrict__ xcw,   const float* __restrict__ dtcw,
    const float* __restrict__ dtcb,  const float* __restrict__ Ac_logs,
    const float* __restrict__ Dsc,   const float* __restrict__ cout_w,
    const float* __restrict__ cout_b,const float* __restrict__ cnw,
    const float* __restrict__ cnb) {
    __shared__ float sxc[4*DI];
    __shared__ float sdt[2*4*DI];
    __shared__ float sdu[2*4*DI];
    __shared__ float su [2*4*DI];
    __shared__ float syc[2*4*DI];
    __shared__ float sg[DI];
    __shared__ float red[128];
    __shared__ float sstat[2];
    int tid = threadIdx.x;
    for (int idx = tid; idx < 4*DI; idx += 128) {
        int ci = idx / DI, l = idx % DI;
        sxc[idx] = g_cmean[l]*cin_w[ci] + cin_b[ci];
    }
    __syncthreads();
    for (int idx = tid; idx < 2*38*DI; idx += 128) {
        int k = idx / (38*DI);
        int r = (idx / DI) % 38;
        int l = idx % DI;
        int ls = k ? (DI-1-l) : l;
        float acc = 0.f;
        #pragma unroll
        for (int ci = 0; ci < 4; ci++)
            acc = fmaf(xcw[(k*38 + r)*4 + ci], sxc[ci*DI + ls], acc);
        g_xcdbl[idx] = acc;
    }
    __syncthreads();
    for (int idx = tid; idx < 2*4*DI; idx += 128) {
        int k = idx / (4*DI);
        int ci = (idx / DI) & 3;
        int l = idx % DI;
        float acc = dtcb[k*4 + ci];
        #pragma unroll
        for (int r = 0; r < 6; r++)
            acc = fmaf(dtcw[(k*4 + ci)*6 + r], g_xcdbl[(k*38 + r)*DI + l], acc);
        float dt = softplusf_(acc);
        int ls = k ? (DI-1-l) : l;
        float u = sxc[ci*DI + ls];
        sdt[idx] = dt; sdu[idx] = dt*u; su[idx] = u;
    }
    __syncthreads();
    {
        int w = tid >> 5, lane = tid & 31;
        int n = lane & 15, half = lane >> 4;
        int seq = w*2 + half;        // 0..7
        int k = seq >> 2, ci = seq & 3;
        float An = -__expf(Ac_logs[(k*4 + ci)*16 + n]);
        float Dc = Dsc[k*4 + ci];
        int base = seq * DI;
        float h = 0.f;
        for (int l = 0; l < DI; l++) {
            float dt = sdt[base + l];
            float du = sdu[base + l];
            float bn = g_xcdbl[(k*38 + 6 + n)*DI + l];
            float cn = g_xcdbl[(k*38 + 22 + n)*DI + l];
            float e = __expf(dt * An);
            h = fmaf(e, h, du * bn);
            float acc = h * cn;
            acc += __shfl_xor_sync(0xffffffffu, acc, 8);
            acc += __shfl_xor_sync(0xffffffffu, acc, 4);
            acc += __shfl_xor_sync(0xffffffffu, acc, 2);
            acc += __shfl_xor_sync(0xffffffffu, acc, 1);
            if (n == 0) syc[base + l] = fmaf(su[base + l], Dc, acc);
        }
    }
    __syncthreads();
    for (int l = tid; l < DI; l += 128) {
        float g = cout_b[0];
        #pragma unroll
        for (int ci = 0; ci < 4; ci++)
            g = fmaf(syc[ci*DI + l] + syc[(4 + ci)*DI + (DI-1-l)], cout_w[ci], g);
        sg[l] = g;
    }
    __syncthreads();
    float p1 = 0.f, p2 = 0.f;
    for (int l = tid; l < DI; l += 128) { float v = sg[l]; p1 += v; p2 += v*v; }
    red[tid] = p1; __syncthreads();
    for (int o = 64; o > 0; o >>= 1) { if (tid < o) red[tid] += red[tid+o]; __syncthreads(); }
    if (tid == 0) sstat[0] = red[0] * (1.f/DI);
    __syncthreads();
    red[tid] = p2; __syncthreads();
    for (int o = 64; o > 0; o >>= 1) { if (tid < o) red[tid] += red[tid+o]; __syncthreads(); }
    if (tid == 0) {
        float mu = sstat[0];
        sstat[1] = rsqrtf(red[0]*(1.f/DI) - mu*mu + 1e-5f);
    }
    __syncthreads();
    float mu = sstat[0], rs = sstat[1];
    for (int l = tid; l < DI; l += 128)
        g_gate[l] = (sg[l] - mu)*rs*cnw[l] + cnb[l];
}

// ---------------- K6: combine + LN + gate*z + out-proj (192 -> 96) ----------------
__global__ void __launch_bounds__(256) k_final(const float* __restrict__ onw,
                                               const float* __restrict__ onb,
                                               const float* __restrict__ ow,
                                               const float* __restrict__ ob,
                                               float* __restrict__ out) {
    __shared__ float sv[DI*33];       // [d][si] with pad-33 pitch
    __shared__ float smu[32], srs[32];
    int tid = threadIdx.x;
    int p0 = blockIdx.x * 32;
    for (int idx = tid; idx < DI*32; idx += 256) {
        int d = idx >> 5, si = idx & 31;
        int p = p0 + si;
        float s = g_y4[(0*DI + d)*L + p] + g_y4[(1*DI + d)*L + p]
                + g_y4[(2*DI + d)*L + p] + g_y4[(3*DI + d)*L + p];
        sv[d*33 + si] = s;
    }
    __syncthreads();
    {
        int w = tid >> 5, lane = tid & 31;
        for (int q = 0; q < 4; q++) {
            int si = w*4 + q;
            float s1 = 0.f, s2 = 0.f;
            #pragma unroll
            for (int j = 0; j < 6; j++) {
                float v = sv[(lane + j*32)*33 + si];
                s1 += v; s2 += v*v;
            }
            #pragma unroll
            for (int o = 16; o > 0; o >>= 1) {
                s1 += __shfl_xor_sync(0xffffffffu, s1, o);
                s2 += __shfl_xor_sync(0xffffffffu, s2, o);
            }
            if (lane == 0) {
                float mu = s1 * (1.f/DI);
                smu[si] = mu;
                srs[si] = rsqrtf(s2*(1.f/DI) - mu*mu + 1e-5f);
            }
        }
    }
    __syncthreads();
    for (int idx = tid; idx < DI*32; idx += 256) {
        int d = idx >> 5, si = idx & 31;
        int p = p0 + si;
        float v = sv[d*33 + si];
        v = (v - smu[si]) * srs[si] * onw[d] + onb[d];
        v = v * g_gate[d] * g_z[d*L + p];
        sv[d*33 + si] = v;
    }
    __syncthreads();
    for (int idx = tid; idx < 96*32; idx += 256) {
        int o = idx >> 5, si = idx & 31;
        const float4* w4 = reinterpret_cast<const float4*>(ow + o*DI);
        float a0 = 0.f, a1 = 0.f, a2 = 0.f, a3 = 0.f;
        #pragma unroll 12
        for (int d4 = 0; d4 < 48; d4++) {
            float4 wv = __ldg(w4 + d4);
            int d = d4*4;
            a0 = fmaf(wv.x, sv[d*33+si], a0);
            a1 = fmaf(wv.y, sv[(d+1)*33+si], a1);
            a2 = fmaf(wv.z, sv[(d+2)*33+si], a2);
            a3 = fmaf(wv.w, sv[(d+3)*33+si], a3);
        }
        out[o*L + p0 + si] = ob[o] + (a0 + a1) + (a2 + a3);
    }
}

// ---------------- launch ----------------
extern "C" void kernel_launch(void* const* d_in, const int* in_sizes, int n_in,
                              void* d_out, int out_size) {
    const float* x      = (const float*)d_in[0];
    const float* in_w   = (const float*)d_in[1];
    const float* in_b   = (const float*)d_in[2];
    const float* c2w    = (const float*)d_in[3];
    const float* c2b    = (const float*)d_in[4];
    const float* xpw    = (const float*)d_in[5];
    const float* dtw    = (const float*)d_in[6];
    const float* dtb    = (const float*)d_in[7];
    const float* Alogs  = (const float*)d_in[8];
    const float* Ds     = (const float*)d_in[9];
    const float* onw    = (const float*)d_in[10];
    const float* onb    = (const float*)d_in[11];
    const float* cinw   = (const float*)d_in[12];
    const float* cinb   = (const float*)d_in[13];
    const float* coutw  = (const float*)d_in[14];
    const float* coutb  = (const float*)d_in[15];
    const float* xcw    = (const float*)d_in[16];
    const float* dtcw   = (const float*)d_in[17];
    const float* dtcb   = (const float*)d_in[18];
    const float* Aclogs = (const float*)d_in[19];
    const float* Dsc    = (const float*)d_in[20];
    const float* cnw    = (const float*)d_in[21];
    const float* cnb    = (const float*)d_in[22];
    const float* ow     = (const float*)d_in[23];
    const float* obias  = (const float*)d_in[24];
    float* out = (float*)d_out;

    k_inproj<<<dim3(32, 24), 128>>>(x, in_w, in_b);
    k_dwconv<<<dim3(2, 2, 192), dim3(32, 32)>>>(c2w, c2b);
    k_proj<<<dim3(128, 4), 320>>>(xpw, dtw, dtb);
    k_scan<<<768, 256>>>(Alogs, Ds);
    k_chan<<<1, 128>>>(cinw, cinb, xcw, dtcw, dtcb, Aclogs, Dsc, coutw, coutb, cnw, cnb);
    k_final<<<128, 256>>>(onw, onb, ow, obias, out);
}

// round 8
// speedup vs baseline: 2.8609x; 1.0574x over previous
#include <cuda_runtime.h>
#include <math.h>

#define L 4096
#define DI 192
#define NS 16
#define NCHUNK 64
#define CLEN 64

// ---------------- device scratch (static, no allocations) ----------------
__device__ float g_xg_pre[DI*L];
__device__ float g_z[DI*L];
__device__ float g_xg_f[DI*L];
__device__ float g_xg_t[DI*L];
__device__ float g_cmean[DI];
// chunk-interleaved scan inputs (chunk = s>>6, i = s&63):
//   g_B[k][i(64)][c(64)][16]   (float4-aligned), same for g_C
//   g_dtu4[seq][pair(32)][c(64)] : (dtA,uA,dtB,uB) for steps 2p, 2p+1 of chunk c
__device__ float4 g_B[4*4096*4];
__device__ float4 g_C[4*4096*4];
__device__ float4 g_dtu4[768*2048];
__device__ float g_y4[4*DI*L];        // scan outputs, pixel-indexed
__device__ float g_xcdbl[2*38*DI];
__device__ float g_gate[DI];

__device__ __forceinline__ float softplusf_(float x){
    return (x > 20.f) ? x : log1pf(__expf(x));
}
__device__ __forceinline__ float ex2_(float x){
    float r;
    asm("ex2.approx.ftz.f32 %0, %1;" : "=f"(r) : "f"(x));
    return r;
}

// ---------------- K1: 1x1 in-proj (96 -> 384), 16 outputs per thread ----------
__global__ void __launch_bounds__(128) k_inproj(const float* __restrict__ x,
                                                const float* __restrict__ W,
                                                const float* __restrict__ b) {
    __shared__ float ws[96*16];   // transposed: [c][j]
    int ob = blockIdx.y * 16;
    for (int i = threadIdx.x; i < 96*16; i += 128) {
        int c = i >> 4, j = i & 15;
        ws[i] = W[(ob + j)*96 + c];
    }
    __syncthreads();
    int p = blockIdx.x * 128 + threadIdx.x;
    if (blockIdx.y == 0 && p < DI) g_cmean[p] = 0.f;   // zero for dwconv atomics
    float acc[16];
    #pragma unroll
    for (int j = 0; j < 16; j++) acc[j] = 0.f;
    #pragma unroll 2
    for (int c = 0; c < 96; c++) {
        float xv = __ldg(x + c*L + p);
        #pragma unroll
        for (int q = 0; q < 4; q++) {
            float4 w = *reinterpret_cast<const float4*>(ws + c*16 + q*4);
            acc[q*4+0] = fmaf(w.x, xv, acc[q*4+0]);
            acc[q*4+1] = fmaf(w.y, xv, acc[q*4+1]);
            acc[q*4+2] = fmaf(w.z, xv, acc[q*4+2]);
            acc[q*4+3] = fmaf(w.w, xv, acc[q*4+3]);
        }
    }
    #pragma unroll
    for (int j = 0; j < 16; j++) {
        int o = ob + j;
        float v = acc[j] + b[o];
        if (o < DI) {
            g_xg_pre[o*L + p] = v;
        } else {
            g_z[(o-DI)*L + p] = v / (1.f + __expf(-v));   // silu
        }
    }
}

// ------- K2: depthwise 3x3 + bias + silu + fused channel-mean (atomics) -------
__global__ void __launch_bounds__(1024) k_dwconv(const float* __restrict__ w,
                                                 const float* __restrict__ b) {
    __shared__ float t[32][33];
    __shared__ float wsum[32];
    int d = blockIdx.z;
    int tx = threadIdx.x, ty = threadIdx.y;
    int h = blockIdx.y*32 + ty;
    int wq = blockIdx.x*32 + tx;
    const float* src = g_xg_pre + d*L;
    float wk[9];
    #pragma unroll
    for (int i = 0; i < 9; i++) wk[i] = w[d*9 + i];
    float acc = b[d];
    #pragma unroll
    for (int kh = 0; kh < 3; kh++) {
        int hh = h + kh - 1;
        #pragma unroll
        for (int kw = 0; kw < 3; kw++) {
            int ww = wq + kw - 1;
            if (hh >= 0 && hh < 64 && ww >= 0 && ww < 64)
                acc = fmaf(wk[kh*3+kw], src[hh*64 + ww], acc);
        }
    }
    float v = acc / (1.f + __expf(-acc));   // silu
    g_xg_f[d*L + h*64 + wq] = v;
    t[ty][tx] = v;
    // block reduction for channel mean
    int tid = ty*32 + tx;
    int lane = tid & 31, wi = tid >> 5;
    float s = v;
    #pragma unroll
    for (int o = 16; o > 0; o >>= 1) s += __shfl_xor_sync(0xffffffffu, s, o);
    if (lane == 0) wsum[wi] = s;
    __syncthreads();
    float v2 = t[tx][ty];
    g_xg_t[d*L + (blockIdx.x*32 + ty)*64 + blockIdx.y*32 + tx] = v2;
    if (wi == 0) {
        float s2 = wsum[lane];
        #pragma unroll
        for (int o = 16; o > 0; o >>= 1) s2 += __shfl_xor_sync(0xffffffffu, s2, o);
        if (lane == 0) atomicAdd(&g_cmean[d], s2 * (1.f / L));
    }
}

// ---------------- K3: x-proj + dt-proj, register-tiled GEMM ----------------
// grid (128, 4): 32 pixels per block; writes chunk-interleaved B/C/dtu layouts.
__global__ void __launch_bounds__(320) k_proj(const float* __restrict__ xpw,
                                              const float* __restrict__ dtw,
                                              const float* __restrict__ dtb) {
    __shared__ float xv[DI*32];       // [d][si]  (24 KB)
    __shared__ float wsm[38*97];      // half-K weight slab, padded (14.7 KB)
    __shared__ float xd6[6*32];
    __shared__ float sBC[32][33];     // [si][slot]  even=B_n, odd=C_n
    int tid = threadIdx.x;
    int s0 = blockIdx.x * 32;
    int oid = blockIdx.y & 1;
    int kk  = blockIdx.y >> 1;
    int k = oid + kk*2;
    const float* uptr = oid ? g_xg_t : g_xg_f;
    for (int i4 = tid; i4 < DI*8; i4 += 320) {
        int d = i4 >> 3, j = i4 & 7;
        float4 v = *reinterpret_cast<const float4*>(uptr + d*L + s0 + j*4);
        *reinterpret_cast<float4*>(xv + d*32 + j*4) = v;
    }
    int r_ = tid >> 3, sq_ = tid & 7;
    float a0 = 0.f, a1 = 0.f, a2 = 0.f, a3 = 0.f;
    #pragma unroll
    for (int half = 0; half < 2; half++) {
        __syncthreads();
        for (int i = tid; i < 38*96; i += 320) {
            int r = i / 96, dd = i - r*96;
            wsm[r*97 + dd] = __ldg(xpw + (k*38 + r)*192 + half*96 + dd);
        }
        __syncthreads();
        if (tid < 304) {
            const float* wr = wsm + r_*97;
            const float* xb = xv + sq_*4 + half*96*32;
            #pragma unroll 4
            for (int dd = 0; dd < 96; dd++) {
                float w = wr[dd];
                float4 xq = *reinterpret_cast<const float4*>(xb + dd*32);
                a0 = fmaf(w, xq.x, a0);
                a1 = fmaf(w, xq.y, a1);
                a2 = fmaf(w, xq.z, a2);
                a3 = fmaf(w, xq.w, a3);
            }
        }
    }
    __syncthreads();
    if (tid < 304) {
        int sb = sq_*4;
        if (r_ < 6) {
            xd6[r_*32 + sb]     = a0;
            xd6[r_*32 + sb + 1] = a1;
            xd6[r_*32 + sb + 2] = a2;
            xd6[r_*32 + sb + 3] = a3;
        } else {
            int slot = (r_ < 22) ? 2*(r_ - 6) : 2*(r_ - 22) + 1;
            sBC[sb][slot]     = a0;
            sBC[sb + 1][slot] = a1;
            sBC[sb + 2][slot] = a2;
            sBC[sb + 3][slot] = a3;
        }
    }
    __syncthreads();
    // write B and C to chunk-interleaved layout [k][i][c][16]
    float* gB = reinterpret_cast<float*>(g_B);
    float* gC = reinterpret_cast<float*>(g_C);
    for (int idx = tid; idx < 32*16; idx += 320) {
        int si = idx >> 4, n = idx & 15;
        int s = s0 + si;
        int fo = (k*4096 + (s & 63)*64 + (s >> 6))*16 + n;
        gB[fo] = sBC[si][2*n];
        gC[fo] = sBC[si][2*n + 1];
    }
    // dt-proj + write (dt, u) pairs to chunk-interleaved float4 layout
    float2* dtu2 = reinterpret_cast<float2*>(g_dtu4);
    for (int idx = tid; idx < DI*32; idx += 320) {
        int d = idx >> 5, si = idx & 31;
        int row = k*DI + d;
        float acc = __ldg(dtb + row);
        #pragma unroll
        for (int r = 0; r < 6; r++)
            acc = fmaf(__ldg(dtw + row*6 + r), xd6[r*32 + si], acc);
        float dt = softplusf_(acc);
        float u = xv[d*32 + si];
        int s = s0 + si;
        int idx2 = row*4096 + ((s & 63) >> 1)*128 + (s >> 6)*2 + (s & 1);
        dtu2[idx2] = make_float2(dt, u);
    }
}

// -------- K4: FUSED chunked scan, 4 states/lane, 4-lane units -------------
// 256 threads = 64 chunks x 4 lanes, CLEN=64. 4 independent h-chains/thread.
template<bool FWD, bool TORD>
__device__ __forceinline__ void scan_body(
    const float4* __restrict__ pdtu4, const float4* __restrict__ pB4,
    const float4* __restrict__ pC4, float* __restrict__ pout,
    float4 An, float Dd, int c, int ln2, int tid,
    float (*s_h)[16], float (*s_p)[16])
{
    // ---- phase 1: local chunk scan (B only) ----
    float h0 = 0.f, h1 = 0.f, h2 = 0.f, h3 = 0.f, sdt = 0.f;
    #pragma unroll 4
    for (int j = 0; j < 32; j++) {
        int iA = FWD ? (2*j) : (63 - 2*j);
        int iB = FWD ? (iA + 1) : (iA - 1);
        float4 q = pdtu4[(FWD ? j : (31 - j))*64 + c];
        float dtA = FWD ? q.x : q.z, uA = FWD ? q.y : q.w;
        float dtB = FWD ? q.z : q.x, uB = FWD ? q.w : q.y;
        float4 bA = pB4[(iA*64 + c)*4 + ln2];
        float4 bB = pB4[(iB*64 + c)*4 + ln2];
        float duA = dtA*uA, duB = dtB*uB;
        h0 = fmaf(ex2_(dtA*An.x), h0, duA*bA.x);
        h1 = fmaf(ex2_(dtA*An.y), h1, duA*bA.y);
        h2 = fmaf(ex2_(dtA*An.z), h2, duA*bA.z);
        h3 = fmaf(ex2_(dtA*An.w), h3, duA*bA.w);
        h0 = fmaf(ex2_(dtB*An.x), h0, duB*bB.x);
        h1 = fmaf(ex2_(dtB*An.y), h1, duB*bB.y);
        h2 = fmaf(ex2_(dtB*An.z), h2, duB*bB.z);
        h3 = fmaf(ex2_(dtB*An.w), h3, duB*bB.w);
        sdt += dtA + dtB;
    }
    int n0 = ln2*4;
    s_h[c][n0+0] = h0; s_h[c][n0+1] = h1; s_h[c][n0+2] = h2; s_h[c][n0+3] = h3;
    s_p[c][n0+0] = ex2_(An.x*sdt); s_p[c][n0+1] = ex2_(An.y*sdt);
    s_p[c][n0+2] = ex2_(An.z*sdt); s_p[c][n0+3] = ex2_(An.w*sdt);
    __syncthreads();

    // ---- phase 2: serial combine across chunks (scan order), in-place h -> h0 ----
    if (tid < 16) {
        float H = 0.f;
        #pragma unroll 4
        for (int cc = 0; cc < NCHUNK; cc++) {
            int c2 = FWD ? cc : (NCHUNK - 1 - cc);
            float hh = s_h[c2][tid];
            float pp = s_p[c2][tid];
            s_h[c2][tid] = H;
            H = fmaf(pp, H, hh);
        }
    }
    __syncthreads();

    // ---- phase 3: re-scan with correct initial state, emit y ----
    h0 = s_h[c][n0+0]; h1 = s_h[c][n0+1]; h2 = s_h[c][n0+2]; h3 = s_h[c][n0+3];
    float ybuf = 0.f;
    const int pa = FWD ? 0 : 1;       // parity of sA
    #pragma unroll 4
    for (int j = 0; j < 32; j++) {
        int iA = FWD ? (2*j) : (63 - 2*j);
        int iB = FWD ? (iA + 1) : (iA - 1);
        int sA = c*CLEN + iA;
        int sB = c*CLEN + iB;
        float4 q = pdtu4[(FWD ? j : (31 - j))*64 + c];
        float dtA = FWD ? q.x : q.z, uA = FWD ? q.y : q.w;
        float dtB = FWD ? q.z : q.x, uB = FWD ? q.w : q.y;
        float4 bA = pB4[(iA*64 + c)*4 + ln2];
        float4 bB = pB4[(iB*64 + c)*4 + ln2];
        float4 cA = pC4[(iA*64 + c)*4 + ln2];
        float4 cB = pC4[(iB*64 + c)*4 + ln2];
        float duA = dtA*uA, duB = dtB*uB;
        h0 = fmaf(ex2_(dtA*An.x), h0, duA*bA.x);
        h1 = fmaf(ex2_(dtA*An.y), h1, duA*bA.y);
        h2 = fmaf(ex2_(dtA*An.z), h2, duA*bA.z);
        h3 = fmaf(ex2_(dtA*An.w), h3, duA*bA.w);
        float accA = fmaf(h3, cA.w, fmaf(h2, cA.z, fmaf(h1, cA.y, h0*cA.x)));
        h0 = fmaf(ex2_(dtB*An.x), h0, duB*bB.x);
        h1 = fmaf(ex2_(dtB*An.y), h1, duB*bB.y);
        h2 = fmaf(ex2_(dtB*An.z), h2, duB*bB.z);
        h3 = fmaf(ex2_(dtB*An.w), h3, duB*bB.w);
        float accB = fmaf(h3, cB.w, fmaf(h2, cB.z, fmaf(h1, cB.y, h0*cB.x)));
        // joint 4-lane reduce: 3 shfls for 2 outputs.
        accA += __shfl_xor_sync(0xffffffffu, accA, 1);
        accB += __shfl_xor_sync(0xffffffffu, accB, 1);
        float u2 = ((ln2 & 1) == pa) ? accA : accB;
        u2 += __shfl_xor_sync(0xffffffffu, u2, 2);
        float yA = fmaf(uA, Dd, u2);   // valid on lanes with parity pa
        float yB = fmaf(uB, Dd, u2);   // valid on lanes with parity 1-pa
        if (TORD) {
            if (ln2 == pa)     pout[((sA & 63) << 6) | (sA >> 6)] = yA;
            if (ln2 == 1 - pa) pout[((sB & 63) << 6) | (sB >> 6)] = yB;
        } else {
            if (ln2 == (sA & 3))      ybuf = yA;
            else if (ln2 == (sB & 3)) ybuf = yB;
            if ((j & 1) == 1)
                pout[(sA & ~3) + ln2] = ybuf;   // coalesced 4-wide per unit
        }
    }
}

__global__ void __launch_bounds__(256, 5) k_scan(const float* __restrict__ A_logs,
                                                 const float* __restrict__ Ds) {
    __shared__ float s_h[NCHUNK][16];
    __shared__ float s_p[NCHUNK][16];
    int tid = threadIdx.x;
    int c = tid >> 2;
    int ln2 = tid & 3;
    int seq = blockIdx.x;
    int k = seq / DI;
    const float4* pdtu4 = g_dtu4 + (size_t)seq*2048;
    const float4* pB4 = g_B + (size_t)k*16384;
    const float4* pC4 = g_C + (size_t)k*16384;
    float* pout = g_y4 + (size_t)seq*L;
    const float LOG2E = 1.4426950408889634f;
    float4 al = *reinterpret_cast<const float4*>(A_logs + seq*NS + ln2*4);
    float4 An = make_float4(-__expf(al.x)*LOG2E, -__expf(al.y)*LOG2E,
                            -__expf(al.z)*LOG2E, -__expf(al.w)*LOG2E);
    float Dd = __ldg(Ds + seq);
    if (k == 0)      scan_body<true,  false>(pdtu4, pB4, pC4, pout, An, Dd, c, ln2, tid, s_h, s_p);
    else if (k == 1) scan_body<true,  true >(pdtu4, pB4, pC4, pout, An, Dd, c, ln2, tid, s_h, s_p);
    else if (k == 2) scan_body<false, false>(pdtu4, pB4, pC4, pout, An, Dd, c, ln2, tid, s_h, s_p);
    else             scan_body<false, true >(pdtu4, pB4, pC4, pout, An, Dd, c, ln2, tid, s_h, s_p);
}

// ---------------- K5: channel-branch (tiny), single block ----------------
__global__ void __launch_bounds__(128) k_chan(
    const float* __restrict__ cin_w, const float* __restrict__ cin_b,
    const float* __restrict__ xcw,   const float* __restrict__ dtcw,
    const float* __restrict__ dtcb,  const float* __restrict__ Ac_logs,
    const float* __restrict__ Dsc,   const float* __restrict__ cout_w,
    const float* __restrict__ cout_b,const float* __restrict__ cnw,
    const float* __restrict__ cnb) {
    __shared__ float sxc[4*DI];
    __shared__ float sdt[2*4*DI];
    __shared__ float sdu[2*4*DI];
    __shared__ float su [2*4*DI];
    __shared__ float syc[2*4*DI];
    __shared__ float sg[DI];
    __shared__ float red[128];
    __shared__ float sstat[2];
    int tid = threadIdx.x;
    for (int idx = tid; idx < 4*DI; idx += 128) {
        int ci = idx / DI, l = idx % DI;
        sxc[idx] = g_cmean[l]*cin_w[ci] + cin_b[ci];
    }
    __syncthreads();
    for (int idx = tid; idx < 2*38*DI; idx += 128) {
        int k = idx / (38*DI);
        int r = (idx / DI) % 38;
        int l = idx % DI;
        int ls = k ? (DI-1-l) : l;
        float acc = 0.f;
        #pragma unroll
        for (int ci = 0; ci < 4; ci++)
            acc = fmaf(xcw[(k*38 + r)*4 + ci], sxc[ci*DI + ls], acc);
        g_xcdbl[idx] = acc;
    }
    __syncthreads();
    for (int idx = tid; idx < 2*4*DI; idx += 128) {
        int k = idx / (4*DI);
        int ci = (idx / DI) & 3;
        int l = idx % DI;
        float acc = dtcb[k*4 + ci];
        #pragma unroll
        for (int r = 0; r < 6; r++)
            acc = fmaf(dtcw[(k*4 + ci)*6 + r], g_xcdbl[(k*38 + r)*DI + l], acc);
        float dt = softplusf_(acc);
        int ls = k ? (DI-1-l) : l;
        float u = sxc[ci*DI + ls];
        sdt[idx] = dt; sdu[idx] = dt*u; su[idx] = u;
    }
    __syncthreads();
    {
        int w = tid >> 5, lane = tid & 31;
        int n = lane & 15, half = lane >> 4;
        int seq = w*2 + half;        // 0..7
        int k = seq >> 2, ci = seq & 3;
        float An = -__expf(Ac_logs[(k*4 + ci)*16 + n]);
        float Dc = Dsc[k*4 + ci];
        int base = seq * DI;
        float h = 0.f;
        for (int l = 0; l < DI; l++) {
            float dt = sdt[base + l];
            float du = sdu[base + l];
            float bn = g_xcdbl[(k*38 + 6 + n)*DI + l];
            float cn = g_xcdbl[(k*38 + 22 + n)*DI + l];
            float e = __expf(dt * An);
            h = fmaf(e, h, du * bn);
            float acc = h * cn;
            acc += __shfl_xor_sync(0xffffffffu, acc, 8);
            acc += __shfl_xor_sync(0xffffffffu, acc, 4);
            acc += __shfl_xor_sync(0xffffffffu, acc, 2);
            acc += __shfl_xor_sync(0xffffffffu, acc, 1);
            if (n == 0) syc[base + l] = fmaf(su[base + l], Dc, acc);
        }
    }
    __syncthreads();
    for (int l = tid; l < DI; l += 128) {
        float g = cout_b[0];
        #pragma unroll
        for (int ci = 0; ci < 4; ci++)
            g = fmaf(syc[ci*DI + l] + syc[(4 + ci)*DI + (DI-1-l)], cout_w[ci], g);
        sg[l] = g;
    }
    __syncthreads();
    float p1 = 0.f, p2 = 0.f;
    for (int l = tid; l < DI; l += 128) { float v = sg[l]; p1 += v; p2 += v*v; }
    red[tid] = p1; __syncthreads();
    for (int o = 64; o > 0; o >>= 1) { if (tid < o) red[tid] += red[tid+o]; __syncthreads(); }
    if (tid == 0) sstat[0] = red[0] * (1.f/DI);
    __syncthreads();
    red[tid] = p2; __syncthreads();
    for (int o = 64; o > 0; o >>= 1) { if (tid < o) red[tid] += red[tid+o]; __syncthreads(); }
    if (tid == 0) {
        float mu = sstat[0];
        sstat[1] = rsqrtf(red[0]*(1.f/DI) - mu*mu + 1e-5f);
    }
    __syncthreads();
    float mu = sstat[0], rs = sstat[1];
    for (int l = tid; l < DI; l += 128)
        g_gate[l] = (sg[l] - mu)*rs*cnw[l] + cnb[l];
}

// ---------------- K6: combine + LN + gate*z + out-proj (192 -> 96) ----------------
__global__ void __launch_bounds__(256) k_final(const float* __restrict__ onw,
                                               const float* __restrict__ onb,
                                               const float* __restrict__ ow,
                                               const float* __restrict__ ob,
                                               float* __restrict__ out) {
    __shared__ float sv[DI*33];       // [d][si] with pad-33 pitch
    __shared__ float smu[32], srs[32];
    int tid = threadIdx.x;
    int p0 = blockIdx.x * 32;
    for (int idx = tid; idx < DI*32; idx += 256) {
        int d = idx >> 5, si = idx & 31;
        int p = p0 + si;
        float s = g_y4[(0*DI + d)*L + p] + g_y4[(1*DI + d)*L + p]
                + g_y4[(2*DI + d)*L + p] + g_y4[(3*DI + d)*L + p];
        sv[d*33 + si] = s;
    }
    __syncthreads();
    {
        int w = tid >> 5, lane = tid & 31;
        for (int q = 0; q < 4; q++) {
            int si = w*4 + q;
            float s1 = 0.f, s2 = 0.f;
            #pragma unroll
            for (int j = 0; j < 6; j++) {
                float v = sv[(lane + j*32)*33 + si];
                s1 += v; s2 += v*v;
            }
            #pragma unroll
            for (int o = 16; o > 0; o >>= 1) {
                s1 += __shfl_xor_sync(0xffffffffu, s1, o);
                s2 += __shfl_xor_sync(0xffffffffu, s2, o);
            }
            if (lane == 0) {
                float mu = s1 * (1.f/DI);
                smu[si] = mu;
                srs[si] = rsqrtf(s2*(1.f/DI) - mu*mu + 1e-5f);
            }
        }
    }
    __syncthreads();
    for (int idx = tid; idx < DI*32; idx += 256) {
        int d = idx >> 5, si = idx & 31;
        int p = p0 + si;
        float v = sv[d*33 + si];
        v = (v - smu[si]) * srs[si] * onw[d] + onb[d];
        v = v * g_gate[d] * g_z[d*L + p];
        sv[d*33 + si] = v;
    }
    __syncthreads();
    for (int idx = tid; idx < 96*32; idx += 256) {
        int o = idx >> 5, si = idx & 31;
        const float4* w4 = reinterpret_cast<const float4*>(ow + o*DI);
        float a0 = 0.f, a1 = 0.f, a2 = 0.f, a3 = 0.f;
        #pragma unroll 12
        for (int d4 = 0; d4 < 48; d4++) {
            float4 wv = __ldg(w4 + d4);
            int d = d4*4;
            a0 = fmaf(wv.x, sv[d*33+si], a0);
            a1 = fmaf(wv.y, sv[(d+1)*33+si], a1);
            a2 = fmaf(wv.z, sv[(d+2)*33+si], a2);
            a3 = fmaf(wv.w, sv[(d+3)*33+si], a3);
        }
        out[o*L + p0 + si] = ob[o] + (a0 + a1) + (a2 + a3);
    }
}

// ---------------- launch ----------------
extern "C" void kernel_launch(void* const* d_in, const int* in_sizes, int n_in,
                              void* d_out, int out_size) {
    const float* x      = (const float*)d_in[0];
    const float* in_w   = (const float*)d_in[1];
    const float* in_b   = (const float*)d_in[2];
    const float* c2w    = (const float*)d_in[3];
    const float* c2b    = (const float*)d_in[4];
    const float* xpw    = (const float*)d_in[5];
    const float* dtw    = (const float*)d_in[6];
    const float* dtb    = (const float*)d_in[7];
    const float* Alogs  = (const float*)d_in[8];
    const float* Ds     = (const float*)d_in[9];
    const float* onw    = (const float*)d_in[10];
    const float* onb    = (const float*)d_in[11];
    const float* cinw   = (const float*)d_in[12];
    const float* cinb   = (const float*)d_in[13];
    const float* coutw  = (const float*)d_in[14];
    const float* coutb  = (const float*)d_in[15];
    const float* xcw    = (const float*)d_in[16];
    const float* dtcw   = (const float*)d_in[17];
    const float* dtcb   = (const float*)d_in[18];
    const float* Aclogs = (const float*)d_in[19];
    const float* Dsc    = (const float*)d_in[20];
    const float* cnw    = (const float*)d_in[21];
    const float* cnb    = (const float*)d_in[22];
    const float* ow     = (const float*)d_in[23];
    const float* obias  = (const float*)d_in[24];
    float* out = (float*)d_out;

    k_inproj<<<dim3(32, 24), 128>>>(x, in_w, in_b);
    k_dwconv<<<dim3(2, 2, 192), dim3(32, 32)>>>(c2w, c2b);
    k_proj<<<dim3(128, 4), 320>>>(xpw, dtw, dtb);
    k_scan<<<768, 256>>>(Alogs, Ds);
    k_chan<<<1, 128>>>(cinw, cinb, xcw, dtcw, dtcb, Aclogs, Dsc, coutw, coutb, cnw, cnb);
    k_final<<<128, 256>>>(onw, onb, ow, obias, out);
}

// round 10
// speedup vs baseline: 3.4008x; 1.1887x over previous
#include <cuda_runtime.h>
#include <math.h>

#define L 4096
#define DI 192
#define NS 16
#define NCHUNK 64
#define CLEN 64

// ---------------- device scratch (static, no allocations) ----------------
__device__ float g_xg_pre[DI*L];
__device__ float g_z[DI*L];
__device__ float g_xg_f[DI*L];
__device__ float g_xg_t[DI*L];
__device__ float g_cmean[DI];
// chunk-interleaved scan inputs (chunk = s>>6, i = s&63):
//   g_B[k][i(64)][c(64)][16]   (float4-aligned), same for g_C
//   g_dtu4[seq][pair(32)][c(64)] : (dtA,uA,dtB,uB) for steps 2p, 2p+1 of chunk c
__device__ float4 g_B[4*4096*4];
__device__ float4 g_C[4*4096*4];
__device__ float4 g_dtu4[768*2048];
__device__ float g_y4[4*DI*L];        // scan outputs, pixel-indexed
__device__ float g_xcdbl[2*38*DI];
__device__ float g_gate[DI];

__device__ __forceinline__ float softplusf_(float x){
    return (x > 20.f) ? x : log1pf(__expf(x));
}
__device__ __forceinline__ float ex2_(float x){
    float r;
    asm("ex2.approx.ftz.f32 %0, %1;" : "=f"(r) : "f"(x));
    return r;
}

// ---------------- K1: 1x1 in-proj (96 -> 384), 16 outputs per thread ----------
__global__ void __launch_bounds__(128) k_inproj(const float* __restrict__ x,
                                                const float* __restrict__ W,
                                                const float* __restrict__ b) {
    __shared__ float ws[96*16];   // transposed: [c][j]
    int ob = blockIdx.y * 16;
    for (int i = threadIdx.x; i < 96*16; i += 128) {
        int c = i >> 4, j = i & 15;
        ws[i] = W[(ob + j)*96 + c];
    }
    __syncthreads();
    int p = blockIdx.x * 128 + threadIdx.x;
    if (blockIdx.y == 0 && p < DI) g_cmean[p] = 0.f;   // zero for dwconv atomics
    float acc[16];
    #pragma unroll
    for (int j = 0; j < 16; j++) acc[j] = 0.f;
    #pragma unroll 2
    for (int c = 0; c < 96; c++) {
        float xv = __ldg(x + c*L + p);
        #pragma unroll
        for (int q = 0; q < 4; q++) {
            float4 w = *reinterpret_cast<const float4*>(ws + c*16 + q*4);
            acc[q*4+0] = fmaf(w.x, xv, acc[q*4+0]);
            acc[q*4+1] = fmaf(w.y, xv, acc[q*4+1]);
            acc[q*4+2] = fmaf(w.z, xv, acc[q*4+2]);
            acc[q*4+3] = fmaf(w.w, xv, acc[q*4+3]);
        }
    }
    #pragma unroll
    for (int j = 0; j < 16; j++) {
        int o = ob + j;
        float v = acc[j] + b[o];
        if (o < DI) {
            g_xg_pre[o*L + p] = v;
        } else {
            g_z[(o-DI)*L + p] = v / (1.f + __expf(-v));   // silu
        }
    }
}

// ------- K2: depthwise 3x3 + bias + silu + fused channel-mean (atomics) -------
__global__ void __launch_bounds__(1024) k_dwconv(const float* __restrict__ w,
                                                 const float* __restrict__ b) {
    __shared__ float t[32][33];
    __shared__ float wsum[32];
    int d = blockIdx.z;
    int tx = threadIdx.x, ty = threadIdx.y;
    int h = blockIdx.y*32 + ty;
    int wq = blockIdx.x*32 + tx;
    const float* src = g_xg_pre + d*L;
    float wk[9];
    #pragma unroll
    for (int i = 0; i < 9; i++) wk[i] = w[d*9 + i];
    float acc = b[d];
    #pragma unroll
    for (int kh = 0; kh < 3; kh++) {
        int hh = h + kh - 1;
        #pragma unroll
        for (int kw = 0; kw < 3; kw++) {
            int ww = wq + kw - 1;
            if (hh >= 0 && hh < 64 && ww >= 0 && ww < 64)
                acc = fmaf(wk[kh*3+kw], src[hh*64 + ww], acc);
        }
    }
    float v = acc / (1.f + __expf(-acc));   // silu
    g_xg_f[d*L + h*64 + wq] = v;
    t[ty][tx] = v;
    // block reduction for channel mean
    int tid = ty*32 + tx;
    int lane = tid & 31, wi = tid >> 5;
    float s = v;
    #pragma unroll
    for (int o = 16; o > 0; o >>= 1) s += __shfl_xor_sync(0xffffffffu, s, o);
    if (lane == 0) wsum[wi] = s;
    __syncthreads();
    float v2 = t[tx][ty];
    g_xg_t[d*L + (blockIdx.x*32 + ty)*64 + blockIdx.y*32 + tx] = v2;
    if (wi == 0) {
        float s2 = wsum[lane];
        #pragma unroll
        for (int o = 16; o > 0; o >>= 1) s2 += __shfl_xor_sync(0xffffffffu, s2, o);
        if (lane == 0) atomicAdd(&g_cmean[d], s2 * (1.f / L));
    }
}

// ---------------- channel-branch, run by one 320-thread block ----------------
// work guarded to tid<128; __syncthreads() unconditional (all 320 threads call).
__device__ __forceinline__ void chan_dev(int tid,
    const float* __restrict__ cin_w, const float* __restrict__ cin_b,
    const float* __restrict__ xcw,   const float* __restrict__ dtcw,
    const float* __restrict__ dtcb,  const float* __restrict__ Ac_logs,
    const float* __restrict__ Dsc,   const float* __restrict__ cout_w,
    const float* __restrict__ cout_b,const float* __restrict__ cnw,
    const float* __restrict__ cnb,
    float* sxc, float* sdt, float* sdu, float* su,
    float* syc, float* sg, float* red, float* sstat)
{
    if (tid < 128) {
        for (int idx = tid; idx < 4*DI; idx += 128) {
            int ci = idx / DI, l = idx % DI;
            sxc[idx] = g_cmean[l]*cin_w[ci] + cin_b[ci];
        }
    }
    __syncthreads();
    if (tid < 128) {
        for (int idx = tid; idx < 2*38*DI; idx += 128) {
            int k = idx / (38*DI);
            int r = (idx / DI) % 38;
            int l = idx % DI;
            int ls = k ? (DI-1-l) : l;
            float acc = 0.f;
            #pragma unroll
            for (int ci = 0; ci < 4; ci++)
                acc = fmaf(xcw[(k*38 + r)*4 + ci], sxc[ci*DI + ls], acc);
            g_xcdbl[idx] = acc;
        }
    }
    __syncthreads();
    if (tid < 128) {
        for (int idx = tid; idx < 2*4*DI; idx += 128) {
            int k = idx / (4*DI);
            int ci = (idx / DI) & 3;
            int l = idx % DI;
            float acc = dtcb[k*4 + ci];
            #pragma unroll
            for (int r = 0; r < 6; r++)
                acc = fmaf(dtcw[(k*4 + ci)*6 + r], g_xcdbl[(k*38 + r)*DI + l], acc);
            float dt = softplusf_(acc);
            int ls = k ? (DI-1-l) : l;
            float u = sxc[ci*DI + ls];
            sdt[idx] = dt; sdu[idx] = dt*u; su[idx] = u;
        }
    }
    __syncthreads();
    if (tid < 128) {
        int w = tid >> 5, lane = tid & 31;
        int n = lane & 15, half = lane >> 4;
        int seq = w*2 + half;        // 0..7
        int k = seq >> 2, ci = seq & 3;
        float An = -__expf(Ac_logs[(k*4 + ci)*16 + n]);
        float Dc = Dsc[k*4 + ci];
        int base = seq * DI;
        float h = 0.f;
        for (int l = 0; l < DI; l++) {
            float dt = sdt[base + l];
            float du = sdu[base + l];
            float bn = g_xcdbl[(k*38 + 6 + n)*DI + l];
            float cn = g_xcdbl[(k*38 + 22 + n)*DI + l];
            float e = __expf(dt * An);
            h = fmaf(e, h, du * bn);
            float acc = h * cn;
            acc += __shfl_xor_sync(0xffffffffu, acc, 8);
            acc += __shfl_xor_sync(0xffffffffu, acc, 4);
            acc += __shfl_xor_sync(0xffffffffu, acc, 2);
            acc += __shfl_xor_sync(0xffffffffu, acc, 1);
            if (n == 0) syc[base + l] = fmaf(su[base + l], Dc, acc);
        }
    }
    __syncthreads();
    if (tid < 128) {
        for (int l = tid; l < DI; l += 128) {
            float g = cout_b[0];
            #pragma unroll
            for (int ci = 0; ci < 4; ci++)
                g = fmaf(syc[ci*DI + l] + syc[(4 + ci)*DI + (DI-1-l)], cout_w[ci], g);
            sg[l] = g;
        }
    }
    __syncthreads();
    float p1 = 0.f, p2 = 0.f;
    if (tid < 128)
        for (int l = tid; l < DI; l += 128) { float v = sg[l]; p1 += v; p2 += v*v; }
    if (tid < 128) red[tid] = p1;
    __syncthreads();
    for (int o = 64; o > 0; o >>= 1) {
        if (tid < o) red[tid] += red[tid+o];
        __syncthreads();
    }
    if (tid == 0) sstat[0] = red[0] * (1.f/DI);
    __syncthreads();
    if (tid < 128) red[tid] = p2;
    __syncthreads();
    for (int o = 64; o > 0; o >>= 1) {
        if (tid < o) red[tid] += red[tid+o];
        __syncthreads();
    }
    if (tid == 0) {
        float mu = sstat[0];
        sstat[1] = rsqrtf(red[0]*(1.f/DI) - mu*mu + 1e-5f);
    }
    __syncthreads();
    if (tid < 128) {
        float mu = sstat[0], rs = sstat[1];
        for (int l = tid; l < DI; l += 128)
            g_gate[l] = (sg[l] - mu)*rs*cnw[l] + cnb[l];
    }
}

// ---------------- K3: x-proj + dt-proj, register-tiled GEMM + fused chan -----
// grid (129, 4): x<128 -> proj (32 pixels, one k); (128,0) -> channel branch.
__global__ void __launch_bounds__(320) k_proj(const float* __restrict__ xpw,
                                              const float* __restrict__ dtw,
                                              const float* __restrict__ dtb,
    const float* __restrict__ cin_w, const float* __restrict__ cin_b,
    const float* __restrict__ xcw,   const float* __restrict__ dtcw,
    const float* __restrict__ dtcb,  const float* __restrict__ Ac_logs,
    const float* __restrict__ Dsc,   const float* __restrict__ cout_w,
    const float* __restrict__ cout_b,const float* __restrict__ cnw,
    const float* __restrict__ cnb) {
    __shared__ float xv[DI*32];       // [d][si]  (24 KB)
    __shared__ float wsm[38*97];      // half-K weight slab, padded (14.7 KB)
    __shared__ float xd6[6*32];
    __shared__ float sBC[32][33];     // [si][slot]  even=B_n, odd=C_n
    int tid = threadIdx.x;
    if (blockIdx.x == 128) {
        if (blockIdx.y == 0) {
            // alias chan smem onto xv / wsm (this block never runs proj)
            chan_dev(tid, cin_w, cin_b, xcw, dtcw, dtcb, Ac_logs, Dsc,
                     cout_w, cout_b, cnw, cnb,
                     xv,             // sxc  768
                     xv + 768,       // sdt  1536
                     xv + 2304,      // sdu  1536
                     xv + 3840,      // su   1536  (ends 5376 <= 6144)
                     wsm,            // syc  1536
                     wsm + 1536,     // sg   192
                     wsm + 1728,     // red  128
                     wsm + 1856);    // sstat 2
        }
        return;
    }
    int s0 = blockIdx.x * 32;
    int oid = blockIdx.y & 1;
    int kk  = blockIdx.y >> 1;
    int k = oid + kk*2;
    const float* uptr = oid ? g_xg_t : g_xg_f;
    for (int i4 = tid; i4 < DI*8; i4 += 320) {
        int d = i4 >> 3, j = i4 & 7;
        float4 v = *reinterpret_cast<const float4*>(uptr + d*L + s0 + j*4);
        *reinterpret_cast<float4*>(xv + d*32 + j*4) = v;
    }
    int r_ = tid >> 3, sq_ = tid & 7;
    float a0 = 0.f, a1 = 0.f, a2 = 0.f, a3 = 0.f;
    #pragma unroll
    for (int half = 0; half < 2; half++) {
        __syncthreads();
        for (int i = tid; i < 38*96; i += 320) {
            int r = i / 96, dd = i - r*96;
            wsm[r*97 + dd] = __ldg(xpw + (k*38 + r)*192 + half*96 + dd);
        }
        __syncthreads();
        if (tid < 304) {
            const float* wr = wsm + r_*97;
            const float* xb = xv + sq_*4 + half*96*32;
            #pragma unroll 4
            for (int dd = 0; dd < 96; dd++) {
                float w = wr[dd];
                float4 xq = *reinterpret_cast<const float4*>(xb + dd*32);
                a0 = fmaf(w, xq.x, a0);
                a1 = fmaf(w, xq.y, a1);
                a2 = fmaf(w, xq.z, a2);
                a3 = fmaf(w, xq.w, a3);
            }
        }
    }
    __syncthreads();
    if (tid < 304) {
        int sb = sq_*4;
        if (r_ < 6) {
            xd6[r_*32 + sb]     = a0;
            xd6[r_*32 + sb + 1] = a1;
            xd6[r_*32 + sb + 2] = a2;
            xd6[r_*32 + sb + 3] = a3;
        } else {
            int slot = (r_ < 22) ? 2*(r_ - 6) : 2*(r_ - 22) + 1;
            sBC[sb][slot]     = a0;
            sBC[sb + 1][slot] = a1;
            sBC[sb + 2][slot] = a2;
            sBC[sb + 3][slot] = a3;
        }
    }
    __syncthreads();
    // write B and C to chunk-interleaved layout [k][i][c][16]
    float* gB = reinterpret_cast<float*>(g_B);
    float* gC = reinterpret_cast<float*>(g_C);
    for (int idx = tid; idx < 32*16; idx += 320) {
        int si = idx >> 4, n = idx & 15;
        int s = s0 + si;
        int fo = (k*4096 + (s & 63)*64 + (s >> 6))*16 + n;
        gB[fo] = sBC[si][2*n];
        gC[fo] = sBC[si][2*n + 1];
    }
    // dt-proj + write (dt, u) pairs to chunk-interleaved float4 layout
    float2* dtu2 = reinterpret_cast<float2*>(g_dtu4);
    for (int idx = tid; idx < DI*32; idx += 320) {
        int d = idx >> 5, si = idx & 31;
        int row = k*DI + d;
        float acc = __ldg(dtb + row);
        #pragma unroll
        for (int r = 0; r < 6; r++)
            acc = fmaf(__ldg(dtw + row*6 + r), xd6[r*32 + si], acc);
        float dt = softplusf_(acc);
        float u = xv[d*32 + si];
        int s = s0 + si;
        int idx2 = row*4096 + ((s & 63) >> 1)*128 + (s >> 6)*2 + (s & 1);
        dtu2[idx2] = make_float2(dt, u);
    }
}

// -------- K4: FUSED chunked scan, 4 states/lane, 4-lane units -------------
// 256 threads = 64 chunks x 4 lanes, CLEN=64. 4 independent h-chains/thread.
template<bool FWD, bool TORD>
__device__ __forceinline__ void scan_body(
    const float4* __restrict__ pdtu4, const float4* __restrict__ pB4,
    const float4* __restrict__ pC4, float* __restrict__ pout,
    float4 An, float Dd, int c, int ln2, int tid,
    float (*s_h)[16], float (*s_p)[16])
{
    // ---- phase 1: local chunk scan (B only) ----
    float h0 = 0.f, h1 = 0.f, h2 = 0.f, h3 = 0.f, sdt = 0.f;
    #pragma unroll 4
    for (int j = 0; j < 32; j++) {
        int iA = FWD ? (2*j) : (63 - 2*j);
        int iB = FWD ? (iA + 1) : (iA - 1);
        float4 q = pdtu4[(FWD ? j : (31 - j))*64 + c];
        float dtA = FWD ? q.x : q.z, uA = FWD ? q.y : q.w;
        float dtB = FWD ? q.z : q.x, uB = FWD ? q.w : q.y;
        float4 bA = pB4[(iA*64 + c)*4 + ln2];
        float4 bB = pB4[(iB*64 + c)*4 + ln2];
        float duA = dtA*uA, duB = dtB*uB;
        h0 = fmaf(ex2_(dtA*An.x), h0, duA*bA.x);
        h1 = fmaf(ex2_(dtA*An.y), h1, duA*bA.y);
        h2 = fmaf(ex2_(dtA*An.z), h2, duA*bA.z);
        h3 = fmaf(ex2_(dtA*An.w), h3, duA*bA.w);
        h0 = fmaf(ex2_(dtB*An.x), h0, duB*bB.x);
        h1 = fmaf(ex2_(dtB*An.y), h1, duB*bB.y);
        h2 = fmaf(ex2_(dtB*An.z), h2, duB*bB.z);
        h3 = fmaf(ex2_(dtB*An.w), h3, duB*bB.w);
        sdt += dtA + dtB;
    }
    int n0 = ln2*4;
    s_h[c][n0+0] = h0; s_h[c][n0+1] = h1; s_h[c][n0+2] = h2; s_h[c][n0+3] = h3;
    s_p[c][n0+0] = ex2_(An.x*sdt); s_p[c][n0+1] = ex2_(An.y*sdt);
    s_p[c][n0+2] = ex2_(An.z*sdt); s_p[c][n0+3] = ex2_(An.w*sdt);
    __syncthreads();

    // ---- phase 2: serial combine across chunks (scan order), in-place h -> h0 ----
    if (tid < 16) {
        float H = 0.f;
        #pragma unroll 4
        for (int cc = 0; cc < NCHUNK; cc++) {
            int c2 = FWD ? cc : (NCHUNK - 1 - cc);
            float hh = s_h[c2][tid];
            float pp = s_p[c2][tid];
            s_h[c2][tid] = H;
            H = fmaf(pp, H, hh);
        }
    }
    __syncthreads();

    // ---- phase 3: re-scan with correct initial state, emit y ----
    h0 = s_h[c][n0+0]; h1 = s_h[c][n0+1]; h2 = s_h[c][n0+2]; h3 = s_h[c][n0+3];
    float ybuf = 0.f;
    const int pa = FWD ? 0 : 1;       // parity of sA
    #pragma unroll 4
    for (int j = 0; j < 32; j++) {
        int iA = FWD ? (2*j) : (63 - 2*j);
        int iB = FWD ? (iA + 1) : (iA - 1);
        int sA = c*CLEN + iA;
        int sB = c*CLEN + iB;
        float4 q = pdtu4[(FWD ? j : (31 - j))*64 + c];
        float dtA = FWD ? q.x : q.z, uA = FWD ? q.y : q.w;
        float dtB = FWD ? q.z : q.x, uB = FWD ? q.w : q.y;
        float4 bA = pB4[(iA*64 + c)*4 + ln2];
        float4 bB = pB4[(iB*64 + c)*4 + ln2];
        float4 cA = pC4[(iA*64 + c)*4 + ln2];
        float4 cB = pC4[(iB*64 + c)*4 + ln2];
        float duA = dtA*uA, duB = dtB*uB;
        h0 = fmaf(ex2_(dtA*An.x), h0, duA*bA.x);
        h1 = fmaf(ex2_(dtA*An.y), h1, duA*bA.y);
        h2 = fmaf(ex2_(dtA*An.z), h2, duA*bA.z);
        h3 = fmaf(ex2_(dtA*An.w), h3, duA*bA.w);
        float accA = fmaf(h3, cA.w, fmaf(h2, cA.z, fmaf(h1, cA.y, h0*cA.x)));
        h0 = fmaf(ex2_(dtB*An.x), h0, duB*bB.x);
        h1 = fmaf(ex2_(dtB*An.y), h1, duB*bB.y);
        h2 = fmaf(ex2_(dtB*An.z), h2, duB*bB.z);
        h3 = fmaf(ex2_(dtB*An.w), h3, duB*bB.w);
        float accB = fmaf(h3, cB.w, fmaf(h2, cB.z, fmaf(h1, cB.y, h0*cB.x)));
        // joint 4-lane reduce: 3 shfls for 2 outputs.
        accA += __shfl_xor_sync(0xffffffffu, accA, 1);
        accB += __shfl_xor_sync(0xffffffffu, accB, 1);
        float u2 = ((ln2 & 1) == pa) ? accA : accB;
        u2 += __shfl_xor_sync(0xffffffffu, u2, 2);
        float yA = fmaf(uA, Dd, u2);   // valid on lanes with parity pa
        float yB = fmaf(uB, Dd, u2);   // valid on lanes with parity 1-pa
        if (TORD) {
            if (ln2 == pa)     pout[((sA & 63) << 6) | (sA >> 6)] = yA;
            if (ln2 == 1 - pa) pout[((sB & 63) << 6) | (sB >> 6)] = yB;
        } else {
            if (ln2 == (sA & 3))      ybuf = yA;
            else if (ln2 == (sB & 3)) ybuf = yB;
            if ((j & 1) == 1)
                pout[(sA & ~3) + ln2] = ybuf;   // coalesced 4-wide per unit
        }
    }
}

__global__ void __launch_bounds__(256, 6) k_scan(const float* __restrict__ A_logs,
                                                 const float* __restrict__ Ds) {
    __shared__ float s_h[NCHUNK][16];
    __shared__ float s_p[NCHUNK][16];
    int tid = threadIdx.x;
    int c = tid >> 2;
    int ln2 = tid & 3;
    int seq = blockIdx.x;
    int k = seq / DI;
    const float4* pdtu4 = g_dtu4 + (size_t)seq*2048;
    const float4* pB4 = g_B + (size_t)k*16384;
    const float4* pC4 = g_C + (size_t)k*16384;
    float* pout = g_y4 + (size_t)seq*L;
    const float LOG2E = 1.4426950408889634f;
    float4 al = *reinterpret_cast<const float4*>(A_logs + seq*NS + ln2*4);
    float4 An = make_float4(-__expf(al.x)*LOG2E, -__expf(al.y)*LOG2E,
                            -__expf(al.z)*LOG2E, -__expf(al.w)*LOG2E);
    float Dd = __ldg(Ds + seq);
    if (k == 0)      scan_body<true,  false>(pdtu4, pB4, pC4, pout, An, Dd, c, ln2, tid, s_h, s_p);
    else if (k == 1) scan_body<true,  true >(pdtu4, pB4, pC4, pout, An, Dd, c, ln2, tid, s_h, s_p);
    else if (k == 2) scan_body<false, false>(pdtu4, pB4, pC4, pout, An, Dd, c, ln2, tid, s_h, s_p);
    else             scan_body<false, true >(pdtu4, pB4, pC4, pout, An, Dd, c, ln2, tid, s_h, s_p);
}

// ---------------- K6: combine + LN + gate*z + out-proj (192 -> 96) ----------------
__global__ void __launch_bounds__(256) k_final(const float* __restrict__ onw,
                                               const float* __restrict__ onb,
                                               const float* __restrict__ ow,
                                               const float* __restrict__ ob,
                                               float* __restrict__ out) {
    __shared__ float sv[DI*33];       // [d][si] with pad-33 pitch
    __shared__ float smu[32], srs[32];
    int tid = threadIdx.x;
    int p0 = blockIdx.x * 32;
    for (int idx = tid; idx < DI*32; idx += 256) {
        int d = idx >> 5, si = idx & 31;
        int p = p0 + si;
        float s = g_y4[(0*DI + d)*L + p] + g_y4[(1*DI + d)*L + p]
                + g_y4[(2*DI + d)*L + p] + g_y4[(3*DI + d)*L + p];
        sv[d*33 + si] = s;
    }
    __syncthreads();
    {
        int w = tid >> 5, lane = tid & 31;
        for (int q = 0; q < 4; q++) {
            int si = w*4 + q;
            float s1 = 0.f, s2 = 0.f;
            #pragma unroll
            for (int j = 0; j < 6; j++) {
                float v = sv[(lane + j*32)*33 + si];
                s1 += v; s2 += v*v;
            }
            #pragma unroll
            for (int o = 16; o > 0; o >>= 1) {
                s1 += __shfl_xor_sync(0xffffffffu, s1, o);
                s2 += __shfl_xor_sync(0xffffffffu, s2, o);
            }
            if (lane == 0) {
                float mu = s1 * (1.f/DI);
                smu[si] = mu;
                srs[si] = rsqrtf(s2*(1.f/DI) - mu*mu + 1e-5f);
            }
        }
    }
    __syncthreads();
    for (int idx = tid; idx < DI*32; idx += 256) {
        int d = idx >> 5, si = idx & 31;
        int p = p0 + si;
        float v = sv[d*33 + si];
        v = (v - smu[si]) * srs[si] * onw[d] + onb[d];
        v = v * g_gate[d] * g_z[d*L + p];
        sv[d*33 + si] = v;
    }
    __syncthreads();
    for (int idx = tid; idx < 96*32; idx += 256) {
        int o = idx >> 5, si = idx & 31;
        const float4* w4 = reinterpret_cast<const float4*>(ow + o*DI);
        float a0 = 0.f, a1 = 0.f, a2 = 0.f, a3 = 0.f;
        #pragma unroll 12
        for (int d4 = 0; d4 < 48; d4++) {
            float4 wv = __ldg(w4 + d4);
            int d = d4*4;
            a0 = fmaf(wv.x, sv[d*33+si], a0);
            a1 = fmaf(wv.y, sv[(d+1)*33+si], a1);
            a2 = fmaf(wv.z, sv[(d+2)*33+si], a2);
            a3 = fmaf(wv.w, sv[(d+3)*33+si], a3);
        }
        out[o*L + p0 + si] = ob[o] + (a0 + a1) + (a2 + a3);
    }
}

// ---------------- launch ----------------
extern "C" void kernel_launch(void* const* d_in, const int* in_sizes, int n_in,
                              void* d_out, int out_size) {
    const float* x      = (const float*)d_in[0];
    const float* in_w   = (const float*)d_in[1];
    const float* in_b   = (const float*)d_in[2];
    const float* c2w    = (const float*)d_in[3];
    const float* c2b    = (const float*)d_in[4];
    const float* xpw    = (const float*)d_in[5];
    const float* dtw    = (const float*)d_in[6];
    const float* dtb    = (const float*)d_in[7];
    const float* Alogs  = (const float*)d_in[8];
    const float* Ds     = (const float*)d_in[9];
    const float* onw    = (const float*)d_in[10];
    const float* onb    = (const float*)d_in[11];
    const float* cinw   = (const float*)d_in[12];
    const float* cinb   = (const float*)d_in[13];
    const float* coutw  = (const float*)d_in[14];
    const float* coutb  = (const float*)d_in[15];
    const float* xcw    = (const float*)d_in[16];
    const float* dtcw   = (const float*)d_in[17];
    const float* dtcb   = (const float*)d_in[18];
    const float* Aclogs = (const float*)d_in[19];
    const float* Dsc    = (const float*)d_in[20];
    const float* cnw    = (const float*)d_in[21];
    const float* cnb    = (const float*)d_in[22];
    const float* ow     = (const float*)d_in[23];
    const float* obias  = (const float*)d_in[24];
    float* out = (float*)d_out;

    k_inproj<<<dim3(32, 24), 128>>>(x, in_w, in_b);
    k_dwconv<<<dim3(2, 2, 192), dim3(32, 32)>>>(c2w, c2b);
    k_proj<<<dim3(129, 4), 320>>>(xpw, dtw, dtb,
                                  cinw, cinb, xcw, dtcw, dtcb, Aclogs, Dsc,
                                  coutw, coutb, cnw, cnb);
    k_scan<<<768, 256>>>(Alogs, Ds);
    k_final<<<128, 256>>>(onw, onb, ow, obias, out);
}

// round 11
// speedup vs baseline: 3.4291x; 1.0083x over previous
#include <cuda_runtime.h>
#include <math.h>

#define L 4096
#define DI 192
#define NS 16
#define NCHUNK 64
#define CLEN 64

// ---------------- device scratch (static, no allocations) ----------------
__device__ float g_xg_pre[DI*L];
__device__ float g_z[DI*L];
__device__ float g_xg_f[DI*L];
__device__ float g_xg_t[DI*L];
__device__ float g_cmean[DI];
// chunk-interleaved scan inputs (chunk = s>>6, i = s&63):
//   g_B[k][i(64)][c(64)][16]   (float4-aligned), same for g_C
//   g_dtu4[seq][pair(32)][c(64)] : (dtA,uA,dtB,uB) for steps 2p, 2p+1 of chunk c
__device__ float4 g_B[4*4096*4];
__device__ float4 g_C[4*4096*4];
__device__ float4 g_dtu4[768*2048];
__device__ float g_y4[4*DI*L];        // scan outputs, pixel-indexed
__device__ float g_xcdbl[2*38*DI];
__device__ float g_gate[DI];

__device__ __forceinline__ float softplusf_(float x){
    return (x > 20.f) ? x : log1pf(__expf(x));
}
__device__ __forceinline__ float ex2_(float x){
    float r;
    asm("ex2.approx.ftz.f32 %0, %1;" : "=f"(r) : "f"(x));
    return r;
}

// ---------------- K1: 1x1 in-proj (96 -> 384), 16 outputs per thread ----------
__global__ void __launch_bounds__(128) k_inproj(const float* __restrict__ x,
                                                const float* __restrict__ W,
                                                const float* __restrict__ b) {
    __shared__ float ws[96*16];   // transposed: [c][j]
    int ob = blockIdx.y * 16;
    for (int i = threadIdx.x; i < 96*16; i += 128) {
        int c = i >> 4, j = i & 15;
        ws[i] = W[(ob + j)*96 + c];
    }
    __syncthreads();
    int p = blockIdx.x * 128 + threadIdx.x;
    if (blockIdx.y == 0 && p < DI) g_cmean[p] = 0.f;   // zero for dwconv atomics
    float acc[16];
    #pragma unroll
    for (int j = 0; j < 16; j++) acc[j] = 0.f;
    #pragma unroll 2
    for (int c = 0; c < 96; c++) {
        float xv = __ldg(x + c*L + p);
        #pragma unroll
        for (int q = 0; q < 4; q++) {
            float4 w = *reinterpret_cast<const float4*>(ws + c*16 + q*4);
            acc[q*4+0] = fmaf(w.x, xv, acc[q*4+0]);
            acc[q*4+1] = fmaf(w.y, xv, acc[q*4+1]);
            acc[q*4+2] = fmaf(w.z, xv, acc[q*4+2]);
            acc[q*4+3] = fmaf(w.w, xv, acc[q*4+3]);
        }
    }
    #pragma unroll
    for (int j = 0; j < 16; j++) {
        int o = ob + j;
        float v = acc[j] + b[o];
        if (o < DI) {
            g_xg_pre[o*L + p] = v;
        } else {
            g_z[(o-DI)*L + p] = v / (1.f + __expf(-v));   // silu
        }
    }
}

// ------- K2: depthwise 3x3 + bias + silu + fused channel-mean (atomics) -------
__global__ void __launch_bounds__(1024) k_dwconv(const float* __restrict__ w,
                                                 const float* __restrict__ b) {
    __shared__ float t[32][33];
    __shared__ float wsum[32];
    int d = blockIdx.z;
    int tx = threadIdx.x, ty = threadIdx.y;
    int h = blockIdx.y*32 + ty;
    int wq = blockIdx.x*32 + tx;
    const float* src = g_xg_pre + d*L;
    float wk[9];
    #pragma unroll
    for (int i = 0; i < 9; i++) wk[i] = w[d*9 + i];
    float acc = b[d];
    #pragma unroll
    for (int kh = 0; kh < 3; kh++) {
        int hh = h + kh - 1;
        #pragma unroll
        for (int kw = 0; kw < 3; kw++) {
            int ww = wq + kw - 1;
            if (hh >= 0 && hh < 64 && ww >= 0 && ww < 64)
                acc = fmaf(wk[kh*3+kw], src[hh*64 + ww], acc);
        }
    }
    float v = acc / (1.f + __expf(-acc));   // silu
    g_xg_f[d*L + h*64 + wq] = v;
    t[ty][tx] = v;
    // block reduction for channel mean
    int tid = ty*32 + tx;
    int lane = tid & 31, wi = tid >> 5;
    float s = v;
    #pragma unroll
    for (int o = 16; o > 0; o >>= 1) s += __shfl_xor_sync(0xffffffffu, s, o);
    if (lane == 0) wsum[wi] = s;
    __syncthreads();
    float v2 = t[tx][ty];
    g_xg_t[d*L + (blockIdx.x*32 + ty)*64 + blockIdx.y*32 + tx] = v2;
    if (wi == 0) {
        float s2 = wsum[lane];
        #pragma unroll
        for (int o = 16; o > 0; o >>= 1) s2 += __shfl_xor_sync(0xffffffffu, s2, o);
        if (lane == 0) atomicAdd(&g_cmean[d], s2 * (1.f / L));
    }
}

// ---------------- channel-branch, run by one 320-thread block ----------------
// work guarded to tid<128; __syncthreads() unconditional (all 320 threads call).
__device__ __forceinline__ void chan_dev(int tid,
    const float* __restrict__ cin_w, const float* __restrict__ cin_b,
    const float* __restrict__ xcw,   const float* __restrict__ dtcw,
    const float* __restrict__ dtcb,  const float* __restrict__ Ac_logs,
    const float* __restrict__ Dsc,   const float* __restrict__ cout_w,
    const float* __restrict__ cout_b,const float* __restrict__ cnw,
    const float* __restrict__ cnb,
    float* sxc, float* sdt, float* sdu, float* su,
    float* syc, float* sg, float* red, float* sstat)
{
    if (tid < 128) {
        for (int idx = tid; idx < 4*DI; idx += 128) {
            int ci = idx / DI, l = idx % DI;
            sxc[idx] = g_cmean[l]*cin_w[ci] + cin_b[ci];
        }
    }
    __syncthreads();
    if (tid < 128) {
        for (int idx = tid; idx < 2*38*DI; idx += 128) {
            int k = idx / (38*DI);
            int r = (idx / DI) % 38;
            int l = idx % DI;
            int ls = k ? (DI-1-l) : l;
            float acc = 0.f;
            #pragma unroll
            for (int ci = 0; ci < 4; ci++)
                acc = fmaf(xcw[(k*38 + r)*4 + ci], sxc[ci*DI + ls], acc);
            g_xcdbl[idx] = acc;
        }
    }
    __syncthreads();
    if (tid < 128) {
        for (int idx = tid; idx < 2*4*DI; idx += 128) {
            int k = idx / (4*DI);
            int ci = (idx / DI) & 3;
            int l = idx % DI;
            float acc = dtcb[k*4 + ci];
            #pragma unroll
            for (int r = 0; r < 6; r++)
                acc = fmaf(dtcw[(k*4 + ci)*6 + r], g_xcdbl[(k*38 + r)*DI + l], acc);
            float dt = softplusf_(acc);
            int ls = k ? (DI-1-l) : l;
            float u = sxc[ci*DI + ls];
            sdt[idx] = dt; sdu[idx] = dt*u; su[idx] = u;
        }
    }
    __syncthreads();
    if (tid < 128) {
        int w = tid >> 5, lane = tid & 31;
        int n = lane & 15, half = lane >> 4;
        int seq = w*2 + half;        // 0..7
        int k = seq >> 2, ci = seq & 3;
        float An = -__expf(Ac_logs[(k*4 + ci)*16 + n]);
        float Dc = Dsc[k*4 + ci];
        int base = seq * DI;
        float h = 0.f;
        for (int l = 0; l < DI; l++) {
            float dt = sdt[base + l];
            float du = sdu[base + l];
            float bn = g_xcdbl[(k*38 + 6 + n)*DI + l];
            float cn = g_xcdbl[(k*38 + 22 + n)*DI + l];
            float e = __expf(dt * An);
            h = fmaf(e, h, du * bn);
            float acc = h * cn;
            acc += __shfl_xor_sync(0xffffffffu, acc, 8);
            acc += __shfl_xor_sync(0xffffffffu, acc, 4);
            acc += __shfl_xor_sync(0xffffffffu, acc, 2);
            acc += __shfl_xor_sync(0xffffffffu, acc, 1);
            if (n == 0) syc[base + l] = fmaf(su[base + l], Dc, acc);
        }
    }
    __syncthreads();
    if (tid < 128) {
        for (int l = tid; l < DI; l += 128) {
            float g = cout_b[0];
            #pragma unroll
            for (int ci = 0; ci < 4; ci++)
                g = fmaf(syc[ci*DI + l] + syc[(4 + ci)*DI + (DI-1-l)], cout_w[ci], g);
            sg[l] = g;
        }
    }
    __syncthreads();
    float p1 = 0.f, p2 = 0.f;
    if (tid < 128)
        for (int l = tid; l < DI; l += 128) { float v = sg[l]; p1 += v; p2 += v*v; }
    if (tid < 128) red[tid] = p1;
    __syncthreads();
    for (int o = 64; o > 0; o >>= 1) {
        if (tid < o) red[tid] += red[tid+o];
        __syncthreads();
    }
    if (tid == 0) sstat[0] = red[0] * (1.f/DI);
    __syncthreads();
    if (tid < 128) red[tid] = p2;
    __syncthreads();
    for (int o = 64; o > 0; o >>= 1) {
        if (tid < o) red[tid] += red[tid+o];
        __syncthreads();
    }
    if (tid == 0) {
        float mu = sstat[0];
        sstat[1] = rsqrtf(red[0]*(1.f/DI) - mu*mu + 1e-5f);
    }
    __syncthreads();
    if (tid < 128) {
        float mu = sstat[0], rs = sstat[1];
        for (int l = tid; l < DI; l += 128)
            g_gate[l] = (sg[l] - mu)*rs*cnw[l] + cnb[l];
    }
}

// ---------------- K3: x-proj + dt-proj, register-tiled GEMM + fused chan -----
// grid (129, 2): x<128 -> proj (32 pixels, BOTH k's of one ordering);
// (128,0) -> channel branch. xv loaded once per block for two k's.
__global__ void __launch_bounds__(320) k_proj(const float* __restrict__ xpw,
                                              const float* __restrict__ dtw,
                                              const float* __restrict__ dtb,
    const float* __restrict__ cin_w, const float* __restrict__ cin_b,
    const float* __restrict__ xcw,   const float* __restrict__ dtcw,
    const float* __restrict__ dtcb,  const float* __restrict__ Ac_logs,
    const float* __restrict__ Dsc,   const float* __restrict__ cout_w,
    const float* __restrict__ cout_b,const float* __restrict__ cnw,
    const float* __restrict__ cnb) {
    __shared__ float xv[DI*32];       // [d][si]  (24 KB)
    __shared__ float wsm[38*97];      // half-K weight slab, padded (14.7 KB)
    __shared__ float xd6[2*6*32];     // dt-rank activations for both k's
    __shared__ float sBC[32][33];     // [si][slot]  even=B_n, odd=C_n
    int tid = threadIdx.x;
    if (blockIdx.x == 128) {
        if (blockIdx.y == 0) {
            // alias chan smem onto xv / wsm (this block never runs proj)
            chan_dev(tid, cin_w, cin_b, xcw, dtcw, dtcb, Ac_logs, Dsc,
                     cout_w, cout_b, cnw, cnb,
                     xv,             // sxc  768
                     xv + 768,       // sdt  1536
                     xv + 2304,      // sdu  1536
                     xv + 3840,      // su   1536  (ends 5376 <= 6144)
                     wsm,            // syc  1536
                     wsm + 1536,     // sg   192
                     wsm + 1728,     // red  128
                     wsm + 1856);    // sstat 2
        }
        return;
    }
    int s0 = blockIdx.x * 32;
    int oid = blockIdx.y;             // 0: f-order {k0,k2}; 1: t-order {k1,k3}
    const float* uptr = oid ? g_xg_t : g_xg_f;
    for (int i4 = tid; i4 < DI*8; i4 += 320) {
        int d = i4 >> 3, j = i4 & 7;
        float4 v = *reinterpret_cast<const float4*>(uptr + d*L + s0 + j*4);
        *reinterpret_cast<float4*>(xv + d*32 + j*4) = v;
    }
    int r_ = tid >> 3, sq_ = tid & 7;
    float* gB = reinterpret_cast<float*>(g_B);
    float* gC = reinterpret_cast<float*>(g_C);
    #pragma unroll
    for (int kk = 0; kk < 2; kk++) {
        int k = oid + kk*2;
        float a0 = 0.f, a1 = 0.f, a2 = 0.f, a3 = 0.f;
        #pragma unroll
        for (int half = 0; half < 2; half++) {
            __syncthreads();   // xv ready (first iter) / prior wsm+sBC readers done
            for (int i = tid; i < 38*96; i += 320) {
                int r = i / 96, dd = i - r*96;
                wsm[r*97 + dd] = __ldg(xpw + (k*38 + r)*192 + half*96 + dd);
            }
            __syncthreads();
            if (tid < 304) {
                const float* wr = wsm + r_*97;
                const float* xb = xv + sq_*4 + half*96*32;
                #pragma unroll 4
                for (int dd = 0; dd < 96; dd++) {
                    float w = wr[dd];
                    float4 xq = *reinterpret_cast<const float4*>(xb + dd*32);
                    a0 = fmaf(w, xq.x, a0);
                    a1 = fmaf(w, xq.y, a1);
                    a2 = fmaf(w, xq.z, a2);
                    a3 = fmaf(w, xq.w, a3);
                }
            }
        }
        __syncthreads();
        if (tid < 304) {
            int sb = sq_*4;
            if (r_ < 6) {
                xd6[(kk*6 + r_)*32 + sb]     = a0;
                xd6[(kk*6 + r_)*32 + sb + 1] = a1;
                xd6[(kk*6 + r_)*32 + sb + 2] = a2;
                xd6[(kk*6 + r_)*32 + sb + 3] = a3;
            } else {
                int slot = (r_ < 22) ? 2*(r_ - 6) : 2*(r_ - 22) + 1;
                sBC[sb][slot]     = a0;
                sBC[sb + 1][slot] = a1;
                sBC[sb + 2][slot] = a2;
                sBC[sb + 3][slot] = a3;
            }
        }
        __syncthreads();
        // write B and C to chunk-interleaved layout [k][i][c][16]
        for (int idx = tid; idx < 32*16; idx += 320) {
            int si = idx >> 4, n = idx & 15;
            int s = s0 + si;
            int fo = (k*4096 + (s & 63)*64 + (s >> 6))*16 + n;
            gB[fo] = sBC[si][2*n];
            gC[fo] = sBC[si][2*n + 1];
        }
    }
    __syncthreads();
    // dt-proj + write (dt, u) pairs to chunk-interleaved float4 layout (both k's)
    float2* dtu2 = reinterpret_cast<float2*>(g_dtu4);
    for (int idx = tid; idx < 2*DI*32; idx += 320) {
        int kk = idx / (DI*32);
        int rem = idx - kk*(DI*32);
        int d = rem >> 5, si = rem & 31;
        int row = (oid + kk*2)*DI + d;
        float acc = __ldg(dtb + row);
        #pragma unroll
        for (int r = 0; r < 6; r++)
            acc = fmaf(__ldg(dtw + row*6 + r), xd6[(kk*6 + r)*32 + si], acc);
        float dt = softplusf_(acc);
        float u = xv[d*32 + si];
        int s = s0 + si;
        int idx2 = row*4096 + ((s & 63) >> 1)*128 + (s >> 6)*2 + (s & 1);
        dtu2[idx2] = make_float2(dt, u);
    }
}

// -------- K4: FUSED chunked scan, 4 states/lane, 4-lane units -------------
// 256 threads = 64 chunks x 4 lanes, CLEN=64. 4 independent h-chains/thread.
template<bool FWD, bool TORD>
__device__ __forceinline__ void scan_body(
    const float4* __restrict__ pdtu4, const float4* __restrict__ pB4,
    const float4* __restrict__ pC4, float* __restrict__ pout,
    float4 An, float Dd, int c, int ln2, int tid,
    float (*s_h)[16], float (*s_p)[16])
{
    // ---- phase 1: local chunk scan (B only) ----
    float h0 = 0.f, h1 = 0.f, h2 = 0.f, h3 = 0.f, sdt = 0.f;
    #pragma unroll 4
    for (int j = 0; j < 32; j++) {
        int iA = FWD ? (2*j) : (63 - 2*j);
        int iB = FWD ? (iA + 1) : (iA - 1);
        float4 q = pdtu4[(FWD ? j : (31 - j))*64 + c];
        float dtA = FWD ? q.x : q.z, uA = FWD ? q.y : q.w;
        float dtB = FWD ? q.z : q.x, uB = FWD ? q.w : q.y;
        float4 bA = pB4[(iA*64 + c)*4 + ln2];
        float4 bB = pB4[(iB*64 + c)*4 + ln2];
        float duA = dtA*uA, duB = dtB*uB;
        h0 = fmaf(ex2_(dtA*An.x), h0, duA*bA.x);
        h1 = fmaf(ex2_(dtA*An.y), h1, duA*bA.y);
        h2 = fmaf(ex2_(dtA*An.z), h2, duA*bA.z);
        h3 = fmaf(ex2_(dtA*An.w), h3, duA*bA.w);
        h0 = fmaf(ex2_(dtB*An.x), h0, duB*bB.x);
        h1 = fmaf(ex2_(dtB*An.y), h1, duB*bB.y);
        h2 = fmaf(ex2_(dtB*An.z), h2, duB*bB.z);
        h3 = fmaf(ex2_(dtB*An.w), h3, duB*bB.w);
        sdt += dtA + dtB;
    }
    int n0 = ln2*4;
    s_h[c][n0+0] = h0; s_h[c][n0+1] = h1; s_h[c][n0+2] = h2; s_h[c][n0+3] = h3;
    s_p[c][n0+0] = ex2_(An.x*sdt); s_p[c][n0+1] = ex2_(An.y*sdt);
    s_p[c][n0+2] = ex2_(An.z*sdt); s_p[c][n0+3] = ex2_(An.w*sdt);
    __syncthreads();

    // ---- phase 2: serial combine across chunks (scan order), in-place h -> h0 ----
    if (tid < 16) {
        float H = 0.f;
        #pragma unroll 4
        for (int cc = 0; cc < NCHUNK; cc++) {
            int c2 = FWD ? cc : (NCHUNK - 1 - cc);
            float hh = s_h[c2][tid];
            float pp = s_p[c2][tid];
            s_h[c2][tid] = H;
            H = fmaf(pp, H, hh);
        }
    }
    __syncthreads();

    // ---- phase 3: re-scan with correct initial state, emit y ----
    h0 = s_h[c][n0+0]; h1 = s_h[c][n0+1]; h2 = s_h[c][n0+2]; h3 = s_h[c][n0+3];
    float ybuf = 0.f;
    const int pa = FWD ? 0 : 1;       // parity of sA
    #pragma unroll 4
    for (int j = 0; j < 32; j++) {
        int iA = FWD ? (2*j) : (63 - 2*j);
        int iB = FWD ? (iA + 1) : (iA - 1);
        int sA = c*CLEN + iA;
        int sB = c*CLEN + iB;
        float4 q = pdtu4[(FWD ? j : (31 - j))*64 + c];
        float dtA = FWD ? q.x : q.z, uA = FWD ? q.y : q.w;
        float dtB = FWD ? q.z : q.x, uB = FWD ? q.w : q.y;
        float4 bA = pB4[(iA*64 + c)*4 + ln2];
        float4 bB = pB4[(iB*64 + c)*4 + ln2];
        float4 cA = pC4[(iA*64 + c)*4 + ln2];
        float4 cB = pC4[(iB*64 + c)*4 + ln2];
        float duA = dtA*uA, duB = dtB*uB;
        h0 = fmaf(ex2_(dtA*An.x), h0, duA*bA.x);
        h1 = fmaf(ex2_(dtA*An.y), h1, duA*bA.y);
        h2 = fmaf(ex2_(dtA*An.z), h2, duA*bA.z);
        h3 = fmaf(ex2_(dtA*An.w), h3, duA*bA.w);
        float accA = fmaf(h3, cA.w, fmaf(h2, cA.z, fmaf(h1, cA.y, h0*cA.x)));
        h0 = fmaf(ex2_(dtB*An.x), h0, duB*bB.x);
        h1 = fmaf(ex2_(dtB*An.y), h1, duB*bB.y);
        h2 = fmaf(ex2_(dtB*An.z), h2, duB*bB.z);
        h3 = fmaf(ex2_(dtB*An.w), h3, duB*bB.w);
        float accB = fmaf(h3, cB.w, fmaf(h2, cB.z, fmaf(h1, cB.y, h0*cB.x)));
        // joint 4-lane reduce: 3 shfls for 2 outputs.
        accA += __shfl_xor_sync(0xffffffffu, accA, 1);
        accB += __shfl_xor_sync(0xffffffffu, accB, 1);
        float u2 = ((ln2 & 1) == pa) ? accA : accB;
        u2 += __shfl_xor_sync(0xffffffffu, u2, 2);
        float yA = fmaf(uA, Dd, u2);   // valid on lanes with parity pa
        float yB = fmaf(uB, Dd, u2);   // valid on lanes with parity 1-pa
        if (TORD) {
            if (ln2 == pa)     pout[((sA & 63) << 6) | (sA >> 6)] = yA;
            if (ln2 == 1 - pa) pout[((sB & 63) << 6) | (sB >> 6)] = yB;
        } else {
            if (ln2 == (sA & 3))      ybuf = yA;
            else if (ln2 == (sB & 3)) ybuf = yB;
            if ((j & 1) == 1)
                pout[(sA & ~3) + ln2] = ybuf;   // coalesced 4-wide per unit
        }
    }
}

__global__ void __launch_bounds__(256, 6) k_scan(const float* __restrict__ A_logs,
                                                 const float* __restrict__ Ds) {
    __shared__ float s_h[NCHUNK][16];
    __shared__ float s_p[NCHUNK][16];
    int tid = threadIdx.x;
    int c = tid >> 2;
    int ln2 = tid & 3;
    int seq = blockIdx.x;
    int k = seq / DI;
    const float4* pdtu4 = g_dtu4 + (size_t)seq*2048;
    const float4* pB4 = g_B + (size_t)k*16384;
    const float4* pC4 = g_C + (size_t)k*16384;
    float* pout = g_y4 + (size_t)seq*L;
    const float LOG2E = 1.4426950408889634f;
    float4 al = *reinterpret_cast<const float4*>(A_logs + seq*NS + ln2*4);
    float4 An = make_float4(-__expf(al.x)*LOG2E, -__expf(al.y)*LOG2E,
                            -__expf(al.z)*LOG2E, -__expf(al.w)*LOG2E);
    float Dd = __ldg(Ds + seq);
    if (k == 0)      scan_body<true,  false>(pdtu4, pB4, pC4, pout, An, Dd, c, ln2, tid, s_h, s_p);
    else if (k == 1) scan_body<true,  true >(pdtu4, pB4, pC4, pout, An, Dd, c, ln2, tid, s_h, s_p);
    else if (k == 2) scan_body<false, false>(pdtu4, pB4, pC4, pout, An, Dd, c, ln2, tid, s_h, s_p);
    else             scan_body<false, true >(pdtu4, pB4, pC4, pout, An, Dd, c, ln2, tid, s_h, s_p);
}

// ---------------- K6: combine + LN + gate*z + out-proj (192 -> 96) ----------------
__global__ void __launch_bounds__(256) k_final(const float* __restrict__ onw,
                                               const float* __restrict__ onb,
                                               const float* __restrict__ ow,
                                               const float* __restrict__ ob,
                                               float* __restrict__ out) {
    __shared__ float sv[DI*33];       // [d][si] with pad-33 pitch
    __shared__ float smu[32], srs[32];
    int tid = threadIdx.x;
    int p0 = blockIdx.x * 32;
    for (int idx = tid; idx < DI*32; idx += 256) {
        int d = idx >> 5, si = idx & 31;
        int p = p0 + si;
        float s = g_y4[(0*DI + d)*L + p] + g_y4[(1*DI + d)*L + p]
                + g_y4[(2*DI + d)*L + p] + g_y4[(3*DI + d)*L + p];
        sv[d*33 + si] = s;
    }
    __syncthreads();
    {
        int w = tid >> 5, lane = tid & 31;
        for (int q = 0; q < 4; q++) {
            int si = w*4 + q;
            float s1 = 0.f, s2 = 0.f;
            #pragma unroll
            for (int j = 0; j < 6; j++) {
                float v = sv[(lane + j*32)*33 + si];
                s1 += v; s2 += v*v;
            }
            #pragma unroll
            for (int o = 16; o > 0; o >>= 1) {
                s1 += __shfl_xor_sync(0xffffffffu, s1, o);
                s2 += __shfl_xor_sync(0xffffffffu, s2, o);
            }
            if (lane == 0) {
                float mu = s1 * (1.f/DI);
                smu[si] = mu;
                srs[si] = rsqrtf(s2*(1.f/DI) - mu*mu + 1e-5f);
            }
        }
    }
    __syncthreads();
    for (int idx = tid; idx < DI*32; idx += 256) {
        int d = idx >> 5, si = idx & 31;
        int p = p0 + si;
        float v = sv[d*33 + si];
        v = (v - smu[si]) * srs[si] * onw[d] + onb[d];
        v = v * g_gate[d] * g_z[d*L + p];
        sv[d*33 + si] = v;
    }
    __syncthreads();
    for (int idx = tid; idx < 96*32; idx += 256) {
        int o = idx >> 5, si = idx & 31;
        const float4* w4 = reinterpret_cast<const float4*>(ow + o*DI);
        float a0 = 0.f, a1 = 0.f, a2 = 0.f, a3 = 0.f;
        #pragma unroll 12
        for (int d4 = 0; d4 < 48; d4++) {
            float4 wv = __ldg(w4 + d4);
            int d = d4*4;
            a0 = fmaf(wv.x, sv[d*33+si], a0);
            a1 = fmaf(wv.y, sv[(d+1)*33+si], a1);
            a2 = fmaf(wv.z, sv[(d+2)*33+si], a2);
            a3 = fmaf(wv.w, sv[(d+3)*33+si], a3);
        }
        out[o*L + p0 + si] = ob[o] + (a0 + a1) + (a2 + a3);
    }
}

// ---------------- launch ----------------
extern "C" void kernel_launch(void* const* d_in, const int* in_sizes, int n_in,
                              void* d_out, int out_size) {
    const float* x      = (const float*)d_in[0];
    const float* in_w   = (const float*)d_in[1];
    const float* in_b   = (const float*)d_in[2];
    const float* c2w    = (const float*)d_in[3];
    const float* c2b    = (const float*)d_in[4];
    const float* xpw    = (const float*)d_in[5];
    const float* dtw    = (const float*)d_in[6];
    const float* dtb    = (const float*)d_in[7];
    const float* Alogs  = (const float*)d_in[8];
    const float* Ds     = (const float*)d_in[9];
    const float* onw    = (const float*)d_in[10];
    const float* onb    = (const float*)d_in[11];
    const float* cinw   = (const float*)d_in[12];
    const float* cinb   = (const float*)d_in[13];
    const float* coutw  = (const float*)d_in[14];
    const float* coutb  = (const float*)d_in[15];
    const float* xcw    = (const float*)d_in[16];
    const float* dtcw   = (const float*)d_in[17];
    const float* dtcb   = (const float*)d_in[18];
    const float* Aclogs = (const float*)d_in[19];
    const float* Dsc    = (const float*)d_in[20];
    const float* cnw    = (const float*)d_in[21];
    const float* cnb    = (const float*)d_in[22];
    const float* ow     = (const float*)d_in[23];
    const float* obias  = (const float*)d_in[24];
    float* out = (float*)d_out;

    k_inproj<<<dim3(32, 24), 128>>>(x, in_w, in_b);
    k_dwconv<<<dim3(2, 2, 192), dim3(32, 32)>>>(c2w, c2b);
    k_proj<<<dim3(129, 2), 320>>>(xpw, dtw, dtb,
                                  cinw, cinb, xcw, dtcw, dtcb, Aclogs, Dsc,
                                  coutw, coutb, cnw, cnb);
    k_scan<<<768, 256>>>(Alogs, Ds);
    k_final<<<128, 256>>>(onw, onb, ow, obias, out);
}

// round 12
// speedup vs baseline: 3.5535x; 1.0363x over previous
#include <cuda_runtime.h>
#include <cuda_fp16.h>
#include <math.h>

#define L 4096
#define DI 192
#define NS 16
#define NCHUNK 64
#define CLEN 64

// ---------------- device scratch (static, no allocations) ----------------
__device__ float g_xg_pre[DI*L];
__device__ float g_z[DI*L];
__device__ float g_xg_f[DI*L];
__device__ float g_xg_t[DI*L];
__device__ float g_cmean[DI];
// chunk-interleaved scan inputs (chunk = s>>6, i = s&63):
//   g_Bh[k][i(64)][c(64)][16]  fp16 states (uint2 = 4 states per lane), same g_Ch
//   g_dtu4[seq][pair(32)][c(64)] : (dtA,uA,dtB,uB) fp32
__device__ __half g_Bh[4*4096*16];
__device__ __half g_Ch[4*4096*16];
__device__ float4 g_dtu4[768*2048];
__device__ float g_y4[4*DI*L];        // scan outputs, pixel-indexed
__device__ float g_xcdbl[2*38*DI];
__device__ float g_gate[DI];

__device__ __forceinline__ float softplusf_(float x){
    return (x > 20.f) ? x : log1pf(__expf(x));
}
__device__ __forceinline__ float ex2_(float x){
    float r;
    asm("ex2.approx.ftz.f32 %0, %1;" : "=f"(r) : "f"(x));
    return r;
}
// load 4 fp16 states as float4 via one 8B load
__device__ __forceinline__ float4 ld_h4(const uint2* __restrict__ p, int idx){
    uint2 r = __ldg(p + idx);
    __half2 h0 = *reinterpret_cast<const __half2*>(&r.x);
    __half2 h1 = *reinterpret_cast<const __half2*>(&r.y);
    float2 a = __half22float2(h0);
    float2 b = __half22float2(h1);
    return make_float4(a.x, a.y, b.x, b.y);
}

// ---------------- K1: 1x1 in-proj (96 -> 384), 16 outputs per thread ----------
__global__ void __launch_bounds__(128) k_inproj(const float* __restrict__ x,
                                                const float* __restrict__ W,
                                                const float* __restrict__ b) {
    __shared__ float ws[96*16];   // transposed: [c][j]
    int ob = blockIdx.y * 16;
    for (int i = threadIdx.x; i < 96*16; i += 128) {
        int c = i >> 4, j = i & 15;
        ws[i] = W[(ob + j)*96 + c];
    }
    __syncthreads();
    int p = blockIdx.x * 128 + threadIdx.x;
    if (blockIdx.y == 0 && p < DI) g_cmean[p] = 0.f;   // zero for dwconv atomics
    float acc[16];
    #pragma unroll
    for (int j = 0; j < 16; j++) acc[j] = 0.f;
    #pragma unroll 2
    for (int c = 0; c < 96; c++) {
        float xv = __ldg(x + c*L + p);
        #pragma unroll
        for (int q = 0; q < 4; q++) {
            float4 w = *reinterpret_cast<const float4*>(ws + c*16 + q*4);
            acc[q*4+0] = fmaf(w.x, xv, acc[q*4+0]);
            acc[q*4+1] = fmaf(w.y, xv, acc[q*4+1]);
            acc[q*4+2] = fmaf(w.z, xv, acc[q*4+2]);
            acc[q*4+3] = fmaf(w.w, xv, acc[q*4+3]);
        }
    }
    #pragma unroll
    for (int j = 0; j < 16; j++) {
        int o = ob + j;
        float v = acc[j] + b[o];
        if (o < DI) {
            g_xg_pre[o*L + p] = v;
        } else {
            g_z[(o-DI)*L + p] = v / (1.f + __expf(-v));   // silu
        }
    }
}

// ------- K2: depthwise 3x3 + bias + silu + fused channel-mean (atomics) -------
__global__ void __launch_bounds__(1024) k_dwconv(const float* __restrict__ w,
                                                 const float* __restrict__ b) {
    __shared__ float t[32][33];
    __shared__ float wsum[32];
    int d = blockIdx.z;
    int tx = threadIdx.x, ty = threadIdx.y;
    int h = blockIdx.y*32 + ty;
    int wq = blockIdx.x*32 + tx;
    const float* src = g_xg_pre + d*L;
    float wk[9];
    #pragma unroll
    for (int i = 0; i < 9; i++) wk[i] = w[d*9 + i];
    float acc = b[d];
    #pragma unroll
    for (int kh = 0; kh < 3; kh++) {
        int hh = h + kh - 1;
        #pragma unroll
        for (int kw = 0; kw < 3; kw++) {
            int ww = wq + kw - 1;
            if (hh >= 0 && hh < 64 && ww >= 0 && ww < 64)
                acc = fmaf(wk[kh*3+kw], src[hh*64 + ww], acc);
        }
    }
    float v = acc / (1.f + __expf(-acc));   // silu
    g_xg_f[d*L + h*64 + wq] = v;
    t[ty][tx] = v;
    // block reduction for channel mean
    int tid = ty*32 + tx;
    int lane = tid & 31, wi = tid >> 5;
    float s = v;
    #pragma unroll
    for (int o = 16; o > 0; o >>= 1) s += __shfl_xor_sync(0xffffffffu, s, o);
    if (lane == 0) wsum[wi] = s;
    __syncthreads();
    float v2 = t[tx][ty];
    g_xg_t[d*L + (blockIdx.x*32 + ty)*64 + blockIdx.y*32 + tx] = v2;
    if (wi == 0) {
        float s2 = wsum[lane];
        #pragma unroll
        for (int o = 16; o > 0; o >>= 1) s2 += __shfl_xor_sync(0xffffffffu, s2, o);
        if (lane == 0) atomicAdd(&g_cmean[d], s2 * (1.f / L));
    }
}

// ---------------- channel-branch, run by one 320-thread block ----------------
__device__ __forceinline__ void chan_dev(int tid,
    const float* __restrict__ cin_w, const float* __restrict__ cin_b,
    const float* __restrict__ xcw,   const float* __restrict__ dtcw,
    const float* __restrict__ dtcb,  const float* __restrict__ Ac_logs,
    const float* __restrict__ Dsc,   const float* __restrict__ cout_w,
    const float* __restrict__ cout_b,const float* __restrict__ cnw,
    const float* __restrict__ cnb,
    float* sxc, float* sdt, float* sdu, float* su,
    float* syc, float* sg, float* red, float* sstat)
{
    if (tid < 128) {
        for (int idx = tid; idx < 4*DI; idx += 128) {
            int ci = idx / DI, l = idx % DI;
            sxc[idx] = g_cmean[l]*cin_w[ci] + cin_b[ci];
        }
    }
    __syncthreads();
    if (tid < 128) {
        for (int idx = tid; idx < 2*38*DI; idx += 128) {
            int k = idx / (38*DI);
            int r = (idx / DI) % 38;
            int l = idx % DI;
            int ls = k ? (DI-1-l) : l;
            float acc = 0.f;
            #pragma unroll
            for (int ci = 0; ci < 4; ci++)
                acc = fmaf(xcw[(k*38 + r)*4 + ci], sxc[ci*DI + ls], acc);
            g_xcdbl[idx] = acc;
        }
    }
    __syncthreads();
    if (tid < 128) {
        for (int idx = tid; idx < 2*4*DI; idx += 128) {
            int k = idx / (4*DI);
            int ci = (idx / DI) & 3;
            int l = idx % DI;
            float acc = dtcb[k*4 + ci];
            #pragma unroll
            for (int r = 0; r < 6; r++)
                acc = fmaf(dtcw[(k*4 + ci)*6 + r], g_xcdbl[(k*38 + r)*DI + l], acc);
            float dt = softplusf_(acc);
            int ls = k ? (DI-1-l) : l;
            float u = sxc[ci*DI + ls];
            sdt[idx] = dt; sdu[idx] = dt*u; su[idx] = u;
        }
    }
    __syncthreads();
    if (tid < 128) {
        int w = tid >> 5, lane = tid & 31;
        int n = lane & 15, half = lane >> 4;
        int seq = w*2 + half;        // 0..7
        int k = seq >> 2, ci = seq & 3;
        float An = -__expf(Ac_logs[(k*4 + ci)*16 + n]);
        float Dc = Dsc[k*4 + ci];
        int base = seq * DI;
        float h = 0.f;
        for (int l = 0; l < DI; l++) {
            float dt = sdt[base + l];
            float du = sdu[base + l];
            float bn = g_xcdbl[(k*38 + 6 + n)*DI + l];
            float cn = g_xcdbl[(k*38 + 22 + n)*DI + l];
            float e = __expf(dt * An);
            h = fmaf(e, h, du * bn);
            float acc = h * cn;
            acc += __shfl_xor_sync(0xffffffffu, acc, 8);
            acc += __shfl_xor_sync(0xffffffffu, acc, 4);
            acc += __shfl_xor_sync(0xffffffffu, acc, 2);
            acc += __shfl_xor_sync(0xffffffffu, acc, 1);
            if (n == 0) syc[base + l] = fmaf(su[base + l], Dc, acc);
        }
    }
    __syncthreads();
    if (tid < 128) {
        for (int l = tid; l < DI; l += 128) {
            float g = cout_b[0];
            #pragma unroll
            for (int ci = 0; ci < 4; ci++)
                g = fmaf(syc[ci*DI + l] + syc[(4 + ci)*DI + (DI-1-l)], cout_w[ci], g);
            sg[l] = g;
        }
    }
    __syncthreads();
    float p1 = 0.f, p2 = 0.f;
    if (tid < 128)
        for (int l = tid; l < DI; l += 128) { float v = sg[l]; p1 += v; p2 += v*v; }
    if (tid < 128) red[tid] = p1;
    __syncthreads();
    for (int o = 64; o > 0; o >>= 1) {
        if (tid < o) red[tid] += red[tid+o];
        __syncthreads();
    }
    if (tid == 0) sstat[0] = red[0] * (1.f/DI);
    __syncthreads();
    if (tid < 128) red[tid] = p2;
    __syncthreads();
    for (int o = 64; o > 0; o >>= 1) {
        if (tid < o) red[tid] += red[tid+o];
        __syncthreads();
    }
    if (tid == 0) {
        float mu = sstat[0];
        sstat[1] = rsqrtf(red[0]*(1.f/DI) - mu*mu + 1e-5f);
    }
    __syncthreads();
    if (tid < 128) {
        float mu = sstat[0], rs = sstat[1];
        for (int l = tid; l < DI; l += 128)
            g_gate[l] = (sg[l] - mu)*rs*cnw[l] + cnb[l];
    }
}

// ---------------- K3: x-proj + dt-proj, register-tiled GEMM + fused chan -----
// grid (129, 2): x<128 -> proj (32 pixels, BOTH k's of one ordering);
// (128,0) -> channel branch. xv loaded once per block for two k's.
__global__ void __launch_bounds__(320) k_proj(const float* __restrict__ xpw,
                                              const float* __restrict__ dtw,
                                              const float* __restrict__ dtb,
    const float* __restrict__ cin_w, const float* __restrict__ cin_b,
    const float* __restrict__ xcw,   const float* __restrict__ dtcw,
    const float* __restrict__ dtcb,  const float* __restrict__ Ac_logs,
    const float* __restrict__ Dsc,   const float* __restrict__ cout_w,
    const float* __restrict__ cout_b,const float* __restrict__ cnw,
    const float* __restrict__ cnb) {
    __shared__ float xv[DI*32];       // [d][si]  (24 KB)
    __shared__ float wsm[38*97];      // half-K weight slab, padded (14.7 KB)
    __shared__ float xd6[2*6*32];     // dt-rank activations for both k's
    __shared__ float sBC[32][33];     // [si][slot]  even=B_n, odd=C_n
    int tid = threadIdx.x;
    if (blockIdx.x == 128) {
        if (blockIdx.y == 0) {
            chan_dev(tid, cin_w, cin_b, xcw, dtcw, dtcb, Ac_logs, Dsc,
                     cout_w, cout_b, cnw, cnb,
                     xv, xv + 768, xv + 2304, xv + 3840,
                     wsm, wsm + 1536, wsm + 1728, wsm + 1856);
        }
        return;
    }
    int s0 = blockIdx.x * 32;
    int oid = blockIdx.y;             // 0: f-order {k0,k2}; 1: t-order {k1,k3}
    const float* uptr = oid ? g_xg_t : g_xg_f;
    for (int i4 = tid; i4 < DI*8; i4 += 320) {
        int d = i4 >> 3, j = i4 & 7;
        float4 v = *reinterpret_cast<const float4*>(uptr + d*L + s0 + j*4);
        *reinterpret_cast<float4*>(xv + d*32 + j*4) = v;
    }
    int r_ = tid >> 3, sq_ = tid & 7;
    #pragma unroll
    for (int kk = 0; kk < 2; kk++) {
        int k = oid + kk*2;
        float a0 = 0.f, a1 = 0.f, a2 = 0.f, a3 = 0.f;
        #pragma unroll
        for (int half = 0; half < 2; half++) {
            __syncthreads();
            for (int i = tid; i < 38*96; i += 320) {
                int r = i / 96, dd = i - r*96;
                wsm[r*97 + dd] = __ldg(xpw + (k*38 + r)*192 + half*96 + dd);
            }
            __syncthreads();
            if (tid < 304) {
                const float* wr = wsm + r_*97;
                const float* xb = xv + sq_*4 + half*96*32;
                #pragma unroll 4
                for (int dd = 0; dd < 96; dd++) {
                    float w = wr[dd];
                    float4 xq = *reinterpret_cast<const float4*>(xb + dd*32);
                    a0 = fmaf(w, xq.x, a0);
                    a1 = fmaf(w, xq.y, a1);
                    a2 = fmaf(w, xq.z, a2);
                    a3 = fmaf(w, xq.w, a3);
                }
            }
        }
        __syncthreads();
        if (tid < 304) {
            int sb = sq_*4;
            if (r_ < 6) {
                xd6[(kk*6 + r_)*32 + sb]     = a0;
                xd6[(kk*6 + r_)*32 + sb + 1] = a1;
                xd6[(kk*6 + r_)*32 + sb + 2] = a2;
                xd6[(kk*6 + r_)*32 + sb + 3] = a3;
            } else {
                int slot = (r_ < 22) ? 2*(r_ - 6) : 2*(r_ - 22) + 1;
                sBC[sb][slot]     = a0;
                sBC[sb + 1][slot] = a1;
                sBC[sb + 2][slot] = a2;
                sBC[sb + 3][slot] = a3;
            }
        }
        __syncthreads();
        // write B and C (fp16) to chunk-interleaved layout [k][i][c][16]
        for (int idx = tid; idx < 32*16; idx += 320) {
            int si = idx >> 4, n = idx & 15;
            int s = s0 + si;
            int fo = (k*4096 + (s & 63)*64 + (s >> 6))*16 + n;
            g_Bh[fo] = __float2half_rn(sBC[si][2*n]);
            g_Ch[fo] = __float2half_rn(sBC[si][2*n + 1]);
        }
    }
    __syncthreads();
    // dt-proj + write (dt, u) pairs to chunk-interleaved float4 layout (both k's)
    float2* dtu2 = reinterpret_cast<float2*>(g_dtu4);
    for (int idx = tid; idx < 2*DI*32; idx += 320) {
        int kk = idx / (DI*32);
        int rem = idx - kk*(DI*32);
        int d = rem >> 5, si = rem & 31;
        int row = (oid + kk*2)*DI + d;
        float acc = __ldg(dtb + row);
        #pragma unroll
        for (int r = 0; r < 6; r++)
            acc = fmaf(__ldg(dtw + row*6 + r), xd6[(kk*6 + r)*32 + si], acc);
        float dt = softplusf_(acc);
        float u = xv[d*32 + si];
        int s = s0 + si;
        int idx2 = row*4096 + ((s & 63) >> 1)*128 + (s >> 6)*2 + (s & 1);
        dtu2[idx2] = make_float2(dt, u);
    }
}

// -------- K4: FUSED chunked scan, 4 states/lane, fp16 B/C -----------------
// 256 threads = 64 chunks x 4 lanes, CLEN=64. 4 independent h-chains/thread.
template<bool FWD, bool TORD>
__device__ __forceinline__ void scan_body(
    const float4* __restrict__ pdtu4, const uint2* __restrict__ pBu,
    const uint2* __restrict__ pCu, float* __restrict__ pout,
    float4 An, float Dd, int c, int ln2, int tid,
    float (*s_h)[16], float (*s_p)[16])
{
    // ---- phase 1: local chunk scan (B only) ----
    float h0 = 0.f, h1 = 0.f, h2 = 0.f, h3 = 0.f, sdt = 0.f;
    #pragma unroll 4
    for (int j = 0; j < 32; j++) {
        int iA = FWD ? (2*j) : (63 - 2*j);
        int iB = FWD ? (iA + 1) : (iA - 1);
        float4 q = pdtu4[(FWD ? j : (31 - j))*64 + c];
        float dtA = FWD ? q.x : q.z, uA = FWD ? q.y : q.w;
        float dtB = FWD ? q.z : q.x, uB = FWD ? q.w : q.y;
        float4 bA = ld_h4(pBu, (iA*64 + c)*4 + ln2);
        float4 bB = ld_h4(pBu, (iB*64 + c)*4 + ln2);
        float duA = dtA*uA, duB = dtB*uB;
        h0 = fmaf(ex2_(dtA*An.x), h0, duA*bA.x);
        h1 = fmaf(ex2_(dtA*An.y), h1, duA*bA.y);
        h2 = fmaf(ex2_(dtA*An.z), h2, duA*bA.z);
        h3 = fmaf(ex2_(dtA*An.w), h3, duA*bA.w);
        h0 = fmaf(ex2_(dtB*An.x), h0, duB*bB.x);
        h1 = fmaf(ex2_(dtB*An.y), h1, duB*bB.y);
        h2 = fmaf(ex2_(dtB*An.z), h2, duB*bB.z);
        h3 = fmaf(ex2_(dtB*An.w), h3, duB*bB.w);
        sdt += dtA + dtB;
    }
    int n0 = ln2*4;
    s_h[c][n0+0] = h0; s_h[c][n0+1] = h1; s_h[c][n0+2] = h2; s_h[c][n0+3] = h3;
    s_p[c][n0+0] = ex2_(An.x*sdt); s_p[c][n0+1] = ex2_(An.y*sdt);
    s_p[c][n0+2] = ex2_(An.z*sdt); s_p[c][n0+3] = ex2_(An.w*sdt);
    __syncthreads();

    // ---- phase 2: serial combine across chunks (scan order), in-place h -> h0 ----
    if (tid < 16) {
        float H = 0.f;
        #pragma unroll 4
        for (int cc = 0; cc < NCHUNK; cc++) {
            int c2 = FWD ? cc : (NCHUNK - 1 - cc);
            float hh = s_h[c2][tid];
            float pp = s_p[c2][tid];
            s_h[c2][tid] = H;
            H = fmaf(pp, H, hh);
        }
    }
    __syncthreads();

    // ---- phase 3: re-scan with correct initial state, emit y ----
    h0 = s_h[c][n0+0]; h1 = s_h[c][n0+1]; h2 = s_h[c][n0+2]; h3 = s_h[c][n0+3];
    float ybuf = 0.f;
    const int pa = FWD ? 0 : 1;       // parity of sA
    #pragma unroll 4
    for (int j = 0; j < 32; j++) {
        int iA = FWD ? (2*j) : (63 - 2*j);
        int iB = FWD ? (iA + 1) : (iA - 1);
        int sA = c*CLEN + iA;
        int sB = c*CLEN + iB;
        float4 q = pdtu4[(FWD ? j : (31 - j))*64 + c];
        float dtA = FWD ? q.x : q.z, uA = FWD ? q.y : q.w;
        float dtB = FWD ? q.z : q.x, uB = FWD ? q.w : q.y;
        float4 bA = ld_h4(pBu, (iA*64 + c)*4 + ln2);
        float4 bB = ld_h4(pBu, (iB*64 + c)*4 + ln2);
        float4 cA = ld_h4(pCu, (iA*64 + c)*4 + ln2);
        float4 cB = ld_h4(pCu, (iB*64 + c)*4 + ln2);
        float duA = dtA*uA, duB = dtB*uB;
        h0 = fmaf(ex2_(dtA*An.x), h0, duA*bA.x);
        h1 = fmaf(ex2_(dtA*An.y), h1, duA*bA.y);
        h2 = fmaf(ex2_(dtA*An.z), h2, duA*bA.z);
        h3 = fmaf(ex2_(dtA*An.w), h3, duA*bA.w);
        float accA = fmaf(h3, cA.w, fmaf(h2, cA.z, fmaf(h1, cA.y, h0*cA.x)));
        h0 = fmaf(ex2_(dtB*An.x), h0, duB*bB.x);
        h1 = fmaf(ex2_(dtB*An.y), h1, duB*bB.y);
        h2 = fmaf(ex2_(dtB*An.z), h2, duB*bB.z);
        h3 = fmaf(ex2_(dtB*An.w), h3, duB*bB.w);
        float accB = fmaf(h3, cB.w, fmaf(h2, cB.z, fmaf(h1, cB.y, h0*cB.x)));
        // joint 4-lane reduce: 3 shfls for 2 outputs.
        accA += __shfl_xor_sync(0xffffffffu, accA, 1);
        accB += __shfl_xor_sync(0xffffffffu, accB, 1);
        float u2 = ((ln2 & 1) == pa) ? accA : accB;
        u2 += __shfl_xor_sync(0xffffffffu, u2, 2);
        float yA = fmaf(uA, Dd, u2);   // valid on lanes with parity pa
        float yB = fmaf(uB, Dd, u2);   // valid on lanes with parity 1-pa
        if (TORD) {
            if (ln2 == pa)     pout[((sA & 63) << 6) | (sA >> 6)] = yA;
            if (ln2 == 1 - pa) pout[((sB & 63) << 6) | (sB >> 6)] = yB;
        } else {
            if (ln2 == (sA & 3))      ybuf = yA;
            else if (ln2 == (sB & 3)) ybuf = yB;
            if ((j & 1) == 1)
                pout[(sA & ~3) + ln2] = ybuf;   // coalesced 4-wide per unit
        }
    }
}

__global__ void __launch_bounds__(256, 6) k_scan(const float* __restrict__ A_logs,
                                                 const float* __restrict__ Ds) {
    __shared__ float s_h[NCHUNK][16];
    __shared__ float s_p[NCHUNK][16];
    int tid = threadIdx.x;
    int c = tid >> 2;
    int ln2 = tid & 3;
    int seq = blockIdx.x;
    int k = seq / DI;
    const float4* pdtu4 = g_dtu4 + (size_t)seq*2048;
    const uint2* pBu = reinterpret_cast<const uint2*>(g_Bh) + (size_t)k*16384;
    const uint2* pCu = reinterpret_cast<const uint2*>(g_Ch) + (size_t)k*16384;
    float* pout = g_y4 + (size_t)seq*L;
    const float LOG2E = 1.4426950408889634f;
    float4 al = *reinterpret_cast<const float4*>(A_logs + seq*NS + ln2*4);
    float4 An = make_float4(-__expf(al.x)*LOG2E, -__expf(al.y)*LOG2E,
                            -__expf(al.z)*LOG2E, -__expf(al.w)*LOG2E);
    float Dd = __ldg(Ds + seq);
    if (k == 0)      scan_body<true,  false>(pdtu4, pBu, pCu, pout, An, Dd, c, ln2, tid, s_h, s_p);
    else if (k == 1) scan_body<true,  true >(pdtu4, pBu, pCu, pout, An, Dd, c, ln2, tid, s_h, s_p);
    else if (k == 2) scan_body<false, false>(pdtu4, pBu, pCu, pout, An, Dd, c, ln2, tid, s_h, s_p);
    else             scan_body<false, true >(pdtu4, pBu, pCu, pout, An, Dd, c, ln2, tid, s_h, s_p);
}

// ---------------- K6: combine + LN + gate*z + out-proj (192 -> 96) ----------------
__global__ void __launch_bounds__(256) k_final(const float* __restrict__ onw,
                                               const float* __restrict__ onb,
                                               const float* __restrict__ ow,
                                               const float* __restrict__ ob,
                                               float* __restrict__ out) {
    __shared__ float sv[DI*33];       // [d][si] with pad-33 pitch
    __shared__ float smu[32], srs[32];
    int tid = threadIdx.x;
    int p0 = blockIdx.x * 32;
    for (int idx = tid; idx < DI*32; idx += 256) {
        int d = idx >> 5, si = idx & 31;
        int p = p0 + si;
        float s = g_y4[(0*DI + d)*L + p] + g_y4[(1*DI + d)*L + p]
                + g_y4[(2*DI + d)*L + p] + g_y4[(3*DI + d)*L + p];
        sv[d*33 + si] = s;
    }
    __syncthreads();
    {
        int w = tid >> 5, lane = tid & 31;
        for (int q = 0; q < 4; q++) {
            int si = w*4 + q;
            float s1 = 0.f, s2 = 0.f;
            #pragma unroll
            for (int j = 0; j < 6; j++) {
                float v = sv[(lane + j*32)*33 + si];
                s1 += v; s2 += v*v;
            }
            #pragma unroll
            for (int o = 16; o > 0; o >>= 1) {
                s1 += __shfl_xor_sync(0xffffffffu, s1, o);
                s2 += __shfl_xor_sync(0xffffffffu, s2, o);
            }
            if (lane == 0) {
                float mu = s1 * (1.f/DI);
                smu[si] = mu;
                srs[si] = rsqrtf(s2*(1.f/DI) - mu*mu + 1e-5f);
            }
        }
    }
    __syncthreads();
    for (int idx = tid; idx < DI*32; idx += 256) {
        int d = idx >> 5, si = idx & 31;
        int p = p0 + si;
        float v = sv[d*33 + si];
        v = (v - smu[si]) * srs[si] * onw[d] + onb[d];
        v = v * g_gate[d] * g_z[d*L + p];
        sv[d*33 + si] = v;
    }
    __syncthreads();
    for (int idx = tid; idx < 96*32; idx += 256) {
        int o = idx >> 5, si = idx & 31;
        const float4* w4 = reinterpret_cast<const float4*>(ow + o*DI);
        float a0 = 0.f, a1 = 0.f, a2 = 0.f, a3 = 0.f;
        #pragma unroll 12
        for (int d4 = 0; d4 < 48; d4++) {
            float4 wv = __ldg(w4 + d4);
            int d = d4*4;
            a0 = fmaf(wv.x, sv[d*33+si], a0);
            a1 = fmaf(wv.y, sv[(d+1)*33+si], a1);
            a2 = fmaf(wv.z, sv[(d+2)*33+si], a2);
            a3 = fmaf(wv.w, sv[(d+3)*33+si], a3);
        }
        out[o*L + p0 + si] = ob[o] + (a0 + a1) + (a2 + a3);
    }
}

// ---------------- launch ----------------
extern "C" void kernel_launch(void* const* d_in, const int* in_sizes, int n_in,
                              void* d_out, int out_size) {
    const float* x      = (const float*)d_in[0];
    const float* in_w   = (const float*)d_in[1];
    const float* in_b   = (const float*)d_in[2];
    const float* c2w    = (const float*)d_in[3];
    const float* c2b    = (const float*)d_in[4];
    const float* xpw    = (const float*)d_in[5];
    const float* dtw    = (const float*)d_in[6];
    const float* dtb    = (const float*)d_in[7];
    const float* Alogs  = (const float*)d_in[8];
    const float* Ds     = (const float*)d_in[9];
    const float* onw    = (const float*)d_in[10];
    const float* onb    = (const float*)d_in[11];
    const float* cinw   = (const float*)d_in[12];
    const float* cinb   = (const float*)d_in[13];
    const float* coutw  = (const float*)d_in[14];
    const float* coutb  = (const float*)d_in[15];
    const float* xcw    = (const float*)d_in[16];
    const float* dtcw   = (const float*)d_in[17];
    const float* dtcb   = (const float*)d_in[18];
    const float* Aclogs = (const float*)d_in[19];
    const float* Dsc    = (const float*)d_in[20];
    const float* cnw    = (const float*)d_in[21];
    const float* cnb    = (const float*)d_in[22];
    const float* ow     = (const float*)d_in[23];
    const float* obias  = (const float*)d_in[24];
    float* out = (float*)d_out;

    k_inproj<<<dim3(32, 24), 128>>>(x, in_w, in_b);
    k_dwconv<<<dim3(2, 2, 192), dim3(32, 32)>>>(c2w, c2b);
    k_proj<<<dim3(129, 2), 320>>>(xpw, dtw, dtb,
                                  cinw, cinb, xcw, dtcw, dtcb, Aclogs, Dsc,
                                  coutw, coutb, cnw, cnb);
    k_scan<<<768, 256>>>(Alogs, Ds);
    k_final<<<128, 256>>>(onw, onb, ow, obias, out);
}